// round 6
// baseline (speedup 1.0000x reference)
#include <cuda_runtime.h>
#include <stdint.h>
#include <math.h>
#include <float.h>

// ---------------- problem constants ----------------
#define NN_   8192      // nodes
#define E1_   131072    // node-graph edges (= trace rows)
#define E2_   524288    // line-graph edges
#define DIN   256       // layer1 channels (4 heads x 64)
#define DED   128       // layer2 channels (4 heads x 32)
#define EPSV  1e-16f

// ---------------- scratch (static device, no allocs) ----------------
__device__ float g_node   [(size_t)NN_ * DIN];
__device__ float g_xl     [(size_t)NN_ * DIN];
__device__ float g_xr     [(size_t)NN_ * DIN];
__device__ float g_alpha1 [(size_t)E1_ * 4];    // exp(logit)
__device__ float g_den1   [(size_t)NN_ * 4];
__device__ float g_nodeout[(size_t)NN_ * DIN];
__device__ float g_xl2    [(size_t)E1_ * DED];
__device__ float g_xr2    [(size_t)E1_ * DED];
__device__ float g_gfeat  [(size_t)NN_ * DED];
__device__ float g_alpha2 [(size_t)E2_ * 4];    // exp(logit)
__device__ float g_den2   [(size_t)E1_ * 4];

// ---------------- helpers ----------------
__device__ __forceinline__ float lrelu02(float x) { return x > 0.f ? x : 0.2f * x; }
__device__ __forceinline__ uint32_t to_tf32(float v) {
    uint32_t t;
    asm("cvt.rna.tf32.f32 %0, %1;" : "=r"(t) : "f"(v));
    return t;
}
__device__ __forceinline__ void cp16(uint32_t dst, const void* src) {
    asm volatile("cp.async.cg.shared.global [%0], [%1], 16;" :: "r"(dst), "l"(src));
}
__device__ __forceinline__ void red_add_v4(float* addr, float4 v) {
    asm volatile("red.global.add.v4.f32 [%0], {%1,%2,%3,%4};"
                 :: "l"(addr), "f"(v.x), "f"(v.y), "f"(v.z), "f"(v.w) : "memory");
}

// ---------------- tf32 GEMM tiles ----------------
#define TBM 128
#define TBN 128
#define TBK 32
#define STG 8960                 // floats per stage: 128*36 + 32*136
#define AS(S,M,K_) smem[(S)*STG + (M)*36 + (K_)]
#define BS(S,KK,N_) smem[(S)*STG + 4608 + (KK)*136 + (N_)]
#define ET(R,C) smem[(R)*132 + (C)]

struct Frag { float c[4][4][4]; };

__device__ __forceinline__ void load_stage(float* smem, int s,
    const float* __restrict__ A, const float* __restrict__ W,
    int bm, int bn, int k0, int K, int Ncol, int tid)
{
#pragma unroll
    for (int i = 0; i < 4; i++) {
        int idx = tid + i * 256;
        int m = idx >> 3, kc = idx & 7;
        cp16((uint32_t)__cvta_generic_to_shared(&AS(s, m, kc * 4)),
             &A[(size_t)(bm + m) * K + k0 + kc * 4]);
    }
#pragma unroll
    for (int i = 0; i < 4; i++) {
        int idx = tid + i * 256;
        int kk = idx >> 5, nc = idx & 31;
        cp16((uint32_t)__cvta_generic_to_shared(&BS(s, kk, nc * 4)),
             &W[(size_t)(k0 + kk) * Ncol + bn + nc * 4]);
    }
    asm volatile("cp.async.commit_group;");
}

__device__ __forceinline__ void compute_stage(const float* smem, int s, Frag& f,
                                              int wm, int wn, int g, int tg)
{
#pragma unroll
    for (int ks = 0; ks < 4; ks++) {
        const int kb = ks * 8;
        uint32_t afr[4][4], bfr[4][2];
#pragma unroll
        for (int mt = 0; mt < 4; mt++) {
            int mr = wm + mt * 16 + g;
            afr[mt][0] = to_tf32(AS(s, mr,     kb + tg));
            afr[mt][1] = to_tf32(AS(s, mr + 8, kb + tg));
            afr[mt][2] = to_tf32(AS(s, mr,     kb + tg + 4));
            afr[mt][3] = to_tf32(AS(s, mr + 8, kb + tg + 4));
        }
#pragma unroll
        for (int nt = 0; nt < 4; nt++) {
            int nc = wn + nt * 8 + g;
            bfr[nt][0] = to_tf32(BS(s, kb + tg,     nc));
            bfr[nt][1] = to_tf32(BS(s, kb + tg + 4, nc));
        }
#pragma unroll
        for (int mt = 0; mt < 4; mt++)
#pragma unroll
            for (int nt = 0; nt < 4; nt++) {
                asm volatile(
                    "mma.sync.aligned.m16n8k8.row.col.f32.tf32.tf32.f32 "
                    "{%0,%1,%2,%3}, {%4,%5,%6,%7}, {%8,%9}, {%0,%1,%2,%3};"
                    : "+f"(f.c[mt][nt][0]), "+f"(f.c[mt][nt][1]),
                      "+f"(f.c[mt][nt][2]), "+f"(f.c[mt][nt][3])
                    : "r"(afr[mt][0]), "r"(afr[mt][1]),
                      "r"(afr[mt][2]), "r"(afr[mt][3]),
                      "r"(bfr[nt][0]), "r"(bfr[nt][1]));
            }
    }
}

// Pipelined GEMM, optionally dual-output (blockIdx.z selects W/bias/C).
__global__ __launch_bounds__(256) void gemm_pipe(
    const float* __restrict__ A,
    const float* __restrict__ W0, const float* __restrict__ W1,
    const float* __restrict__ b0, const float* __restrict__ b1,
    float* __restrict__ C0, float* __restrict__ C1,
    int M, int Ncol, int K)
{
    extern __shared__ float smem[];
    const int tid  = threadIdx.x;
    const int lane = tid & 31, warp = tid >> 5;
    const int g = lane >> 2, tg = lane & 3;
    const int wm = (warp >> 2) * 64, wn = (warp & 3) * 32;
    const int bm = blockIdx.y * TBM, bn = blockIdx.x * TBN;
    const int z  = blockIdx.z;
    const float* W    = z ? W1 : W0;
    const float* bias = z ? b1 : b0;
    float* C          = z ? C1 : C0;

    Frag f;
#pragma unroll
    for (int mt = 0; mt < 4; mt++)
#pragma unroll
        for (int nt = 0; nt < 4; nt++)
#pragma unroll
            for (int r = 0; r < 4; r++) f.c[mt][nt][r] = 0.f;

    const int KT = K / TBK;
    load_stage(smem, 0, A, W, bm, bn, 0, K, Ncol, tid);
    for (int kt = 0; kt < KT; kt++) {
        int s = kt & 1;
        if (kt + 1 < KT) {
            load_stage(smem, s ^ 1, A, W, bm, bn, (kt + 1) * TBK, K, Ncol, tid);
            asm volatile("cp.async.wait_group 1;");
        } else {
            asm volatile("cp.async.wait_group 0;");
        }
        __syncthreads();
        compute_stage(smem, s, f, wm, wn, g, tg);
        __syncthreads();
    }

#pragma unroll
    for (int mt = 0; mt < 4; mt++) {
        int r0 = bm + wm + mt * 16 + g;
#pragma unroll
        for (int nt = 0; nt < 4; nt++) {
            int col = bn + wn + nt * 8 + 2 * tg;
            float bb0 = bias ? bias[col] : 0.f;
            float bb1 = bias ? bias[col + 1] : 0.f;
            float2 v0 = make_float2(f.c[mt][nt][0] + bb0, f.c[mt][nt][1] + bb1);
            float2 v1 = make_float2(f.c[mt][nt][2] + bb0, f.c[mt][nt][3] + bb1);
            *(float2*)&C[(size_t)r0 * Ncol + col] = v0;
            *(float2*)&C[(size_t)(r0 + 8) * Ncol + col] = v1;
        }
    }
}

// Fused: e1 = trace @ We, kept in smem, then exp-logit + denominator accumulation.
// grid (2, E1/128): blockIdx.x selects channels [0,128) = heads {0,1} or [128,256) = heads {2,3}.
__global__ __launch_bounds__(256) void gemm_alpha1_fused(
    const float* __restrict__ A,      // x_trace [E1,128]
    const float* __restrict__ W,      // n2n_We [128,256]
    const int*   __restrict__ adj,    // node_adj [2,E1]
    const float* __restrict__ att)    // [4,64]
{
    extern __shared__ float smem[];
    const int tid  = threadIdx.x;
    const int lane = tid & 31, warp = tid >> 5;
    const int g = lane >> 2, tg = lane & 3;
    const int wm = (warp >> 2) * 64, wn = (warp & 3) * 32;
    const int bm = blockIdx.y * TBM, bn = blockIdx.x * TBN;
    const int K = 128, Ncol = DIN;

    Frag f;
#pragma unroll
    for (int mt = 0; mt < 4; mt++)
#pragma unroll
        for (int nt = 0; nt < 4; nt++)
#pragma unroll
            for (int r = 0; r < 4; r++) f.c[mt][nt][r] = 0.f;

    const int KT = K / TBK;
    load_stage(smem, 0, A, W, bm, bn, 0, K, Ncol, tid);
    for (int kt = 0; kt < KT; kt++) {
        int s = kt & 1;
        if (kt + 1 < KT) {
            load_stage(smem, s ^ 1, A, W, bm, bn, (kt + 1) * TBK, K, Ncol, tid);
            asm volatile("cp.async.wait_group 1;");
        } else {
            asm volatile("cp.async.wait_group 0;");
        }
        __syncthreads();
        compute_stage(smem, s, f, wm, wn, g, tg);
        __syncthreads();
    }

    // stage e1 tile into smem (overwrites stage buffers; synced above)
#pragma unroll
    for (int mt = 0; mt < 4; mt++) {
        int r0 = wm + mt * 16 + g;
#pragma unroll
        for (int nt = 0; nt < 4; nt++) {
            int col = wn + nt * 8 + 2 * tg;
            ET(r0, col)         = f.c[mt][nt][0];
            ET(r0, col + 1)     = f.c[mt][nt][1];
            ET(r0 + 8, col)     = f.c[mt][nt][2];
            ET(r0 + 8, col + 1) = f.c[mt][nt][3];
        }
    }
    __syncthreads();

    // phase 2: per-edge attention logits for this head-pair, exp'd directly
    const float4 av = *(const float4*)&att[bn + lane * 4];
#pragma unroll 2
    for (int er = warp * 16; er < warp * 16 + 16; er++) {
        int e = bm + er;
        int src = adj[e], dst = adj[E1_ + e];
        float4 xlv = *(const float4*)&g_xl[(size_t)src * DIN + bn + lane * 4];
        float4 xrv = *(const float4*)&g_xr[(size_t)dst * DIN + bn + lane * 4];
        float p;
        p  = lrelu02(xlv.x + xrv.x + ET(er, lane * 4 + 0)) * av.x;
        p += lrelu02(xlv.y + xrv.y + ET(er, lane * 4 + 1)) * av.y;
        p += lrelu02(xlv.z + xrv.z + ET(er, lane * 4 + 2)) * av.z;
        p += lrelu02(xlv.w + xrv.w + ET(er, lane * 4 + 3)) * av.w;
#pragma unroll
        for (int off = 8; off > 0; off >>= 1)
            p += __shfl_xor_sync(0xffffffff, p, off);
        if (lane == 0 || lane == 16) {
            int head = 2 * blockIdx.x + (lane >> 4);
            float ex = expf(p);
            g_alpha1[(size_t)e * 4 + head] = ex;
            atomicAdd(&g_den1[(size_t)dst * 4 + head], ex);
        }
    }
}

// ---------------- prep: concat + inits ----------------
__global__ void prep_kernel(const float* __restrict__ x_node,
                            const float* __restrict__ x_log,
                            const float* __restrict__ bias1)
{
    size_t idx = (size_t)blockIdx.x * blockDim.x + threadIdx.x;
    if (idx >= (size_t)NN_ * DIN) return;
    int i = (int)(idx >> 8), c = (int)(idx & 255);
    g_node[idx] = (c < 128) ? x_node[(size_t)i * 128 + c]
                            : x_log[(size_t)i * 128 + (c - 128)];
    g_nodeout[idx] = bias1[c];
    if (idx < NN_ * 4) g_den1[idx] = 0.f;
    if (idx < (size_t)E1_ * 4) g_den2[idx] = 0.f;
}

// ---------------- layer-1 aggregate (2 edges per warp) ----------------
__global__ __launch_bounds__(256) void agg1_kernel(const int* __restrict__ adj) {
    int warp = (blockIdx.x * blockDim.x + threadIdx.x) >> 5;
    int lane = threadIdx.x & 31;
    int e0 = warp * 2;
    if (e0 >= E1_) return;
    int h0 = lane >> 4;
#pragma unroll
    for (int i = 0; i < 2; i++) {
        int e = e0 + i;
        int src = adj[e], dst = adj[E1_ + e];
        float a0 = g_alpha1[(size_t)e * 4 + h0]     / (g_den1[(size_t)dst * 4 + h0]     + EPSV);
        float a1 = g_alpha1[(size_t)e * 4 + 2 + h0] / (g_den1[(size_t)dst * 4 + 2 + h0] + EPSV);
        const float* xl = g_xl + (size_t)src * DIN;
        float* out = g_nodeout + (size_t)dst * DIN;
        float4 v0 = *(const float4*)&xl[lane * 4];
        float4 v1 = *(const float4*)&xl[128 + lane * 4];
        red_add_v4(&out[lane * 4],       make_float4(a0 * v0.x, a0 * v0.y, a0 * v0.z, a0 * v0.w));
        red_add_v4(&out[128 + lane * 4], make_float4(a1 * v1.x, a1 * v1.y, a1 * v1.z, a1 * v1.w));
    }
}

// ---------------- layer-2 edge kernels ----------------
// 4 edges per warp, unrolled for MLP; lane l covers channels [4l..4l+3], head = l>>3
__global__ __launch_bounds__(256) void alpha2_kernel(const int* __restrict__ adj,
                                                     const int* __restrict__ efea,
                                                     const float* __restrict__ att)
{
    int warp = (blockIdx.x * blockDim.x + threadIdx.x) >> 5;
    int lane = threadIdx.x & 31;
    int e0 = warp * 4;
    if (e0 >= E2_) return;
    float4 av = *(const float4*)&att[lane * 4];
    int src[4], dst[4], ef[4];
#pragma unroll
    for (int i = 0; i < 4; i++) {
        src[i] = adj[e0 + i];
        dst[i] = adj[(size_t)E2_ + e0 + i];
        ef[i]  = efea[e0 + i];
    }
    float p[4];
#pragma unroll
    for (int i = 0; i < 4; i++) {
        float4 xlv = *(const float4*)&g_xl2  [(size_t)src[i] * DED + lane * 4];
        float4 xrv = *(const float4*)&g_xr2  [(size_t)dst[i] * DED + lane * 4];
        float4 eev = *(const float4*)&g_gfeat[(size_t)ef[i]  * DED + lane * 4];
        float q;
        q  = lrelu02(xlv.x + xrv.x + eev.x) * av.x;
        q += lrelu02(xlv.y + xrv.y + eev.y) * av.y;
        q += lrelu02(xlv.z + xrv.z + eev.z) * av.z;
        q += lrelu02(xlv.w + xrv.w + eev.w) * av.w;
        p[i] = q;
    }
#pragma unroll
    for (int i = 0; i < 4; i++) {
#pragma unroll
        for (int off = 4; off > 0; off >>= 1)
            p[i] += __shfl_xor_sync(0xffffffff, p[i], off);
        if ((lane & 7) == 0) {
            int head = lane >> 3;
            float ex = expf(p[i]);
            g_alpha2[(size_t)(e0 + i) * 4 + head] = ex;
            atomicAdd(&g_den2[(size_t)dst[i] * 4 + head], ex);
        }
    }
}

__global__ void out_split_kernel(float* __restrict__ out, const float* __restrict__ bias2) {
    size_t idx = (size_t)blockIdx.x * blockDim.x + threadIdx.x;
    const size_t XN = (size_t)NN_ * 128;
    const size_t XT = (size_t)E1_ * 128;
    if (idx >= XN + XT + XN) return;
    if (idx < XN) {
        int i = (int)(idx >> 7), c = (int)(idx & 127);
        out[idx] = g_nodeout[(size_t)i * DIN + c];
    } else if (idx < XN + XT) {
        out[idx] = bias2[idx & 127];
    } else {
        size_t r = idx - (XN + XT);
        int i = (int)(r >> 7), c = (int)(r & 127);
        out[idx] = g_nodeout[(size_t)i * DIN + 128 + c];
    }
}

// 2 edges per warp
__global__ __launch_bounds__(256) void agg2_kernel(const int* __restrict__ adj,
                                                   float* __restrict__ out_xt)
{
    int warp = (blockIdx.x * blockDim.x + threadIdx.x) >> 5;
    int lane = threadIdx.x & 31;
    int e0 = warp * 2;
    if (e0 >= E2_) return;
    int h = lane >> 3;
#pragma unroll
    for (int i = 0; i < 2; i++) {
        int e = e0 + i;
        int src = adj[e], dst = adj[(size_t)E2_ + e];
        float a = g_alpha2[(size_t)e * 4 + h] / (g_den2[(size_t)dst * 4 + h] + EPSV);
        float4 v = *(const float4*)&g_xl2[(size_t)src * DED + lane * 4];
        red_add_v4(&out_xt[(size_t)dst * DED + lane * 4],
                   make_float4(a * v.x, a * v.y, a * v.z, a * v.w));
    }
}

// ---------------- launch ----------------
extern "C" void kernel_launch(void* const* d_in, const int* in_sizes, int n_in,
                              void* d_out, int out_size)
{
    const float* x_node   = (const float*)d_in[0];
    const float* x_trace  = (const float*)d_in[1];
    const float* x_log    = (const float*)d_in[2];
    const int*   node_adj = (const int*)d_in[3];
    const int*   edge_adj = (const int*)d_in[4];
    const int*   edge_efea= (const int*)d_in[5];
    const float* n2n_Wl   = (const float*)d_in[6];
    const float* n2n_bl   = (const float*)d_in[7];
    const float* n2n_Wr   = (const float*)d_in[8];
    const float* n2n_br   = (const float*)d_in[9];
    const float* n2n_We   = (const float*)d_in[10];
    const float* n2n_att  = (const float*)d_in[11];
    const float* n2n_bias = (const float*)d_in[12];
    const float* e2n_Wl   = (const float*)d_in[13];
    const float* e2n_bl   = (const float*)d_in[14];
    const float* e2n_Wr   = (const float*)d_in[15];
    const float* e2n_br   = (const float*)d_in[16];
    const float* e2n_We   = (const float*)d_in[17];
    const float* e2n_att  = (const float*)d_in[18];
    const float* e2n_bias = (const float*)d_in[19];
    float* out = (float*)d_out;

    float* p_node;    cudaGetSymbolAddress((void**)&p_node,    g_node);
    float* p_xl;      cudaGetSymbolAddress((void**)&p_xl,      g_xl);
    float* p_xr;      cudaGetSymbolAddress((void**)&p_xr,      g_xr);
    float* p_nodeout; cudaGetSymbolAddress((void**)&p_nodeout, g_nodeout);
    float* p_xl2;     cudaGetSymbolAddress((void**)&p_xl2,     g_xl2);
    float* p_xr2;     cudaGetSymbolAddress((void**)&p_xr2,     g_xr2);
    float* p_g;       cudaGetSymbolAddress((void**)&p_g,       g_gfeat);

    const int SMEM_PIPE  = 2 * STG * 4;          // 71680 (covers ET 128*132*4=67584 too)
    static int attr_done = 0;
    if (!attr_done) {
        cudaFuncSetAttribute(gemm_pipe, cudaFuncAttributeMaxDynamicSharedMemorySize, SMEM_PIPE);
        cudaFuncSetAttribute(gemm_alpha1_fused, cudaFuncAttributeMaxDynamicSharedMemorySize, SMEM_PIPE);
        attr_done = 1;
    }

    // 1: prep (concat + den inits + nodeout=bias)
    prep_kernel<<<(NN_ * DIN) / 256, 256>>>(x_node, x_log, n2n_bias);

    // 2: xl/xr dual GEMM
    {
        dim3 gdim(DIN / TBN, NN_ / TBM, 2);
        gemm_pipe<<<gdim, 256, SMEM_PIPE>>>(p_node, n2n_Wl, n2n_Wr, n2n_bl, n2n_br,
                                            p_xl, p_xr, NN_, DIN, DIN);
    }
    // 3: xl2/xr2 dual GEMM (depends only on x_trace)
    {
        dim3 gdim(DED / TBN, E1_ / TBM, 2);
        gemm_pipe<<<gdim, 256, SMEM_PIPE>>>(x_trace, e2n_Wl, e2n_Wr, e2n_bl, e2n_br,
                                            p_xl2, p_xr2, E1_, DED, DED);
    }
    // 4: fused e1 GEMM + alpha1 (exp + den accumulation)
    {
        dim3 gdim(DIN / TBN, E1_ / TBM);
        gemm_alpha1_fused<<<gdim, 256, SMEM_PIPE>>>(x_trace, n2n_We, node_adj, n2n_att);
    }
    // 5: layer-1 aggregate
    agg1_kernel<<<E1_ / 16, 256>>>(node_adj);

    // 6: gfeat = node_out @ We2
    {
        dim3 gdim(DED / TBN, NN_ / TBM, 1);
        gemm_pipe<<<gdim, 256, SMEM_PIPE>>>(p_nodeout, e2n_We, e2n_We, nullptr, nullptr,
                                            p_g, p_g, NN_, DED, DIN);
    }
    // 7: layer-2 attention (exp + den accumulation)
    alpha2_kernel<<<E2_ / 32, 256>>>(edge_adj, edge_efea, e2n_att);

    // 8-9: outputs
    {
        size_t total = (size_t)NN_ * 128 * 2 + (size_t)E1_ * 128;
        out_split_kernel<<<(unsigned)((total + 255) / 256), 256>>>(out, e2n_bias);
    }
    agg2_kernel<<<E2_ / 16, 256>>>(edge_adj, out + (size_t)NN_ * 128);
}

// round 7
// speedup vs baseline: 1.2313x; 1.2313x over previous
#include <cuda_runtime.h>
#include <stdint.h>
#include <math.h>
#include <float.h>

// ---------------- problem constants ----------------
#define NN_   8192      // nodes
#define E1_   131072    // node-graph edges (= trace rows)
#define E2_   524288    // line-graph edges
#define DIN   256       // layer1 channels (4 heads x 64)
#define DED   128       // layer2 channels (4 heads x 32)
#define EPSV  1e-16f

// ---------------- scratch (static device, no allocs) ----------------
__device__ float g_node   [(size_t)NN_ * DIN];
__device__ float g_xl     [(size_t)NN_ * DIN];
__device__ float g_xr     [(size_t)NN_ * DIN];
__device__ float g_alpha1 [(size_t)E1_ * 4];
__device__ float g_amax1  [(size_t)NN_ * 4];
__device__ float g_den1   [(size_t)NN_ * 4];
__device__ float g_nodeout[(size_t)NN_ * DIN];
__device__ float g_xl2    [(size_t)E1_ * DED];
__device__ float g_xr2    [(size_t)E1_ * DED];
__device__ float g_gfeat  [(size_t)NN_ * DED];
__device__ float g_alpha2 [(size_t)E2_ * 4];    // exp(logit)
__device__ float g_den2   [(size_t)E1_ * 4];

// ---------------- helpers ----------------
__device__ __forceinline__ void atomicMaxFloat(float* addr, float val) {
    if (val >= 0.f) atomicMax((int*)addr, __float_as_int(val));
    else            atomicMin((unsigned int*)addr, __float_as_uint(val));
}
__device__ __forceinline__ float lrelu02(float x) { return x > 0.f ? x : 0.2f * x; }
__device__ __forceinline__ uint32_t to_tf32(float v) {
    uint32_t t;
    asm("cvt.rna.tf32.f32 %0, %1;" : "=r"(t) : "f"(v));
    return t;
}
__device__ __forceinline__ void cp16(uint32_t dst, const void* src) {
    asm volatile("cp.async.cg.shared.global [%0], [%1], 16;" :: "r"(dst), "l"(src));
}
__device__ __forceinline__ void red_add_v4(float* addr, float4 v) {
    asm volatile("red.global.add.v4.f32 [%0], {%1,%2,%3,%4};"
                 :: "l"(addr), "f"(v.x), "f"(v.y), "f"(v.z), "f"(v.w) : "memory");
}

// ---------------- tf32 GEMM tiles ----------------
#define TBM 128
#define TBN 128
#define TBK 32
#define STG 8960                 // floats per stage: 128*36 + 32*136
#define AS(S,M,K_) smem[(S)*STG + (M)*36 + (K_)]
#define BS(S,KK,N_) smem[(S)*STG + 4608 + (KK)*136 + (N_)]
#define ET(R,C) smem[(R)*132 + (C)]

struct Frag { float c[4][4][4]; };

__device__ __forceinline__ void load_stage(float* smem, int s,
    const float* __restrict__ A, const float* __restrict__ W,
    int bm, int bn, int k0, int K, int Ncol, int tid)
{
#pragma unroll
    for (int i = 0; i < 4; i++) {
        int idx = tid + i * 256;
        int m = idx >> 3, kc = idx & 7;
        cp16((uint32_t)__cvta_generic_to_shared(&AS(s, m, kc * 4)),
             &A[(size_t)(bm + m) * K + k0 + kc * 4]);
    }
#pragma unroll
    for (int i = 0; i < 4; i++) {
        int idx = tid + i * 256;
        int kk = idx >> 5, nc = idx & 31;
        cp16((uint32_t)__cvta_generic_to_shared(&BS(s, kk, nc * 4)),
             &W[(size_t)(k0 + kk) * Ncol + bn + nc * 4]);
    }
    asm volatile("cp.async.commit_group;");
}

__device__ __forceinline__ void compute_stage(const float* smem, int s, Frag& f,
                                              int wm, int wn, int g, int tg)
{
#pragma unroll
    for (int ks = 0; ks < 4; ks++) {
        const int kb = ks * 8;
        uint32_t afr[4][4], bfr[4][2];
#pragma unroll
        for (int mt = 0; mt < 4; mt++) {
            int mr = wm + mt * 16 + g;
            afr[mt][0] = to_tf32(AS(s, mr,     kb + tg));
            afr[mt][1] = to_tf32(AS(s, mr + 8, kb + tg));
            afr[mt][2] = to_tf32(AS(s, mr,     kb + tg + 4));
            afr[mt][3] = to_tf32(AS(s, mr + 8, kb + tg + 4));
        }
#pragma unroll
        for (int nt = 0; nt < 4; nt++) {
            int nc = wn + nt * 8 + g;
            bfr[nt][0] = to_tf32(BS(s, kb + tg,     nc));
            bfr[nt][1] = to_tf32(BS(s, kb + tg + 4, nc));
        }
#pragma unroll
        for (int mt = 0; mt < 4; mt++)
#pragma unroll
            for (int nt = 0; nt < 4; nt++) {
                asm volatile(
                    "mma.sync.aligned.m16n8k8.row.col.f32.tf32.tf32.f32 "
                    "{%0,%1,%2,%3}, {%4,%5,%6,%7}, {%8,%9}, {%0,%1,%2,%3};"
                    : "+f"(f.c[mt][nt][0]), "+f"(f.c[mt][nt][1]),
                      "+f"(f.c[mt][nt][2]), "+f"(f.c[mt][nt][3])
                    : "r"(afr[mt][0]), "r"(afr[mt][1]),
                      "r"(afr[mt][2]), "r"(afr[mt][3]),
                      "r"(bfr[nt][0]), "r"(bfr[nt][1]));
            }
    }
}

// Pipelined GEMM, optionally dual-output (blockIdx.z selects W/bias/C).
__global__ __launch_bounds__(256) void gemm_pipe(
    const float* __restrict__ A,
    const float* __restrict__ W0, const float* __restrict__ W1,
    const float* __restrict__ b0, const float* __restrict__ b1,
    float* __restrict__ C0, float* __restrict__ C1,
    int M, int Ncol, int K)
{
    extern __shared__ float smem[];
    const int tid  = threadIdx.x;
    const int lane = tid & 31, warp = tid >> 5;
    const int g = lane >> 2, tg = lane & 3;
    const int wm = (warp >> 2) * 64, wn = (warp & 3) * 32;
    const int bm = blockIdx.y * TBM, bn = blockIdx.x * TBN;
    const int z  = blockIdx.z;
    const float* W    = z ? W1 : W0;
    const float* bias = z ? b1 : b0;
    float* C          = z ? C1 : C0;

    Frag f;
#pragma unroll
    for (int mt = 0; mt < 4; mt++)
#pragma unroll
        for (int nt = 0; nt < 4; nt++)
#pragma unroll
            for (int r = 0; r < 4; r++) f.c[mt][nt][r] = 0.f;

    const int KT = K / TBK;
    load_stage(smem, 0, A, W, bm, bn, 0, K, Ncol, tid);
    for (int kt = 0; kt < KT; kt++) {
        int s = kt & 1;
        if (kt + 1 < KT) {
            load_stage(smem, s ^ 1, A, W, bm, bn, (kt + 1) * TBK, K, Ncol, tid);
            asm volatile("cp.async.wait_group 1;");
        } else {
            asm volatile("cp.async.wait_group 0;");
        }
        __syncthreads();
        compute_stage(smem, s, f, wm, wn, g, tg);
        __syncthreads();
    }

#pragma unroll
    for (int mt = 0; mt < 4; mt++) {
        int r0 = bm + wm + mt * 16 + g;
#pragma unroll
        for (int nt = 0; nt < 4; nt++) {
            int col = bn + wn + nt * 8 + 2 * tg;
            float bb0 = bias ? bias[col] : 0.f;
            float bb1 = bias ? bias[col + 1] : 0.f;
            float2 v0 = make_float2(f.c[mt][nt][0] + bb0, f.c[mt][nt][1] + bb1);
            float2 v1 = make_float2(f.c[mt][nt][2] + bb0, f.c[mt][nt][3] + bb1);
            *(float2*)&C[(size_t)r0 * Ncol + col] = v0;
            *(float2*)&C[(size_t)(r0 + 8) * Ncol + col] = v1;
        }
    }
}

// Fused: e1 = trace @ We, kept in smem, then alpha1 = att . lrelu(xl[src]+xr[dst]+e1)
// (identical to the R5 version: writes raw logit + atomicMax)
__global__ __launch_bounds__(256) void gemm_alpha1_fused(
    const float* __restrict__ A,      // x_trace [E1,128]
    const float* __restrict__ W,      // n2n_We [128,256]
    const int*   __restrict__ adj,    // node_adj [2,E1]
    const float* __restrict__ att)    // [4,64]
{
    extern __shared__ float smem[];
    const int tid  = threadIdx.x;
    const int lane = tid & 31, warp = tid >> 5;
    const int g = lane >> 2, tg = lane & 3;
    const int wm = (warp >> 2) * 64, wn = (warp & 3) * 32;
    const int bm = blockIdx.y * TBM, bn = blockIdx.x * TBN;
    const int K = 128, Ncol = DIN;

    Frag f;
#pragma unroll
    for (int mt = 0; mt < 4; mt++)
#pragma unroll
        for (int nt = 0; nt < 4; nt++)
#pragma unroll
            for (int r = 0; r < 4; r++) f.c[mt][nt][r] = 0.f;

    const int KT = K / TBK;
    load_stage(smem, 0, A, W, bm, bn, 0, K, Ncol, tid);
    for (int kt = 0; kt < KT; kt++) {
        int s = kt & 1;
        if (kt + 1 < KT) {
            load_stage(smem, s ^ 1, A, W, bm, bn, (kt + 1) * TBK, K, Ncol, tid);
            asm volatile("cp.async.wait_group 1;");
        } else {
            asm volatile("cp.async.wait_group 0;");
        }
        __syncthreads();
        compute_stage(smem, s, f, wm, wn, g, tg);
        __syncthreads();
    }

    // stage e1 tile into smem (overwrites stage buffers; synced above)
#pragma unroll
    for (int mt = 0; mt < 4; mt++) {
        int r0 = wm + mt * 16 + g;
#pragma unroll
        for (int nt = 0; nt < 4; nt++) {
            int col = wn + nt * 8 + 2 * tg;
            ET(r0, col)         = f.c[mt][nt][0];
            ET(r0, col + 1)     = f.c[mt][nt][1];
            ET(r0 + 8, col)     = f.c[mt][nt][2];
            ET(r0 + 8, col + 1) = f.c[mt][nt][3];
        }
    }
    __syncthreads();

    // phase 2: per-edge attention logits for this head-pair
    const float4 av = *(const float4*)&att[bn + lane * 4];
#pragma unroll 2
    for (int er = warp * 16; er < warp * 16 + 16; er++) {
        int e = bm + er;
        int src = adj[e], dst = adj[E1_ + e];
        float4 xlv = *(const float4*)&g_xl[(size_t)src * DIN + bn + lane * 4];
        float4 xrv = *(const float4*)&g_xr[(size_t)dst * DIN + bn + lane * 4];
        float p;
        p  = lrelu02(xlv.x + xrv.x + ET(er, lane * 4 + 0)) * av.x;
        p += lrelu02(xlv.y + xrv.y + ET(er, lane * 4 + 1)) * av.y;
        p += lrelu02(xlv.z + xrv.z + ET(er, lane * 4 + 2)) * av.z;
        p += lrelu02(xlv.w + xrv.w + ET(er, lane * 4 + 3)) * av.w;
#pragma unroll
        for (int off = 8; off > 0; off >>= 1)
            p += __shfl_xor_sync(0xffffffff, p, off);
        if (lane == 0 || lane == 16) {
            int head = 2 * blockIdx.x + (lane >> 4);
            g_alpha1[(size_t)e * 4 + head] = p;
            atomicMaxFloat(&g_amax1[(size_t)dst * 4 + head], p);
        }
    }
}

// ---------------- prep: concat + inits ----------------
__global__ void prep_kernel(const float* __restrict__ x_node,
                            const float* __restrict__ x_log,
                            const float* __restrict__ bias1)
{
    size_t idx = (size_t)blockIdx.x * blockDim.x + threadIdx.x;
    if (idx >= (size_t)NN_ * DIN) return;
    int i = (int)(idx >> 8), c = (int)(idx & 255);
    g_node[idx] = (c < 128) ? x_node[(size_t)i * 128 + c]
                            : x_log[(size_t)i * 128 + (c - 128)];
    g_nodeout[idx] = bias1[c];
    if (idx < NN_ * 4) { g_amax1[idx] = -FLT_MAX; g_den1[idx] = 0.f; }
    if (idx < (size_t)E1_ * 4) g_den2[idx] = 0.f;
}

// ---------------- layer-1 softmax + aggregate (R5 forms) ----------------
__global__ void exp1_kernel(const int* __restrict__ adj) {
    int idx = blockIdx.x * blockDim.x + threadIdx.x;
    if (idx >= E1_ * 4) return;
    int e = idx >> 2, h = idx & 3;
    int dst = adj[E1_ + e];
    float ex = expf(g_alpha1[idx] - g_amax1[dst * 4 + h]);
    g_alpha1[idx] = ex;
    atomicAdd(&g_den1[dst * 4 + h], ex);
}

// warp per edge, float4 lanes, v4 reductions. lane l covers channels 4l and 128+4l.
__global__ __launch_bounds__(256) void agg1_kernel(const int* __restrict__ adj) {
    int warp = (blockIdx.x * blockDim.x + threadIdx.x) >> 5;
    int lane = threadIdx.x & 31;
    if (warp >= E1_) return;
    int src = adj[warp], dst = adj[E1_ + warp];
    int h0 = lane >> 4;
    float a0 = g_alpha1[(size_t)warp * 4 + h0]     / (g_den1[(size_t)dst * 4 + h0]     + EPSV);
    float a1 = g_alpha1[(size_t)warp * 4 + 2 + h0] / (g_den1[(size_t)dst * 4 + 2 + h0] + EPSV);
    const float* xl = g_xl + (size_t)src * DIN;
    float* out = g_nodeout + (size_t)dst * DIN;
    float4 v0 = *(const float4*)&xl[lane * 4];
    float4 v1 = *(const float4*)&xl[128 + lane * 4];
    red_add_v4(&out[lane * 4],       make_float4(a0 * v0.x, a0 * v0.y, a0 * v0.z, a0 * v0.w));
    red_add_v4(&out[128 + lane * 4], make_float4(a1 * v1.x, a1 * v1.y, a1 * v1.z, a1 * v1.w));
}

// ---------------- layer-2 edge kernels ----------------
// warp per edge (R5 form); max-free softmax: write exp(logit), accumulate denom.
__global__ __launch_bounds__(256) void alpha2_kernel(const int* __restrict__ adj,
                                                     const int* __restrict__ efea,
                                                     const float* __restrict__ att)
{
    int warp = (blockIdx.x * blockDim.x + threadIdx.x) >> 5;
    int lane = threadIdx.x & 31;
    if (warp >= E2_) return;
    int src = adj[warp], dst = adj[E2_ + warp];
    int ef = efea[warp];
    float4 xlv = *(const float4*)&g_xl2  [(size_t)src * DED + lane * 4];
    float4 xrv = *(const float4*)&g_xr2  [(size_t)dst * DED + lane * 4];
    float4 eev = *(const float4*)&g_gfeat[(size_t)ef  * DED + lane * 4];
    float4 av  = *(const float4*)&att[lane * 4];
    float p;
    p  = lrelu02(xlv.x + xrv.x + eev.x) * av.x;
    p += lrelu02(xlv.y + xrv.y + eev.y) * av.y;
    p += lrelu02(xlv.z + xrv.z + eev.z) * av.z;
    p += lrelu02(xlv.w + xrv.w + eev.w) * av.w;
#pragma unroll
    for (int off = 4; off > 0; off >>= 1)
        p += __shfl_xor_sync(0xffffffff, p, off);
    if ((lane & 7) == 0) {
        int head = lane >> 3;
        float ex = expf(p);
        g_alpha2[(size_t)warp * 4 + head] = ex;
        atomicAdd(&g_den2[(size_t)dst * 4 + head], ex);
    }
}

__global__ void out_split_kernel(float* __restrict__ out, const float* __restrict__ bias2) {
    size_t idx = (size_t)blockIdx.x * blockDim.x + threadIdx.x;
    const size_t XN = (size_t)NN_ * 128;
    const size_t XT = (size_t)E1_ * 128;
    if (idx >= XN + XT + XN) return;
    if (idx < XN) {
        int i = (int)(idx >> 7), c = (int)(idx & 127);
        out[idx] = g_nodeout[(size_t)i * DIN + c];
    } else if (idx < XN + XT) {
        out[idx] = bias2[idx & 127];
    } else {
        size_t r = idx - (XN + XT);
        int i = (int)(r >> 7), c = (int)(r & 127);
        out[idx] = g_nodeout[(size_t)i * DIN + 128 + c];
    }
}

__global__ __launch_bounds__(256) void agg2_kernel(const int* __restrict__ adj,
                                                   float* __restrict__ out_xt)
{
    int warp = (blockIdx.x * blockDim.x + threadIdx.x) >> 5;
    int lane = threadIdx.x & 31;
    if (warp >= E2_) return;
    int src = adj[warp], dst = adj[(size_t)E2_ + warp];
    int h = lane >> 3;
    float a = g_alpha2[(size_t)warp * 4 + h] / (g_den2[(size_t)dst * 4 + h] + EPSV);
    float4 v = *(const float4*)&g_xl2[(size_t)src * DED + lane * 4];
    red_add_v4(&out_xt[(size_t)dst * DED + lane * 4],
               make_float4(a * v.x, a * v.y, a * v.z, a * v.w));
}

// ---------------- launch ----------------
extern "C" void kernel_launch(void* const* d_in, const int* in_sizes, int n_in,
                              void* d_out, int out_size)
{
    const float* x_node   = (const float*)d_in[0];
    const float* x_trace  = (const float*)d_in[1];
    const float* x_log    = (const float*)d_in[2];
    const int*   node_adj = (const int*)d_in[3];
    const int*   edge_adj = (const int*)d_in[4];
    const int*   edge_efea= (const int*)d_in[5];
    const float* n2n_Wl   = (const float*)d_in[6];
    const float* n2n_bl   = (const float*)d_in[7];
    const float* n2n_Wr   = (const float*)d_in[8];
    const float* n2n_br   = (const float*)d_in[9];
    const float* n2n_We   = (const float*)d_in[10];
    const float* n2n_att  = (const float*)d_in[11];
    const float* n2n_bias = (const float*)d_in[12];
    const float* e2n_Wl   = (const float*)d_in[13];
    const float* e2n_bl   = (const float*)d_in[14];
    const float* e2n_Wr   = (const float*)d_in[15];
    const float* e2n_br   = (const float*)d_in[16];
    const float* e2n_We   = (const float*)d_in[17];
    const float* e2n_att  = (const float*)d_in[18];
    const float* e2n_bias = (const float*)d_in[19];
    float* out = (float*)d_out;

    float* p_node;    cudaGetSymbolAddress((void**)&p_node,    g_node);
    float* p_xl;      cudaGetSymbolAddress((void**)&p_xl,      g_xl);
    float* p_xr;      cudaGetSymbolAddress((void**)&p_xr,      g_xr);
    float* p_nodeout; cudaGetSymbolAddress((void**)&p_nodeout, g_nodeout);
    float* p_xl2;     cudaGetSymbolAddress((void**)&p_xl2,     g_xl2);
    float* p_xr2;     cudaGetSymbolAddress((void**)&p_xr2,     g_xr2);
    float* p_g;       cudaGetSymbolAddress((void**)&p_g,       g_gfeat);

    const int SMEM_PIPE = 2 * STG * 4;          // 71680 (covers ET 128*132*4=67584 too)
    static cudaStream_t s1 = nullptr;
    static cudaEvent_t evA = nullptr, evB = nullptr;
    if (!s1) {
        cudaFuncSetAttribute(gemm_pipe, cudaFuncAttributeMaxDynamicSharedMemorySize, SMEM_PIPE);
        cudaFuncSetAttribute(gemm_alpha1_fused, cudaFuncAttributeMaxDynamicSharedMemorySize, SMEM_PIPE);
        cudaStreamCreateWithFlags(&s1, cudaStreamNonBlocking);
        cudaEventCreateWithFlags(&evA, cudaEventDisableTiming);
        cudaEventCreateWithFlags(&evB, cudaEventDisableTiming);
    }

    // fork: xl2/xr2 GEMM depends only on x_trace — run on side stream
    cudaEventRecord(evA, 0);
    cudaStreamWaitEvent(s1, evA, 0);
    {
        dim3 gdim(DED / TBN, E1_ / TBM, 2);
        gemm_pipe<<<gdim, 256, SMEM_PIPE, s1>>>(x_trace, e2n_Wl, e2n_Wr, e2n_bl, e2n_br,
                                                p_xl2, p_xr2, E1_, DED, DED);
    }
    cudaEventRecord(evB, s1);

    // main stream: prep -> xl/xr -> fused alpha1 -> softmax1 -> agg1 -> gfeat
    prep_kernel<<<(NN_ * DIN) / 256, 256>>>(x_node, x_log, n2n_bias);
    {
        dim3 gdim(DIN / TBN, NN_ / TBM, 2);
        gemm_pipe<<<gdim, 256, SMEM_PIPE>>>(p_node, n2n_Wl, n2n_Wr, n2n_bl, n2n_br,
                                            p_xl, p_xr, NN_, DIN, DIN);
    }
    {
        dim3 gdim(DIN / TBN, E1_ / TBM);
        gemm_alpha1_fused<<<gdim, 256, SMEM_PIPE>>>(x_trace, n2n_We, node_adj, n2n_att);
    }
    exp1_kernel<<<(E1_ * 4) / 256, 256>>>(node_adj);
    agg1_kernel<<<E1_ / 8, 256>>>(node_adj);
    {
        dim3 gdim(DED / TBN, NN_ / TBM, 1);
        gemm_pipe<<<gdim, 256, SMEM_PIPE>>>(p_nodeout, e2n_We, e2n_We, nullptr, nullptr,
                                            p_g, p_g, NN_, DED, DIN);
    }

    // join: alpha2 needs xl2/xr2 from the side stream
    cudaStreamWaitEvent(0, evB, 0);

    // layer-2 attention (max-free: exp + denom accumulate), then outputs
    alpha2_kernel<<<E2_ / 8, 256>>>(edge_adj, edge_efea, e2n_att);
    {
        size_t total = (size_t)NN_ * 128 * 2 + (size_t)E1_ * 128;
        out_split_kernel<<<(unsigned)((total + 255) / 256), 256>>>(out, e2n_bias);
    }
    agg2_kernel<<<E2_ / 8, 256>>>(edge_adj, out + (size_t)NN_ * 128);
}

// round 8
// speedup vs baseline: 1.2595x; 1.0229x over previous
#include <cuda_runtime.h>
#include <stdint.h>
#include <math.h>
#include <float.h>

// ---------------- problem constants ----------------
#define NN_   8192      // nodes
#define E1_   131072    // node-graph edges (= trace rows)
#define E2_   524288    // line-graph edges
#define DIN   256       // layer1 channels (4 heads x 64)
#define DED   128       // layer2 channels (4 heads x 32)
#define EPSV  1e-16f

// ---------------- scratch (static device, no allocs) ----------------
__device__ float g_node   [(size_t)NN_ * DIN];
__device__ float g_xl     [(size_t)NN_ * DIN];
__device__ float g_xr     [(size_t)NN_ * DIN];
__device__ float g_alpha1 [(size_t)E1_ * 4];    // logit, then exp(logit)
__device__ float g_den1   [(size_t)NN_ * 4];
__device__ float g_nodeout[(size_t)NN_ * DIN];
__device__ float g_xl2    [(size_t)E1_ * DED];
__device__ float g_xr2    [(size_t)E1_ * DED];
__device__ float g_gfeat  [(size_t)NN_ * DED];
__device__ float g_alpha2 [(size_t)E2_ * 4];    // exp(logit)
__device__ float g_den2   [(size_t)E1_ * 4];

// ---------------- helpers ----------------
__device__ __forceinline__ float lrelu02(float x) { return x > 0.f ? x : 0.2f * x; }
__device__ __forceinline__ uint32_t to_tf32(float v) {
    uint32_t t;
    asm("cvt.rna.tf32.f32 %0, %1;" : "=r"(t) : "f"(v));
    return t;
}
__device__ __forceinline__ void cp16(uint32_t dst, const void* src) {
    asm volatile("cp.async.cg.shared.global [%0], [%1], 16;" :: "r"(dst), "l"(src));
}
__device__ __forceinline__ void red_add_v4(float* addr, float4 v) {
    asm volatile("red.global.add.v4.f32 [%0], {%1,%2,%3,%4};"
                 :: "l"(addr), "f"(v.x), "f"(v.y), "f"(v.z), "f"(v.w) : "memory");
}

// ---------------- tf32 GEMM tiles ----------------
#define TBM 128
#define TBN 128
#define TBK 32
#define STG 8960                 // floats per stage: 128*36 + 32*136
#define AS(S,M,K_) smem[(S)*STG + (M)*36 + (K_)]
#define BS(S,KK,N_) smem[(S)*STG + 4608 + (KK)*136 + (N_)]
#define ET(R,C) smem[(R)*132 + (C)]

struct Frag { float c[4][4][4]; };

__device__ __forceinline__ void load_stage(float* smem, int s,
    const float* __restrict__ A, const float* __restrict__ W,
    int bm, int bn, int k0, int K, int Ncol, int tid)
{
#pragma unroll
    for (int i = 0; i < 4; i++) {
        int idx = tid + i * 256;
        int m = idx >> 3, kc = idx & 7;
        cp16((uint32_t)__cvta_generic_to_shared(&AS(s, m, kc * 4)),
             &A[(size_t)(bm + m) * K + k0 + kc * 4]);
    }
#pragma unroll
    for (int i = 0; i < 4; i++) {
        int idx = tid + i * 256;
        int kk = idx >> 5, nc = idx & 31;
        cp16((uint32_t)__cvta_generic_to_shared(&BS(s, kk, nc * 4)),
             &W[(size_t)(k0 + kk) * Ncol + bn + nc * 4]);
    }
    asm volatile("cp.async.commit_group;");
}

__device__ __forceinline__ void compute_stage(const float* smem, int s, Frag& f,
                                              int wm, int wn, int g, int tg)
{
#pragma unroll
    for (int ks = 0; ks < 4; ks++) {
        const int kb = ks * 8;
        uint32_t afr[4][4], bfr[4][2];
#pragma unroll
        for (int mt = 0; mt < 4; mt++) {
            int mr = wm + mt * 16 + g;
            afr[mt][0] = to_tf32(AS(s, mr,     kb + tg));
            afr[mt][1] = to_tf32(AS(s, mr + 8, kb + tg));
            afr[mt][2] = to_tf32(AS(s, mr,     kb + tg + 4));
            afr[mt][3] = to_tf32(AS(s, mr + 8, kb + tg + 4));
        }
#pragma unroll
        for (int nt = 0; nt < 4; nt++) {
            int nc = wn + nt * 8 + g;
            bfr[nt][0] = to_tf32(BS(s, kb + tg,     nc));
            bfr[nt][1] = to_tf32(BS(s, kb + tg + 4, nc));
        }
#pragma unroll
        for (int mt = 0; mt < 4; mt++)
#pragma unroll
            for (int nt = 0; nt < 4; nt++) {
                asm volatile(
                    "mma.sync.aligned.m16n8k8.row.col.f32.tf32.tf32.f32 "
                    "{%0,%1,%2,%3}, {%4,%5,%6,%7}, {%8,%9}, {%0,%1,%2,%3};"
                    : "+f"(f.c[mt][nt][0]), "+f"(f.c[mt][nt][1]),
                      "+f"(f.c[mt][nt][2]), "+f"(f.c[mt][nt][3])
                    : "r"(afr[mt][0]), "r"(afr[mt][1]),
                      "r"(afr[mt][2]), "r"(afr[mt][3]),
                      "r"(bfr[nt][0]), "r"(bfr[nt][1]));
            }
    }
}

// Pipelined GEMM, optionally dual-output (blockIdx.z selects W/bias/C).
__global__ __launch_bounds__(256) void gemm_pipe(
    const float* __restrict__ A,
    const float* __restrict__ W0, const float* __restrict__ W1,
    const float* __restrict__ b0, const float* __restrict__ b1,
    float* __restrict__ C0, float* __restrict__ C1,
    int M, int Ncol, int K)
{
    extern __shared__ float smem[];
    const int tid  = threadIdx.x;
    const int lane = tid & 31, warp = tid >> 5;
    const int g = lane >> 2, tg = lane & 3;
    const int wm = (warp >> 2) * 64, wn = (warp & 3) * 32;
    const int bm = blockIdx.y * TBM, bn = blockIdx.x * TBN;
    const int z  = blockIdx.z;
    const float* W    = z ? W1 : W0;
    const float* bias = z ? b1 : b0;
    float* C          = z ? C1 : C0;

    Frag f;
#pragma unroll
    for (int mt = 0; mt < 4; mt++)
#pragma unroll
        for (int nt = 0; nt < 4; nt++)
#pragma unroll
            for (int r = 0; r < 4; r++) f.c[mt][nt][r] = 0.f;

    const int KT = K / TBK;
    load_stage(smem, 0, A, W, bm, bn, 0, K, Ncol, tid);
    for (int kt = 0; kt < KT; kt++) {
        int s = kt & 1;
        if (kt + 1 < KT) {
            load_stage(smem, s ^ 1, A, W, bm, bn, (kt + 1) * TBK, K, Ncol, tid);
            asm volatile("cp.async.wait_group 1;");
        } else {
            asm volatile("cp.async.wait_group 0;");
        }
        __syncthreads();
        compute_stage(smem, s, f, wm, wn, g, tg);
        __syncthreads();
    }

#pragma unroll
    for (int mt = 0; mt < 4; mt++) {
        int r0 = bm + wm + mt * 16 + g;
#pragma unroll
        for (int nt = 0; nt < 4; nt++) {
            int col = bn + wn + nt * 8 + 2 * tg;
            float bb0 = bias ? bias[col] : 0.f;
            float bb1 = bias ? bias[col + 1] : 0.f;
            float2 v0 = make_float2(f.c[mt][nt][0] + bb0, f.c[mt][nt][1] + bb1);
            float2 v1 = make_float2(f.c[mt][nt][2] + bb0, f.c[mt][nt][3] + bb1);
            *(float2*)&C[(size_t)r0 * Ncol + col] = v0;
            *(float2*)&C[(size_t)(r0 + 8) * Ncol + col] = v1;
        }
    }
}

// Fused: e1 = trace @ We, kept in smem, then alpha1 logit = att . lrelu(xl[src]+xr[dst]+e1)
// Writes raw logit only (max-free softmax downstream; no atomicMax).
__global__ __launch_bounds__(256) void gemm_alpha1_fused(
    const float* __restrict__ A,      // x_trace [E1,128]
    const float* __restrict__ W,      // n2n_We [128,256]
    const int*   __restrict__ adj,    // node_adj [2,E1]
    const float* __restrict__ att)    // [4,64]
{
    extern __shared__ float smem[];
    const int tid  = threadIdx.x;
    const int lane = tid & 31, warp = tid >> 5;
    const int g = lane >> 2, tg = lane & 3;
    const int wm = (warp >> 2) * 64, wn = (warp & 3) * 32;
    const int bm = blockIdx.y * TBM, bn = blockIdx.x * TBN;
    const int K = 128, Ncol = DIN;

    Frag f;
#pragma unroll
    for (int mt = 0; mt < 4; mt++)
#pragma unroll
        for (int nt = 0; nt < 4; nt++)
#pragma unroll
            for (int r = 0; r < 4; r++) f.c[mt][nt][r] = 0.f;

    const int KT = K / TBK;
    load_stage(smem, 0, A, W, bm, bn, 0, K, Ncol, tid);
    for (int kt = 0; kt < KT; kt++) {
        int s = kt & 1;
        if (kt + 1 < KT) {
            load_stage(smem, s ^ 1, A, W, bm, bn, (kt + 1) * TBK, K, Ncol, tid);
            asm volatile("cp.async.wait_group 1;");
        } else {
            asm volatile("cp.async.wait_group 0;");
        }
        __syncthreads();
        compute_stage(smem, s, f, wm, wn, g, tg);
        __syncthreads();
    }

    // stage e1 tile into smem (overwrites stage buffers; synced above)
#pragma unroll
    for (int mt = 0; mt < 4; mt++) {
        int r0 = wm + mt * 16 + g;
#pragma unroll
        for (int nt = 0; nt < 4; nt++) {
            int col = wn + nt * 8 + 2 * tg;
            ET(r0, col)         = f.c[mt][nt][0];
            ET(r0, col + 1)     = f.c[mt][nt][1];
            ET(r0 + 8, col)     = f.c[mt][nt][2];
            ET(r0 + 8, col + 1) = f.c[mt][nt][3];
        }
    }
    __syncthreads();

    // phase 2: per-edge attention logits for this head-pair
    const float4 av = *(const float4*)&att[bn + lane * 4];
#pragma unroll 2
    for (int er = warp * 16; er < warp * 16 + 16; er++) {
        int e = bm + er;
        int src = adj[e], dst = adj[E1_ + e];
        float4 xlv = *(const float4*)&g_xl[(size_t)src * DIN + bn + lane * 4];
        float4 xrv = *(const float4*)&g_xr[(size_t)dst * DIN + bn + lane * 4];
        float p;
        p  = lrelu02(xlv.x + xrv.x + ET(er, lane * 4 + 0)) * av.x;
        p += lrelu02(xlv.y + xrv.y + ET(er, lane * 4 + 1)) * av.y;
        p += lrelu02(xlv.z + xrv.z + ET(er, lane * 4 + 2)) * av.z;
        p += lrelu02(xlv.w + xrv.w + ET(er, lane * 4 + 3)) * av.w;
#pragma unroll
        for (int off = 8; off > 0; off >>= 1)
            p += __shfl_xor_sync(0xffffffff, p, off);
        if (lane == 0 || lane == 16) {
            int head = 2 * blockIdx.x + (lane >> 4);
            g_alpha1[(size_t)e * 4 + head] = p;
        }
    }
}

// ---------------- prep: concat + inits ----------------
__global__ void prep_kernel(const float* __restrict__ x_node,
                            const float* __restrict__ x_log,
                            const float* __restrict__ bias1)
{
    size_t idx = (size_t)blockIdx.x * blockDim.x + threadIdx.x;
    if (idx >= (size_t)NN_ * DIN) return;
    int i = (int)(idx >> 8), c = (int)(idx & 255);
    g_node[idx] = (c < 128) ? x_node[(size_t)i * 128 + c]
                            : x_log[(size_t)i * 128 + (c - 128)];
    g_nodeout[idx] = bias1[c];
    if (idx < NN_ * 4) g_den1[idx] = 0.f;
    if (idx < (size_t)E1_ * 4) g_den2[idx] = 0.f;
}

// ---------------- layer-1 softmax (max-free) + aggregate ----------------
__global__ void exp1_kernel(const int* __restrict__ adj) {
    int idx = blockIdx.x * blockDim.x + threadIdx.x;
    if (idx >= E1_ * 4) return;
    int e = idx >> 2, h = idx & 3;
    int dst = adj[E1_ + e];
    float ex = expf(g_alpha1[idx]);
    g_alpha1[idx] = ex;
    atomicAdd(&g_den1[dst * 4 + h], ex);
}

// warp per edge, float4 lanes, v4 reductions. lane l covers channels 4l and 128+4l.
__global__ __launch_bounds__(256) void agg1_kernel(const int* __restrict__ adj) {
    int warp = (blockIdx.x * blockDim.x + threadIdx.x) >> 5;
    int lane = threadIdx.x & 31;
    if (warp >= E1_) return;
    int src = adj[warp], dst = adj[E1_ + warp];
    int h0 = lane >> 4;
    float a0 = g_alpha1[(size_t)warp * 4 + h0]     / (g_den1[(size_t)dst * 4 + h0]     + EPSV);
    float a1 = g_alpha1[(size_t)warp * 4 + 2 + h0] / (g_den1[(size_t)dst * 4 + 2 + h0] + EPSV);
    const float* xl = g_xl + (size_t)src * DIN;
    float* out = g_nodeout + (size_t)dst * DIN;
    float4 v0 = *(const float4*)&xl[lane * 4];
    float4 v1 = *(const float4*)&xl[128 + lane * 4];
    red_add_v4(&out[lane * 4],       make_float4(a0 * v0.x, a0 * v0.y, a0 * v0.z, a0 * v0.w));
    red_add_v4(&out[128 + lane * 4], make_float4(a1 * v1.x, a1 * v1.y, a1 * v1.z, a1 * v1.w));
}

// ---------------- layer-2 edge kernels ----------------
// warp per edge; max-free softmax: write exp(logit), accumulate denom.
__global__ __launch_bounds__(256) void alpha2_kernel(const int* __restrict__ adj,
                                                     const int* __restrict__ efea,
                                                     const float* __restrict__ att)
{
    int warp = (blockIdx.x * blockDim.x + threadIdx.x) >> 5;
    int lane = threadIdx.x & 31;
    if (warp >= E2_) return;
    int src = adj[warp], dst = adj[E2_ + warp];
    int ef = efea[warp];
    float4 xlv = *(const float4*)&g_xl2  [(size_t)src * DED + lane * 4];
    float4 xrv = *(const float4*)&g_xr2  [(size_t)dst * DED + lane * 4];
    float4 eev = *(const float4*)&g_gfeat[(size_t)ef  * DED + lane * 4];
    float4 av  = *(const float4*)&att[lane * 4];
    float p;
    p  = lrelu02(xlv.x + xrv.x + eev.x) * av.x;
    p += lrelu02(xlv.y + xrv.y + eev.y) * av.y;
    p += lrelu02(xlv.z + xrv.z + eev.z) * av.z;
    p += lrelu02(xlv.w + xrv.w + eev.w) * av.w;
#pragma unroll
    for (int off = 4; off > 0; off >>= 1)
        p += __shfl_xor_sync(0xffffffff, p, off);
    if ((lane & 7) == 0) {
        int head = lane >> 3;
        float ex = expf(p);
        g_alpha2[(size_t)warp * 4 + head] = ex;
        atomicAdd(&g_den2[(size_t)dst * 4 + head], ex);
    }
}

// seed xt output region with bias2 (independent of all compute)
__global__ void seed_xt_kernel(float* __restrict__ out_xt, const float* __restrict__ bias2) {
    size_t idx = (size_t)blockIdx.x * blockDim.x + threadIdx.x;
    if (idx >= (size_t)E1_ * 128) return;
    out_xt[idx] = bias2[idx & 127];
}

// copy nodeout halves into xn / xlg regions of out
__global__ void copy_nodeout_kernel(float* __restrict__ out) {
    size_t idx = (size_t)blockIdx.x * blockDim.x + threadIdx.x;
    const size_t XN = (size_t)NN_ * 128;
    const size_t XT = (size_t)E1_ * 128;
    if (idx >= 2 * XN) return;
    if (idx < XN) {
        int i = (int)(idx >> 7), c = (int)(idx & 127);
        out[idx] = g_nodeout[(size_t)i * DIN + c];
    } else {
        size_t r = idx - XN;
        int i = (int)(r >> 7), c = (int)(r & 127);
        out[XT + idx] = g_nodeout[(size_t)i * DIN + 128 + c];   // XN + XT + r
    }
}

__global__ __launch_bounds__(256) void agg2_kernel(const int* __restrict__ adj,
                                                   float* __restrict__ out_xt)
{
    int warp = (blockIdx.x * blockDim.x + threadIdx.x) >> 5;
    int lane = threadIdx.x & 31;
    if (warp >= E2_) return;
    int src = adj[warp], dst = adj[(size_t)E2_ + warp];
    int h = lane >> 3;
    float a = g_alpha2[(size_t)warp * 4 + h] / (g_den2[(size_t)dst * 4 + h] + EPSV);
    float4 v = *(const float4*)&g_xl2[(size_t)src * DED + lane * 4];
    red_add_v4(&out_xt[(size_t)dst * DED + lane * 4],
               make_float4(a * v.x, a * v.y, a * v.z, a * v.w));
}

// ---------------- launch ----------------
extern "C" void kernel_launch(void* const* d_in, const int* in_sizes, int n_in,
                              void* d_out, int out_size)
{
    const float* x_node   = (const float*)d_in[0];
    const float* x_trace  = (const float*)d_in[1];
    const float* x_log    = (const float*)d_in[2];
    const int*   node_adj = (const int*)d_in[3];
    const int*   edge_adj = (const int*)d_in[4];
    const int*   edge_efea= (const int*)d_in[5];
    const float* n2n_Wl   = (const float*)d_in[6];
    const float* n2n_bl   = (const float*)d_in[7];
    const float* n2n_Wr   = (const float*)d_in[8];
    const float* n2n_br   = (const float*)d_in[9];
    const float* n2n_We   = (const float*)d_in[10];
    const float* n2n_att  = (const float*)d_in[11];
    const float* n2n_bias = (const float*)d_in[12];
    const float* e2n_Wl   = (const float*)d_in[13];
    const float* e2n_bl   = (const float*)d_in[14];
    const float* e2n_Wr   = (const float*)d_in[15];
    const float* e2n_br   = (const float*)d_in[16];
    const float* e2n_We   = (const float*)d_in[17];
    const float* e2n_att  = (const float*)d_in[18];
    const float* e2n_bias = (const float*)d_in[19];
    float* out = (float*)d_out;
    float* out_xt = out + (size_t)NN_ * 128;

    float* p_node;    cudaGetSymbolAddress((void**)&p_node,    g_node);
    float* p_xl;      cudaGetSymbolAddress((void**)&p_xl,      g_xl);
    float* p_xr;      cudaGetSymbolAddress((void**)&p_xr,      g_xr);
    float* p_nodeout; cudaGetSymbolAddress((void**)&p_nodeout, g_nodeout);
    float* p_xl2;     cudaGetSymbolAddress((void**)&p_xl2,     g_xl2);
    float* p_xr2;     cudaGetSymbolAddress((void**)&p_xr2,     g_xr2);
    float* p_g;       cudaGetSymbolAddress((void**)&p_g,       g_gfeat);

    const int SMEM_PIPE = 2 * STG * 4;          // 71680 (covers ET 128*132*4=67584 too)
    static cudaStream_t s1 = nullptr;
    static cudaEvent_t evA = nullptr, evB = nullptr, evC = nullptr, evD = nullptr;
    if (!s1) {
        cudaFuncSetAttribute(gemm_pipe, cudaFuncAttributeMaxDynamicSharedMemorySize, SMEM_PIPE);
        cudaFuncSetAttribute(gemm_alpha1_fused, cudaFuncAttributeMaxDynamicSharedMemorySize, SMEM_PIPE);
        cudaStreamCreateWithFlags(&s1, cudaStreamNonBlocking);
        cudaEventCreateWithFlags(&evA, cudaEventDisableTiming);
        cudaEventCreateWithFlags(&evB, cudaEventDisableTiming);
        cudaEventCreateWithFlags(&evC, cudaEventDisableTiming);
        cudaEventCreateWithFlags(&evD, cudaEventDisableTiming);
    }

    // fork side stream: seed xt output + xl2/xr2 GEMM (depend only on inputs)
    cudaEventRecord(evA, 0);
    cudaStreamWaitEvent(s1, evA, 0);
    seed_xt_kernel<<<(E1_ * 128) / 256, 256, 0, s1>>>(out_xt, e2n_bias);
    {
        dim3 gdim(DED / TBN, E1_ / TBM, 2);
        gemm_pipe<<<gdim, 256, SMEM_PIPE, s1>>>(x_trace, e2n_Wl, e2n_Wr, e2n_bl, e2n_br,
                                                p_xl2, p_xr2, E1_, DED, DED);
    }
    cudaEventRecord(evB, s1);

    // main stream: prep -> xl/xr -> fused alpha1 -> exp1 -> agg1
    prep_kernel<<<(NN_ * DIN) / 256, 256>>>(x_node, x_log, n2n_bias);
    {
        dim3 gdim(DIN / TBN, NN_ / TBM, 2);
        gemm_pipe<<<gdim, 256, SMEM_PIPE>>>(p_node, n2n_Wl, n2n_Wr, n2n_bl, n2n_br,
                                            p_xl, p_xr, NN_, DIN, DIN);
    }
    {
        dim3 gdim(DIN / TBN, E1_ / TBM);
        gemm_alpha1_fused<<<gdim, 256, SMEM_PIPE>>>(x_trace, n2n_We, node_adj, n2n_att);
    }
    exp1_kernel<<<(E1_ * 4) / 256, 256>>>(node_adj);
    agg1_kernel<<<E1_ / 8, 256>>>(node_adj);
    cudaEventRecord(evC, 0);   // nodeout final

    // side stream: copy nodeout -> out (xn, xlg) while main does gfeat/alpha2/agg2
    cudaStreamWaitEvent(s1, evC, 0);
    copy_nodeout_kernel<<<(2 * NN_ * 128) / 256, 256, 0, s1>>>(out);
    cudaEventRecord(evD, s1);

    // main: gfeat = node_out @ We2
    {
        dim3 gdim(DED / TBN, NN_ / TBM, 1);
        gemm_pipe<<<gdim, 256, SMEM_PIPE>>>(p_nodeout, e2n_We, e2n_We, nullptr, nullptr,
                                            p_g, p_g, NN_, DED, DIN);
    }

    // join: alpha2 needs xl2/xr2 (and agg2 needs seeded xt) from side stream
    cudaStreamWaitEvent(0, evB, 0);

    alpha2_kernel<<<E2_ / 8, 256>>>(edge_adj, edge_efea, e2n_att);
    agg2_kernel<<<E2_ / 8, 256>>>(edge_adj, out_xt);

    // final join: ensure copy_nodeout completes within stream-0 ordering
    cudaStreamWaitEvent(0, evD, 0);
}

// round 9
// speedup vs baseline: 1.3619x; 1.0813x over previous
#include <cuda_runtime.h>
#include <stdint.h>
#include <math.h>
#include <float.h>

// ---------------- problem constants ----------------
#define NN_   8192      // nodes
#define E1_   131072    // node-graph edges (= trace rows)
#define E2_   524288    // line-graph edges
#define DIN   256       // layer1 channels (4 heads x 64)
#define DED   128       // layer2 channels (4 heads x 32)
#define EPSV  1e-16f

// ---------------- scratch (static device, no allocs) ----------------
__device__ float g_node   [(size_t)NN_ * DIN];
__device__ float g_xl     [(size_t)NN_ * DIN];
__device__ float g_xr     [(size_t)NN_ * DIN];
__device__ float g_alpha1 [(size_t)E1_ * 4];    // raw logits
__device__ float g_den1   [(size_t)NN_ * 4];
__device__ float g_nodeout[(size_t)NN_ * DIN];  // numerator, then normalized
__device__ float g_xl2    [(size_t)E1_ * DED];
__device__ float g_xr2    [(size_t)E1_ * DED];
__device__ float g_gfeat  [(size_t)NN_ * DED];
__device__ float g_den2   [(size_t)E1_ * 4];

// ---------------- helpers ----------------
__device__ __forceinline__ float lrelu02(float x) { return x > 0.f ? x : 0.2f * x; }
__device__ __forceinline__ uint32_t to_tf32(float v) {
    uint32_t t;
    asm("cvt.rna.tf32.f32 %0, %1;" : "=r"(t) : "f"(v));
    return t;
}
__device__ __forceinline__ void cp16(uint32_t dst, const void* src) {
    asm volatile("cp.async.cg.shared.global [%0], [%1], 16;" :: "r"(dst), "l"(src));
}
__device__ __forceinline__ void red_add_v4(float* addr, float4 v) {
    asm volatile("red.global.add.v4.f32 [%0], {%1,%2,%3,%4};"
                 :: "l"(addr), "f"(v.x), "f"(v.y), "f"(v.z), "f"(v.w) : "memory");
}

// ---------------- tf32 GEMM tiles ----------------
#define TBM 128
#define TBN 128
#define TBK 32
#define STG 8960                 // floats per stage: 128*36 + 32*136
#define AS(S,M,K_) smem[(S)*STG + (M)*36 + (K_)]
#define BS(S,KK,N_) smem[(S)*STG + 4608 + (KK)*136 + (N_)]
#define ET(R,C) smem[(R)*132 + (C)]

struct Frag { float c[4][4][4]; };

__device__ __forceinline__ void load_stage(float* smem, int s,
    const float* __restrict__ A, const float* __restrict__ W,
    int bm, int bn, int k0, int K, int Ncol, int tid)
{
#pragma unroll
    for (int i = 0; i < 4; i++) {
        int idx = tid + i * 256;
        int m = idx >> 3, kc = idx & 7;
        cp16((uint32_t)__cvta_generic_to_shared(&AS(s, m, kc * 4)),
             &A[(size_t)(bm + m) * K + k0 + kc * 4]);
    }
#pragma unroll
    for (int i = 0; i < 4; i++) {
        int idx = tid + i * 256;
        int kk = idx >> 5, nc = idx & 31;
        cp16((uint32_t)__cvta_generic_to_shared(&BS(s, kk, nc * 4)),
             &W[(size_t)(k0 + kk) * Ncol + bn + nc * 4]);
    }
    asm volatile("cp.async.commit_group;");
}

__device__ __forceinline__ void compute_stage(const float* smem, int s, Frag& f,
                                              int wm, int wn, int g, int tg)
{
#pragma unroll
    for (int ks = 0; ks < 4; ks++) {
        const int kb = ks * 8;
        uint32_t afr[4][4], bfr[4][2];
#pragma unroll
        for (int mt = 0; mt < 4; mt++) {
            int mr = wm + mt * 16 + g;
            afr[mt][0] = to_tf32(AS(s, mr,     kb + tg));
            afr[mt][1] = to_tf32(AS(s, mr + 8, kb + tg));
            afr[mt][2] = to_tf32(AS(s, mr,     kb + tg + 4));
            afr[mt][3] = to_tf32(AS(s, mr + 8, kb + tg + 4));
        }
#pragma unroll
        for (int nt = 0; nt < 4; nt++) {
            int nc = wn + nt * 8 + g;
            bfr[nt][0] = to_tf32(BS(s, kb + tg,     nc));
            bfr[nt][1] = to_tf32(BS(s, kb + tg + 4, nc));
        }
#pragma unroll
        for (int mt = 0; mt < 4; mt++)
#pragma unroll
            for (int nt = 0; nt < 4; nt++) {
                asm volatile(
                    "mma.sync.aligned.m16n8k8.row.col.f32.tf32.tf32.f32 "
                    "{%0,%1,%2,%3}, {%4,%5,%6,%7}, {%8,%9}, {%0,%1,%2,%3};"
                    : "+f"(f.c[mt][nt][0]), "+f"(f.c[mt][nt][1]),
                      "+f"(f.c[mt][nt][2]), "+f"(f.c[mt][nt][3])
                    : "r"(afr[mt][0]), "r"(afr[mt][1]),
                      "r"(afr[mt][2]), "r"(afr[mt][3]),
                      "r"(bfr[nt][0]), "r"(bfr[nt][1]));
            }
    }
}

// Pipelined GEMM, optionally dual-output (blockIdx.z selects W/bias/C).
__global__ __launch_bounds__(256) void gemm_pipe(
    const float* __restrict__ A,
    const float* __restrict__ W0, const float* __restrict__ W1,
    const float* __restrict__ b0, const float* __restrict__ b1,
    float* __restrict__ C0, float* __restrict__ C1,
    int M, int Ncol, int K)
{
    extern __shared__ float smem[];
    const int tid  = threadIdx.x;
    const int lane = tid & 31, warp = tid >> 5;
    const int g = lane >> 2, tg = lane & 3;
    const int wm = (warp >> 2) * 64, wn = (warp & 3) * 32;
    const int bm = blockIdx.y * TBM, bn = blockIdx.x * TBN;
    const int z  = blockIdx.z;
    const float* W    = z ? W1 : W0;
    const float* bias = z ? b1 : b0;
    float* C          = z ? C1 : C0;

    Frag f;
#pragma unroll
    for (int mt = 0; mt < 4; mt++)
#pragma unroll
        for (int nt = 0; nt < 4; nt++)
#pragma unroll
            for (int r = 0; r < 4; r++) f.c[mt][nt][r] = 0.f;

    const int KT = K / TBK;
    load_stage(smem, 0, A, W, bm, bn, 0, K, Ncol, tid);
    for (int kt = 0; kt < KT; kt++) {
        int s = kt & 1;
        if (kt + 1 < KT) {
            load_stage(smem, s ^ 1, A, W, bm, bn, (kt + 1) * TBK, K, Ncol, tid);
            asm volatile("cp.async.wait_group 1;");
        } else {
            asm volatile("cp.async.wait_group 0;");
        }
        __syncthreads();
        compute_stage(smem, s, f, wm, wn, g, tg);
        __syncthreads();
    }

#pragma unroll
    for (int mt = 0; mt < 4; mt++) {
        int r0 = bm + wm + mt * 16 + g;
#pragma unroll
        for (int nt = 0; nt < 4; nt++) {
            int col = bn + wn + nt * 8 + 2 * tg;
            float bb0 = bias ? bias[col] : 0.f;
            float bb1 = bias ? bias[col + 1] : 0.f;
            float2 v0 = make_float2(f.c[mt][nt][0] + bb0, f.c[mt][nt][1] + bb1);
            float2 v1 = make_float2(f.c[mt][nt][2] + bb0, f.c[mt][nt][3] + bb1);
            *(float2*)&C[(size_t)r0 * Ncol + col] = v0;
            *(float2*)&C[(size_t)(r0 + 8) * Ncol + col] = v1;
        }
    }
}

// Fused: e1 = trace @ We, kept in smem, then alpha1 logit = att . lrelu(xl[src]+xr[dst]+e1)
// Writes raw logit only.
__global__ __launch_bounds__(256) void gemm_alpha1_fused(
    const float* __restrict__ A,      // x_trace [E1,128]
    const float* __restrict__ W,      // n2n_We [128,256]
    const int*   __restrict__ adj,    // node_adj [2,E1]
    const float* __restrict__ att)    // [4,64]
{
    extern __shared__ float smem[];
    const int tid  = threadIdx.x;
    const int lane = tid & 31, warp = tid >> 5;
    const int g = lane >> 2, tg = lane & 3;
    const int wm = (warp >> 2) * 64, wn = (warp & 3) * 32;
    const int bm = blockIdx.y * TBM, bn = blockIdx.x * TBN;
    const int K = 128, Ncol = DIN;

    Frag f;
#pragma unroll
    for (int mt = 0; mt < 4; mt++)
#pragma unroll
        for (int nt = 0; nt < 4; nt++)
#pragma unroll
            for (int r = 0; r < 4; r++) f.c[mt][nt][r] = 0.f;

    const int KT = K / TBK;
    load_stage(smem, 0, A, W, bm, bn, 0, K, Ncol, tid);
    for (int kt = 0; kt < KT; kt++) {
        int s = kt & 1;
        if (kt + 1 < KT) {
            load_stage(smem, s ^ 1, A, W, bm, bn, (kt + 1) * TBK, K, Ncol, tid);
            asm volatile("cp.async.wait_group 1;");
        } else {
            asm volatile("cp.async.wait_group 0;");
        }
        __syncthreads();
        compute_stage(smem, s, f, wm, wn, g, tg);
        __syncthreads();
    }

    // stage e1 tile into smem (overwrites stage buffers; synced above)
#pragma unroll
    for (int mt = 0; mt < 4; mt++) {
        int r0 = wm + mt * 16 + g;
#pragma unroll
        for (int nt = 0; nt < 4; nt++) {
            int col = wn + nt * 8 + 2 * tg;
            ET(r0, col)         = f.c[mt][nt][0];
            ET(r0, col + 1)     = f.c[mt][nt][1];
            ET(r0 + 8, col)     = f.c[mt][nt][2];
            ET(r0 + 8, col + 1) = f.c[mt][nt][3];
        }
    }
    __syncthreads();

    // phase 2: per-edge attention logits for this head-pair
    const float4 av = *(const float4*)&att[bn + lane * 4];
#pragma unroll 2
    for (int er = warp * 16; er < warp * 16 + 16; er++) {
        int e = bm + er;
        int src = adj[e], dst = adj[E1_ + e];
        float4 xlv = *(const float4*)&g_xl[(size_t)src * DIN + bn + lane * 4];
        float4 xrv = *(const float4*)&g_xr[(size_t)dst * DIN + bn + lane * 4];
        float p;
        p  = lrelu02(xlv.x + xrv.x + ET(er, lane * 4 + 0)) * av.x;
        p += lrelu02(xlv.y + xrv.y + ET(er, lane * 4 + 1)) * av.y;
        p += lrelu02(xlv.z + xrv.z + ET(er, lane * 4 + 2)) * av.z;
        p += lrelu02(xlv.w + xrv.w + ET(er, lane * 4 + 3)) * av.w;
#pragma unroll
        for (int off = 8; off > 0; off >>= 1)
            p += __shfl_xor_sync(0xffffffff, p, off);
        if (lane == 0 || lane == 16) {
            int head = 2 * blockIdx.x + (lane >> 4);
            g_alpha1[(size_t)e * 4 + head] = p;
        }
    }
}

// ---------------- prep: concat + inits (nodeout zero-seeded: numerator accumulator) ----------------
__global__ void prep_kernel(const float* __restrict__ x_node,
                            const float* __restrict__ x_log)
{
    size_t idx = (size_t)blockIdx.x * blockDim.x + threadIdx.x;
    if (idx >= (size_t)NN_ * DIN) return;
    int i = (int)(idx >> 8), c = (int)(idx & 255);
    g_node[idx] = (c < 128) ? x_node[(size_t)i * 128 + c]
                            : x_log[(size_t)i * 128 + (c - 128)];
    g_nodeout[idx] = 0.f;
    if (idx < NN_ * 4) g_den1[idx] = 0.f;
    if (idx < (size_t)E1_ * 4) g_den2[idx] = 0.f;
}

// ---------------- layer-1 merged exp+aggregate (numerator + denominator) ----------------
// warp per edge; lane l covers channels 4l (head l>>4) and 128+4l (head 2+(l>>4)).
__global__ __launch_bounds__(256) void agg1_kernel(const int* __restrict__ adj) {
    int warp = (blockIdx.x * blockDim.x + threadIdx.x) >> 5;
    int lane = threadIdx.x & 31;
    if (warp >= E1_) return;
    int src = adj[warp], dst = adj[E1_ + warp];
    int h0 = lane >> 4;
    float ex0 = expf(g_alpha1[(size_t)warp * 4 + h0]);
    float ex1 = expf(g_alpha1[(size_t)warp * 4 + 2 + h0]);
    const float* xl = g_xl + (size_t)src * DIN;
    float* out = g_nodeout + (size_t)dst * DIN;
    float4 v0 = *(const float4*)&xl[lane * 4];
    float4 v1 = *(const float4*)&xl[128 + lane * 4];
    red_add_v4(&out[lane * 4],       make_float4(ex0 * v0.x, ex0 * v0.y, ex0 * v0.z, ex0 * v0.w));
    red_add_v4(&out[128 + lane * 4], make_float4(ex1 * v1.x, ex1 * v1.y, ex1 * v1.z, ex1 * v1.w));
    if (lane == 0 || lane == 16) {
        atomicAdd(&g_den1[(size_t)dst * 4 + h0],     ex0);
        atomicAdd(&g_den1[(size_t)dst * 4 + 2 + h0], ex1);
    }
}

// normalize nodeout in place AND write xn / xlg output regions
__global__ void normalize_node_kernel(float* __restrict__ out, const float* __restrict__ bias1) {
    size_t idx = (size_t)blockIdx.x * blockDim.x + threadIdx.x;
    if (idx >= (size_t)NN_ * DIN) return;
    int i = (int)(idx >> 8), c = (int)(idx & 255);
    float v = g_nodeout[idx] / (g_den1[i * 4 + (c >> 6)] + EPSV) + bias1[c];
    g_nodeout[idx] = v;
    const size_t XN = (size_t)NN_ * 128;
    const size_t XT = (size_t)E1_ * 128;
    if (c < 128) out[(size_t)i * 128 + c] = v;
    else         out[XN + XT + (size_t)i * 128 + (c - 128)] = v;
}

// ---------------- layer-2 merged attention + aggregate ----------------
// warp per edge; lane l covers channels [4l..4l+3], head = l>>3.
// Computes logit, exp, accumulates numerator (ex * xl2[src]) into out_xt[dst]
// and denominator into den2 — xl2[src] row reused from registers.
__global__ __launch_bounds__(256) void alpha2_agg2_kernel(const int* __restrict__ adj,
                                                          const int* __restrict__ efea,
                                                          const float* __restrict__ att,
                                                          float* __restrict__ out_xt)
{
    int warp = (blockIdx.x * blockDim.x + threadIdx.x) >> 5;
    int lane = threadIdx.x & 31;
    if (warp >= E2_) return;
    int src = adj[warp], dst = adj[E2_ + warp];
    int ef = efea[warp];
    float4 xlv = *(const float4*)&g_xl2  [(size_t)src * DED + lane * 4];
    float4 xrv = *(const float4*)&g_xr2  [(size_t)dst * DED + lane * 4];
    float4 eev = *(const float4*)&g_gfeat[(size_t)ef  * DED + lane * 4];
    float4 av  = *(const float4*)&att[lane * 4];
    float p;
    p  = lrelu02(xlv.x + xrv.x + eev.x) * av.x;
    p += lrelu02(xlv.y + xrv.y + eev.y) * av.y;
    p += lrelu02(xlv.z + xrv.z + eev.z) * av.z;
    p += lrelu02(xlv.w + xrv.w + eev.w) * av.w;
#pragma unroll
    for (int off = 4; off > 0; off >>= 1)
        p += __shfl_xor_sync(0xffffffff, p, off);
    float ex = expf(p);                     // per-head value, broadcast in 8-lane group
    red_add_v4(&out_xt[(size_t)dst * DED + lane * 4],
               make_float4(ex * xlv.x, ex * xlv.y, ex * xlv.z, ex * xlv.w));
    if ((lane & 7) == 0)
        atomicAdd(&g_den2[(size_t)dst * 4 + (lane >> 3)], ex);
}

// seed xt output region with zeros (numerator accumulator)
__global__ void seed_xt_kernel(float* __restrict__ out_xt) {
    size_t idx = (size_t)blockIdx.x * blockDim.x + threadIdx.x;
    if (idx >= (size_t)E1_ * 128) return;
    out_xt[idx] = 0.f;
}

// normalize xt in place: divide by den, add bias
__global__ void normalize_xt_kernel(float* __restrict__ out_xt, const float* __restrict__ bias2) {
    size_t idx = (size_t)blockIdx.x * blockDim.x + threadIdx.x;
    if (idx >= (size_t)E1_ * 128) return;
    int e = (int)(idx >> 7), c = (int)(idx & 127);
    out_xt[idx] = out_xt[idx] / (g_den2[(size_t)e * 4 + (c >> 5)] + EPSV) + bias2[c];
}

// ---------------- launch ----------------
extern "C" void kernel_launch(void* const* d_in, const int* in_sizes, int n_in,
                              void* d_out, int out_size)
{
    const float* x_node   = (const float*)d_in[0];
    const float* x_trace  = (const float*)d_in[1];
    const float* x_log    = (const float*)d_in[2];
    const int*   node_adj = (const int*)d_in[3];
    const int*   edge_adj = (const int*)d_in[4];
    const int*   edge_efea= (const int*)d_in[5];
    const float* n2n_Wl   = (const float*)d_in[6];
    const float* n2n_bl   = (const float*)d_in[7];
    const float* n2n_Wr   = (const float*)d_in[8];
    const float* n2n_br   = (const float*)d_in[9];
    const float* n2n_We   = (const float*)d_in[10];
    const float* n2n_att  = (const float*)d_in[11];
    const float* n2n_bias = (const float*)d_in[12];
    const float* e2n_Wl   = (const float*)d_in[13];
    const float* e2n_bl   = (const float*)d_in[14];
    const float* e2n_Wr   = (const float*)d_in[15];
    const float* e2n_br   = (const float*)d_in[16];
    const float* e2n_We   = (const float*)d_in[17];
    const float* e2n_att  = (const float*)d_in[18];
    const float* e2n_bias = (const float*)d_in[19];
    float* out = (float*)d_out;
    float* out_xt = out + (size_t)NN_ * 128;

    float* p_node;    cudaGetSymbolAddress((void**)&p_node,    g_node);
    float* p_xl;      cudaGetSymbolAddress((void**)&p_xl,      g_xl);
    float* p_xr;      cudaGetSymbolAddress((void**)&p_xr,      g_xr);
    float* p_nodeout; cudaGetSymbolAddress((void**)&p_nodeout, g_nodeout);
    float* p_xl2;     cudaGetSymbolAddress((void**)&p_xl2,     g_xl2);
    float* p_xr2;     cudaGetSymbolAddress((void**)&p_xr2,     g_xr2);
    float* p_g;       cudaGetSymbolAddress((void**)&p_g,       g_gfeat);

    const int SMEM_PIPE = 2 * STG * 4;          // 71680 (covers ET 128*132*4=67584 too)
    static cudaStream_t s1 = nullptr;
    static cudaEvent_t evA = nullptr, evB = nullptr;
    if (!s1) {
        cudaFuncSetAttribute(gemm_pipe, cudaFuncAttributeMaxDynamicSharedMemorySize, SMEM_PIPE);
        cudaFuncSetAttribute(gemm_alpha1_fused, cudaFuncAttributeMaxDynamicSharedMemorySize, SMEM_PIPE);
        cudaStreamCreateWithFlags(&s1, cudaStreamNonBlocking);
        cudaEventCreateWithFlags(&evA, cudaEventDisableTiming);
        cudaEventCreateWithFlags(&evB, cudaEventDisableTiming);
    }

    // fork side stream: zero-seed xt numerator + xl2/xr2 GEMM (depend only on inputs)
    cudaEventRecord(evA, 0);
    cudaStreamWaitEvent(s1, evA, 0);
    seed_xt_kernel<<<(E1_ * 128) / 256, 256, 0, s1>>>(out_xt);
    {
        dim3 gdim(DED / TBN, E1_ / TBM, 2);
        gemm_pipe<<<gdim, 256, SMEM_PIPE, s1>>>(x_trace, e2n_Wl, e2n_Wr, e2n_bl, e2n_br,
                                                p_xl2, p_xr2, E1_, DED, DED);
    }
    cudaEventRecord(evB, s1);

    // main stream: prep -> xl/xr -> fused alpha1 -> merged agg1 -> normalize_node
    prep_kernel<<<(NN_ * DIN) / 256, 256>>>(x_node, x_log);
    {
        dim3 gdim(DIN / TBN, NN_ / TBM, 2);
        gemm_pipe<<<gdim, 256, SMEM_PIPE>>>(p_node, n2n_Wl, n2n_Wr, n2n_bl, n2n_br,
                                            p_xl, p_xr, NN_, DIN, DIN);
    }
    {
        dim3 gdim(DIN / TBN, E1_ / TBM);
        gemm_alpha1_fused<<<gdim, 256, SMEM_PIPE>>>(x_trace, n2n_We, node_adj, n2n_att);
    }
    agg1_kernel<<<E1_ / 8, 256>>>(node_adj);
    normalize_node_kernel<<<(NN_ * DIN) / 256, 256>>>(out, n2n_bias);

    // main: gfeat = node_out @ We2
    {
        dim3 gdim(DED / TBN, NN_ / TBM, 1);
        gemm_pipe<<<gdim, 256, SMEM_PIPE>>>(p_nodeout, e2n_We, e2n_We, nullptr, nullptr,
                                            p_g, p_g, NN_, DED, DIN);
    }

    // join: merged layer-2 needs xl2/xr2 + seeded xt from side stream
    cudaStreamWaitEvent(0, evB, 0);

    alpha2_agg2_kernel<<<E2_ / 8, 256>>>(edge_adj, edge_efea, e2n_att, out_xt);
    normalize_xt_kernel<<<(E1_ * 128) / 256, 256>>>(out_xt, e2n_bias);
}

// round 10
// speedup vs baseline: 1.4111x; 1.0361x over previous
#include <cuda_runtime.h>
#include <stdint.h>
#include <math.h>
#include <float.h>

// ---------------- problem constants ----------------
#define NN_   8192      // nodes
#define E1_   131072    // node-graph edges (= trace rows)
#define E2_   524288    // line-graph edges
#define DIN   256       // layer1 channels (4 heads x 64)
#define DED   128       // layer2 channels (4 heads x 32)
#define EPSV  1e-16f

// ---------------- scratch (static device, no allocs) ----------------
__device__ float g_node   [(size_t)NN_ * DIN];
__device__ float g_xl     [(size_t)NN_ * DIN];
__device__ float g_xr     [(size_t)NN_ * DIN];
__device__ float g_den1   [(size_t)NN_ * 4];
__device__ float g_nodeout[(size_t)NN_ * DIN];  // numerator, then normalized
__device__ float g_xl2    [(size_t)E1_ * DED];
__device__ float g_xr2    [(size_t)E1_ * DED];
__device__ float g_gfeat  [(size_t)NN_ * DED];
__device__ float g_den2   [(size_t)E1_ * 4];

// ---------------- helpers ----------------
__device__ __forceinline__ float lrelu02(float x) { return x > 0.f ? x : 0.2f * x; }
__device__ __forceinline__ uint32_t to_tf32(float v) {
    uint32_t t;
    asm("cvt.rna.tf32.f32 %0, %1;" : "=r"(t) : "f"(v));
    return t;
}
__device__ __forceinline__ void cp16(uint32_t dst, const void* src) {
    asm volatile("cp.async.cg.shared.global [%0], [%1], 16;" :: "r"(dst), "l"(src));
}
__device__ __forceinline__ void red_add_v4(float* addr, float4 v) {
    asm volatile("red.global.add.v4.f32 [%0], {%1,%2,%3,%4};"
                 :: "l"(addr), "f"(v.x), "f"(v.y), "f"(v.z), "f"(v.w) : "memory");
}

// ---------------- tf32 GEMM tiles ----------------
#define TBM 128
#define TBN 128
#define TBK 32
#define STG 8960                 // floats per stage: 128*36 + 32*136
#define AS(S,M,K_) smem[(S)*STG + (M)*36 + (K_)]
#define BS(S,KK,N_) smem[(S)*STG + 4608 + (KK)*136 + (N_)]
#define ET(R,C) smem[(R)*132 + (C)]

struct Frag { float c[4][4][4]; };

__device__ __forceinline__ void load_stage(float* smem, int s,
    const float* __restrict__ A, const float* __restrict__ W,
    int bm, int bn, int k0, int K, int Ncol, int tid)
{
#pragma unroll
    for (int i = 0; i < 4; i++) {
        int idx = tid + i * 256;
        int m = idx >> 3, kc = idx & 7;
        cp16((uint32_t)__cvta_generic_to_shared(&AS(s, m, kc * 4)),
             &A[(size_t)(bm + m) * K + k0 + kc * 4]);
    }
#pragma unroll
    for (int i = 0; i < 4; i++) {
        int idx = tid + i * 256;
        int kk = idx >> 5, nc = idx & 31;
        cp16((uint32_t)__cvta_generic_to_shared(&BS(s, kk, nc * 4)),
             &W[(size_t)(k0 + kk) * Ncol + bn + nc * 4]);
    }
    asm volatile("cp.async.commit_group;");
}

__device__ __forceinline__ void compute_stage(const float* smem, int s, Frag& f,
                                              int wm, int wn, int g, int tg)
{
#pragma unroll
    for (int ks = 0; ks < 4; ks++) {
        const int kb = ks * 8;
        uint32_t afr[4][4], bfr[4][2];
#pragma unroll
        for (int mt = 0; mt < 4; mt++) {
            int mr = wm + mt * 16 + g;
            afr[mt][0] = to_tf32(AS(s, mr,     kb + tg));
            afr[mt][1] = to_tf32(AS(s, mr + 8, kb + tg));
            afr[mt][2] = to_tf32(AS(s, mr,     kb + tg + 4));
            afr[mt][3] = to_tf32(AS(s, mr + 8, kb + tg + 4));
        }
#pragma unroll
        for (int nt = 0; nt < 4; nt++) {
            int nc = wn + nt * 8 + g;
            bfr[nt][0] = to_tf32(BS(s, kb + tg,     nc));
            bfr[nt][1] = to_tf32(BS(s, kb + tg + 4, nc));
        }
#pragma unroll
        for (int mt = 0; mt < 4; mt++)
#pragma unroll
            for (int nt = 0; nt < 4; nt++) {
                asm volatile(
                    "mma.sync.aligned.m16n8k8.row.col.f32.tf32.tf32.f32 "
                    "{%0,%1,%2,%3}, {%4,%5,%6,%7}, {%8,%9}, {%0,%1,%2,%3};"
                    : "+f"(f.c[mt][nt][0]), "+f"(f.c[mt][nt][1]),
                      "+f"(f.c[mt][nt][2]), "+f"(f.c[mt][nt][3])
                    : "r"(afr[mt][0]), "r"(afr[mt][1]),
                      "r"(afr[mt][2]), "r"(afr[mt][3]),
                      "r"(bfr[nt][0]), "r"(bfr[nt][1]));
            }
    }
}

// Pipelined GEMM, optionally dual-output (blockIdx.z selects W/bias/C).
__global__ __launch_bounds__(256) void gemm_pipe(
    const float* __restrict__ A,
    const float* __restrict__ W0, const float* __restrict__ W1,
    const float* __restrict__ b0, const float* __restrict__ b1,
    float* __restrict__ C0, float* __restrict__ C1,
    int M, int Ncol, int K)
{
    extern __shared__ float smem[];
    const int tid  = threadIdx.x;
    const int lane = tid & 31, warp = tid >> 5;
    const int g = lane >> 2, tg = lane & 3;
    const int wm = (warp >> 2) * 64, wn = (warp & 3) * 32;
    const int bm = blockIdx.y * TBM, bn = blockIdx.x * TBN;
    const int z  = blockIdx.z;
    const float* W    = z ? W1 : W0;
    const float* bias = z ? b1 : b0;
    float* C          = z ? C1 : C0;

    Frag f;
#pragma unroll
    for (int mt = 0; mt < 4; mt++)
#pragma unroll
        for (int nt = 0; nt < 4; nt++)
#pragma unroll
            for (int r = 0; r < 4; r++) f.c[mt][nt][r] = 0.f;

    const int KT = K / TBK;
    load_stage(smem, 0, A, W, bm, bn, 0, K, Ncol, tid);
    for (int kt = 0; kt < KT; kt++) {
        int s = kt & 1;
        if (kt + 1 < KT) {
            load_stage(smem, s ^ 1, A, W, bm, bn, (kt + 1) * TBK, K, Ncol, tid);
            asm volatile("cp.async.wait_group 1;");
        } else {
            asm volatile("cp.async.wait_group 0;");
        }
        __syncthreads();
        compute_stage(smem, s, f, wm, wn, g, tg);
        __syncthreads();
    }

#pragma unroll
    for (int mt = 0; mt < 4; mt++) {
        int r0 = bm + wm + mt * 16 + g;
#pragma unroll
        for (int nt = 0; nt < 4; nt++) {
            int col = bn + wn + nt * 8 + 2 * tg;
            float bb0 = bias ? bias[col] : 0.f;
            float bb1 = bias ? bias[col + 1] : 0.f;
            float2 v0 = make_float2(f.c[mt][nt][0] + bb0, f.c[mt][nt][1] + bb1);
            float2 v1 = make_float2(f.c[mt][nt][2] + bb0, f.c[mt][nt][3] + bb1);
            *(float2*)&C[(size_t)r0 * Ncol + col] = v0;
            *(float2*)&C[(size_t)(r0 + 8) * Ncol + col] = v1;
        }
    }
}

// Fused layer-1: e1 = trace @ We in smem, then per-edge logit -> exp ->
// numerator (ex * xl[src]) RED into nodeout + denominator RED into den1.
// grid (2, E1/128): blockIdx.x selects channels [0,128)=heads{0,1} or [128,256)=heads{2,3}.
__global__ __launch_bounds__(256) void gemm_alpha1_agg1_fused(
    const float* __restrict__ A,      // x_trace [E1,128]
    const float* __restrict__ W,      // n2n_We [128,256]
    const int*   __restrict__ adj,    // node_adj [2,E1]
    const float* __restrict__ att)    // [4,64]
{
    extern __shared__ float smem[];
    const int tid  = threadIdx.x;
    const int lane = tid & 31, warp = tid >> 5;
    const int g = lane >> 2, tg = lane & 3;
    const int wm = (warp >> 2) * 64, wn = (warp & 3) * 32;
    const int bm = blockIdx.y * TBM, bn = blockIdx.x * TBN;
    const int K = 128, Ncol = DIN;

    Frag f;
#pragma unroll
    for (int mt = 0; mt < 4; mt++)
#pragma unroll
        for (int nt = 0; nt < 4; nt++)
#pragma unroll
            for (int r = 0; r < 4; r++) f.c[mt][nt][r] = 0.f;

    const int KT = K / TBK;
    load_stage(smem, 0, A, W, bm, bn, 0, K, Ncol, tid);
    for (int kt = 0; kt < KT; kt++) {
        int s = kt & 1;
        if (kt + 1 < KT) {
            load_stage(smem, s ^ 1, A, W, bm, bn, (kt + 1) * TBK, K, Ncol, tid);
            asm volatile("cp.async.wait_group 1;");
        } else {
            asm volatile("cp.async.wait_group 0;");
        }
        __syncthreads();
        compute_stage(smem, s, f, wm, wn, g, tg);
        __syncthreads();
    }

    // stage e1 tile into smem (overwrites stage buffers; synced above)
#pragma unroll
    for (int mt = 0; mt < 4; mt++) {
        int r0 = wm + mt * 16 + g;
#pragma unroll
        for (int nt = 0; nt < 4; nt++) {
            int col = wn + nt * 8 + 2 * tg;
            ET(r0, col)         = f.c[mt][nt][0];
            ET(r0, col + 1)     = f.c[mt][nt][1];
            ET(r0 + 8, col)     = f.c[mt][nt][2];
            ET(r0 + 8, col + 1) = f.c[mt][nt][3];
        }
    }
    __syncthreads();

    // phase 2: per-edge logit -> exp -> numerator + denominator accumulation.
    // After the butterfly, all 16 lanes of each half hold their head's full logit;
    // xlv (this block's numerator channels) is still live in registers.
    const float4 av = *(const float4*)&att[bn + lane * 4];
#pragma unroll 2
    for (int er = warp * 16; er < warp * 16 + 16; er++) {
        int e = bm + er;
        int src = adj[e], dst = adj[E1_ + e];
        float4 xlv = *(const float4*)&g_xl[(size_t)src * DIN + bn + lane * 4];
        float4 xrv = *(const float4*)&g_xr[(size_t)dst * DIN + bn + lane * 4];
        float p;
        p  = lrelu02(xlv.x + xrv.x + ET(er, lane * 4 + 0)) * av.x;
        p += lrelu02(xlv.y + xrv.y + ET(er, lane * 4 + 1)) * av.y;
        p += lrelu02(xlv.z + xrv.z + ET(er, lane * 4 + 2)) * av.z;
        p += lrelu02(xlv.w + xrv.w + ET(er, lane * 4 + 3)) * av.w;
#pragma unroll
        for (int off = 8; off > 0; off >>= 1)
            p += __shfl_xor_sync(0xffffffff, p, off);
        float ex = expf(p);
        red_add_v4(&g_nodeout[(size_t)dst * DIN + bn + lane * 4],
                   make_float4(ex * xlv.x, ex * xlv.y, ex * xlv.z, ex * xlv.w));
        if (lane == 0 || lane == 16) {
            int head = 2 * blockIdx.x + (lane >> 4);
            atomicAdd(&g_den1[(size_t)dst * 4 + head], ex);
        }
    }
}

// ---------------- prep: concat + inits (nodeout zero-seeded: numerator accumulator) ----------------
__global__ void prep_kernel(const float* __restrict__ x_node,
                            const float* __restrict__ x_log)
{
    size_t idx = (size_t)blockIdx.x * blockDim.x + threadIdx.x;
    if (idx >= (size_t)NN_ * DIN) return;
    int i = (int)(idx >> 8), c = (int)(idx & 255);
    g_node[idx] = (c < 128) ? x_node[(size_t)i * 128 + c]
                            : x_log[(size_t)i * 128 + (c - 128)];
    g_nodeout[idx] = 0.f;
    if (idx < NN_ * 4) g_den1[idx] = 0.f;
    if (idx < (size_t)E1_ * 4) g_den2[idx] = 0.f;
}

// normalize nodeout in place AND write xn / xlg output regions
__global__ void normalize_node_kernel(float* __restrict__ out, const float* __restrict__ bias1) {
    size_t idx = (size_t)blockIdx.x * blockDim.x + threadIdx.x;
    if (idx >= (size_t)NN_ * DIN) return;
    int i = (int)(idx >> 8), c = (int)(idx & 255);
    float v = g_nodeout[idx] / (g_den1[i * 4 + (c >> 6)] + EPSV) + bias1[c];
    g_nodeout[idx] = v;
    const size_t XN = (size_t)NN_ * 128;
    const size_t XT = (size_t)E1_ * 128;
    if (c < 128) out[(size_t)i * 128 + c] = v;
    else         out[XN + XT + (size_t)i * 128 + (c - 128)] = v;
}

// ---------------- layer-2 merged attention + aggregate ----------------
__global__ __launch_bounds__(256) void alpha2_agg2_kernel(const int* __restrict__ adj,
                                                          const int* __restrict__ efea,
                                                          const float* __restrict__ att,
                                                          float* __restrict__ out_xt)
{
    int warp = (blockIdx.x * blockDim.x + threadIdx.x) >> 5;
    int lane = threadIdx.x & 31;
    if (warp >= E2_) return;
    int src = adj[warp], dst = adj[E2_ + warp];
    int ef = efea[warp];
    float4 xlv = *(const float4*)&g_xl2  [(size_t)src * DED + lane * 4];
    float4 xrv = *(const float4*)&g_xr2  [(size_t)dst * DED + lane * 4];
    float4 eev = *(const float4*)&g_gfeat[(size_t)ef  * DED + lane * 4];
    float4 av  = *(const float4*)&att[lane * 4];
    float p;
    p  = lrelu02(xlv.x + xrv.x + eev.x) * av.x;
    p += lrelu02(xlv.y + xrv.y + eev.y) * av.y;
    p += lrelu02(xlv.z + xrv.z + eev.z) * av.z;
    p += lrelu02(xlv.w + xrv.w + eev.w) * av.w;
#pragma unroll
    for (int off = 4; off > 0; off >>= 1)
        p += __shfl_xor_sync(0xffffffff, p, off);
    float ex = expf(p);
    red_add_v4(&out_xt[(size_t)dst * DED + lane * 4],
               make_float4(ex * xlv.x, ex * xlv.y, ex * xlv.z, ex * xlv.w));
    if ((lane & 7) == 0)
        atomicAdd(&g_den2[(size_t)dst * 4 + (lane >> 3)], ex);
}

// seed xt output region with zeros (numerator accumulator)
__global__ void seed_xt_kernel(float* __restrict__ out_xt) {
    size_t idx = (size_t)blockIdx.x * blockDim.x + threadIdx.x;
    if (idx >= (size_t)E1_ * 128) return;
    out_xt[idx] = 0.f;
}

// normalize xt in place: divide by den, add bias
__global__ void normalize_xt_kernel(float* __restrict__ out_xt, const float* __restrict__ bias2) {
    size_t idx = (size_t)blockIdx.x * blockDim.x + threadIdx.x;
    if (idx >= (size_t)E1_ * 128) return;
    int e = (int)(idx >> 7), c = (int)(idx & 127);
    out_xt[idx] = out_xt[idx] / (g_den2[(size_t)e * 4 + (c >> 5)] + EPSV) + bias2[c];
}

// ---------------- launch ----------------
extern "C" void kernel_launch(void* const* d_in, const int* in_sizes, int n_in,
                              void* d_out, int out_size)
{
    const float* x_node   = (const float*)d_in[0];
    const float* x_trace  = (const float*)d_in[1];
    const float* x_log    = (const float*)d_in[2];
    const int*   node_adj = (const int*)d_in[3];
    const int*   edge_adj = (const int*)d_in[4];
    const int*   edge_efea= (const int*)d_in[5];
    const float* n2n_Wl   = (const float*)d_in[6];
    const float* n2n_bl   = (const float*)d_in[7];
    const float* n2n_Wr   = (const float*)d_in[8];
    const float* n2n_br   = (const float*)d_in[9];
    const float* n2n_We   = (const float*)d_in[10];
    const float* n2n_att  = (const float*)d_in[11];
    const float* n2n_bias = (const float*)d_in[12];
    const float* e2n_Wl   = (const float*)d_in[13];
    const float* e2n_bl   = (const float*)d_in[14];
    const float* e2n_Wr   = (const float*)d_in[15];
    const float* e2n_br   = (const float*)d_in[16];
    const float* e2n_We   = (const float*)d_in[17];
    const float* e2n_att  = (const float*)d_in[18];
    const float* e2n_bias = (const float*)d_in[19];
    float* out = (float*)d_out;
    float* out_xt = out + (size_t)NN_ * 128;

    float* p_node;    cudaGetSymbolAddress((void**)&p_node,    g_node);
    float* p_xl;      cudaGetSymbolAddress((void**)&p_xl,      g_xl);
    float* p_xr;      cudaGetSymbolAddress((void**)&p_xr,      g_xr);
    float* p_nodeout; cudaGetSymbolAddress((void**)&p_nodeout, g_nodeout);
    float* p_xl2;     cudaGetSymbolAddress((void**)&p_xl2,     g_xl2);
    float* p_xr2;     cudaGetSymbolAddress((void**)&p_xr2,     g_xr2);
    float* p_g;       cudaGetSymbolAddress((void**)&p_g,       g_gfeat);

    const int SMEM_PIPE = 2 * STG * 4;          // 71680 (covers ET 128*132*4=67584 too)
    static cudaStream_t s1 = nullptr;
    static cudaEvent_t evA = nullptr, evB = nullptr;
    if (!s1) {
        cudaFuncSetAttribute(gemm_pipe, cudaFuncAttributeMaxDynamicSharedMemorySize, SMEM_PIPE);
        cudaFuncSetAttribute(gemm_alpha1_agg1_fused, cudaFuncAttributeMaxDynamicSharedMemorySize, SMEM_PIPE);
        cudaStreamCreateWithFlags(&s1, cudaStreamNonBlocking);
        cudaEventCreateWithFlags(&evA, cudaEventDisableTiming);
        cudaEventCreateWithFlags(&evB, cudaEventDisableTiming);
    }

    // fork side stream: zero-seed xt numerator + xl2/xr2 GEMM (depend only on inputs)
    cudaEventRecord(evA, 0);
    cudaStreamWaitEvent(s1, evA, 0);
    seed_xt_kernel<<<(E1_ * 128) / 256, 256, 0, s1>>>(out_xt);
    {
        dim3 gdim(DED / TBN, E1_ / TBM, 2);
        gemm_pipe<<<gdim, 256, SMEM_PIPE, s1>>>(x_trace, e2n_Wl, e2n_Wr, e2n_bl, e2n_br,
                                                p_xl2, p_xr2, E1_, DED, DED);
    }
    cudaEventRecord(evB, s1);

    // main stream: prep -> xl/xr -> fused alpha1+agg1 -> normalize_node
    prep_kernel<<<(NN_ * DIN) / 256, 256>>>(x_node, x_log);
    {
        dim3 gdim(DIN / TBN, NN_ / TBM, 2);
        gemm_pipe<<<gdim, 256, SMEM_PIPE>>>(p_node, n2n_Wl, n2n_Wr, n2n_bl, n2n_br,
                                            p_xl, p_xr, NN_, DIN, DIN);
    }
    {
        dim3 gdim(DIN / TBN, E1_ / TBM);
        gemm_alpha1_agg1_fused<<<gdim, 256, SMEM_PIPE>>>(x_trace, n2n_We, node_adj, n2n_att);
    }
    normalize_node_kernel<<<(NN_ * DIN) / 256, 256>>>(out, n2n_bias);

    // main: gfeat = node_out @ We2
    {
        dim3 gdim(DED / TBN, NN_ / TBM, 1);
        gemm_pipe<<<gdim, 256, SMEM_PIPE>>>(p_nodeout, e2n_We, e2n_We, nullptr, nullptr,
                                            p_g, p_g, NN_, DED, DIN);
    }

    // join: merged layer-2 needs xl2/xr2 + seeded xt from side stream
    cudaStreamWaitEvent(0, evB, 0);

    alpha2_agg2_kernel<<<E2_ / 8, 256>>>(edge_adj, edge_efea, e2n_att, out_xt);
    normalize_xt_kernel<<<(E1_ * 128) / 256, 256>>>(out_xt, e2n_bias);
}

// round 11
// speedup vs baseline: 1.4529x; 1.0296x over previous
#include <cuda_runtime.h>
#include <stdint.h>
#include <math.h>
#include <float.h>

// ---------------- problem constants ----------------
#define NN_   8192      // nodes
#define E1_   131072    // node-graph edges (= trace rows)
#define E2_   524288    // line-graph edges
#define DIN   256       // layer1 channels (4 heads x 64)
#define DED   128       // layer2 channels (4 heads x 32)
#define EPSV  1e-16f

// ---------------- scratch (static device, no allocs) ----------------
__device__ float g_node   [(size_t)NN_ * DIN];
__device__ float g_xl     [(size_t)NN_ * DIN];
__device__ float g_xr     [(size_t)NN_ * DIN];
__device__ float g_den1   [(size_t)NN_ * 4];
__device__ float g_nodeout[(size_t)NN_ * DIN];  // numerator, then normalized
__device__ float g_xl2    [(size_t)E1_ * DED];
__device__ float g_xr2    [(size_t)E1_ * DED];
__device__ float g_gfeat  [(size_t)NN_ * DED];
__device__ float g_den2   [(size_t)E1_ * 4];

// ---------------- helpers ----------------
__device__ __forceinline__ float lrelu02(float x) { return x > 0.f ? x : 0.2f * x; }
__device__ __forceinline__ uint32_t to_tf32(float v) {
    uint32_t t;
    asm("cvt.rna.tf32.f32 %0, %1;" : "=r"(t) : "f"(v));
    return t;
}
__device__ __forceinline__ void cp16(uint32_t dst, const void* src) {
    asm volatile("cp.async.cg.shared.global [%0], [%1], 16;" :: "r"(dst), "l"(src));
}
__device__ __forceinline__ void red_add_v4(float* addr, float4 v) {
    asm volatile("red.global.add.v4.f32 [%0], {%1,%2,%3,%4};"
                 :: "l"(addr), "f"(v.x), "f"(v.y), "f"(v.z), "f"(v.w) : "memory");
}

// ---------------- tf32 GEMM tiles ----------------
#define TBM 128
#define TBN 128
#define TBK 32
#define STG 8960                 // floats per stage: 128*36 + 32*136
#define AS(S,M,K_) smem[(S)*STG + (M)*36 + (K_)]
#define BS(S,KK,N_) smem[(S)*STG + 4608 + (KK)*136 + (N_)]
#define ET(R,C) smem[(R)*132 + (C)]

struct Frag { float c[4][4][4]; };

__device__ __forceinline__ void load_stage(float* smem, int s,
    const float* __restrict__ A, const float* __restrict__ W,
    int bm, int bn, int k0, int K, int Ncol, int tid)
{
#pragma unroll
    for (int i = 0; i < 4; i++) {
        int idx = tid + i * 256;
        int m = idx >> 3, kc = idx & 7;
        cp16((uint32_t)__cvta_generic_to_shared(&AS(s, m, kc * 4)),
             &A[(size_t)(bm + m) * K + k0 + kc * 4]);
    }
#pragma unroll
    for (int i = 0; i < 4; i++) {
        int idx = tid + i * 256;
        int kk = idx >> 5, nc = idx & 31;
        cp16((uint32_t)__cvta_generic_to_shared(&BS(s, kk, nc * 4)),
             &W[(size_t)(k0 + kk) * Ncol + bn + nc * 4]);
    }
    asm volatile("cp.async.commit_group;");
}

__device__ __forceinline__ void compute_stage(const float* smem, int s, Frag& f,
                                              int wm, int wn, int g, int tg)
{
#pragma unroll
    for (int ks = 0; ks < 4; ks++) {
        const int kb = ks * 8;
        uint32_t afr[4][4], bfr[4][2];
#pragma unroll
        for (int mt = 0; mt < 4; mt++) {
            int mr = wm + mt * 16 + g;
            afr[mt][0] = to_tf32(AS(s, mr,     kb + tg));
            afr[mt][1] = to_tf32(AS(s, mr + 8, kb + tg));
            afr[mt][2] = to_tf32(AS(s, mr,     kb + tg + 4));
            afr[mt][3] = to_tf32(AS(s, mr + 8, kb + tg + 4));
        }
#pragma unroll
        for (int nt = 0; nt < 4; nt++) {
            int nc = wn + nt * 8 + g;
            bfr[nt][0] = to_tf32(BS(s, kb + tg,     nc));
            bfr[nt][1] = to_tf32(BS(s, kb + tg + 4, nc));
        }
#pragma unroll
        for (int mt = 0; mt < 4; mt++)
#pragma unroll
            for (int nt = 0; nt < 4; nt++) {
                asm volatile(
                    "mma.sync.aligned.m16n8k8.row.col.f32.tf32.tf32.f32 "
                    "{%0,%1,%2,%3}, {%4,%5,%6,%7}, {%8,%9}, {%0,%1,%2,%3};"
                    : "+f"(f.c[mt][nt][0]), "+f"(f.c[mt][nt][1]),
                      "+f"(f.c[mt][nt][2]), "+f"(f.c[mt][nt][3])
                    : "r"(afr[mt][0]), "r"(afr[mt][1]),
                      "r"(afr[mt][2]), "r"(afr[mt][3]),
                      "r"(bfr[nt][0]), "r"(bfr[nt][1]));
            }
    }
}

// Pipelined GEMM, optionally dual-output (blockIdx.z selects W/bias/C).
__global__ __launch_bounds__(256) void gemm_pipe(
    const float* __restrict__ A,
    const float* __restrict__ W0, const float* __restrict__ W1,
    const float* __restrict__ b0, const float* __restrict__ b1,
    float* __restrict__ C0, float* __restrict__ C1,
    int M, int Ncol, int K)
{
    extern __shared__ float smem[];
    const int tid  = threadIdx.x;
    const int lane = tid & 31, warp = tid >> 5;
    const int g = lane >> 2, tg = lane & 3;
    const int wm = (warp >> 2) * 64, wn = (warp & 3) * 32;
    const int bm = blockIdx.y * TBM, bn = blockIdx.x * TBN;
    const int z  = blockIdx.z;
    const float* W    = z ? W1 : W0;
    const float* bias = z ? b1 : b0;
    float* C          = z ? C1 : C0;

    Frag f;
#pragma unroll
    for (int mt = 0; mt < 4; mt++)
#pragma unroll
        for (int nt = 0; nt < 4; nt++)
#pragma unroll
            for (int r = 0; r < 4; r++) f.c[mt][nt][r] = 0.f;

    const int KT = K / TBK;
    load_stage(smem, 0, A, W, bm, bn, 0, K, Ncol, tid);
    for (int kt = 0; kt < KT; kt++) {
        int s = kt & 1;
        if (kt + 1 < KT) {
            load_stage(smem, s ^ 1, A, W, bm, bn, (kt + 1) * TBK, K, Ncol, tid);
            asm volatile("cp.async.wait_group 1;");
        } else {
            asm volatile("cp.async.wait_group 0;");
        }
        __syncthreads();
        compute_stage(smem, s, f, wm, wn, g, tg);
        __syncthreads();
    }

#pragma unroll
    for (int mt = 0; mt < 4; mt++) {
        int r0 = bm + wm + mt * 16 + g;
#pragma unroll
        for (int nt = 0; nt < 4; nt++) {
            int col = bn + wn + nt * 8 + 2 * tg;
            float bb0 = bias ? bias[col] : 0.f;
            float bb1 = bias ? bias[col + 1] : 0.f;
            float2 v0 = make_float2(f.c[mt][nt][0] + bb0, f.c[mt][nt][1] + bb1);
            float2 v1 = make_float2(f.c[mt][nt][2] + bb0, f.c[mt][nt][3] + bb1);
            *(float2*)&C[(size_t)r0 * Ncol + col] = v0;
            *(float2*)&C[(size_t)(r0 + 8) * Ncol + col] = v1;
        }
    }
}

// Fused layer-1: e1 = trace @ We in smem, then per-edge logit -> exp ->
// numerator (ex * xl[src]) RED into nodeout + denominator RED into den1.
// grid (2, E1/128): blockIdx.x selects channels [0,128)=heads{0,1} or [128,256)=heads{2,3}.
__global__ __launch_bounds__(256) void gemm_alpha1_agg1_fused(
    const float* __restrict__ A,      // x_trace [E1,128]
    const float* __restrict__ W,      // n2n_We [128,256]
    const int*   __restrict__ adj,    // node_adj [2,E1]
    const float* __restrict__ att)    // [4,64]
{
    extern __shared__ float smem[];
    const int tid  = threadIdx.x;
    const int lane = tid & 31, warp = tid >> 5;
    const int g = lane >> 2, tg = lane & 3;
    const int wm = (warp >> 2) * 64, wn = (warp & 3) * 32;
    const int bm = blockIdx.y * TBM, bn = blockIdx.x * TBN;
    const int K = 128, Ncol = DIN;

    Frag f;
#pragma unroll
    for (int mt = 0; mt < 4; mt++)
#pragma unroll
        for (int nt = 0; nt < 4; nt++)
#pragma unroll
            for (int r = 0; r < 4; r++) f.c[mt][nt][r] = 0.f;

    const int KT = K / TBK;
    load_stage(smem, 0, A, W, bm, bn, 0, K, Ncol, tid);
    for (int kt = 0; kt < KT; kt++) {
        int s = kt & 1;
        if (kt + 1 < KT) {
            load_stage(smem, s ^ 1, A, W, bm, bn, (kt + 1) * TBK, K, Ncol, tid);
            asm volatile("cp.async.wait_group 1;");
        } else {
            asm volatile("cp.async.wait_group 0;");
        }
        __syncthreads();
        compute_stage(smem, s, f, wm, wn, g, tg);
        __syncthreads();
    }

    // stage e1 tile into smem (overwrites stage buffers; synced above)
#pragma unroll
    for (int mt = 0; mt < 4; mt++) {
        int r0 = wm + mt * 16 + g;
#pragma unroll
        for (int nt = 0; nt < 4; nt++) {
            int col = wn + nt * 8 + 2 * tg;
            ET(r0, col)         = f.c[mt][nt][0];
            ET(r0, col + 1)     = f.c[mt][nt][1];
            ET(r0 + 8, col)     = f.c[mt][nt][2];
            ET(r0 + 8, col + 1) = f.c[mt][nt][3];
        }
    }
    __syncthreads();

    // phase 2: per-edge logit -> exp -> numerator + denominator accumulation.
    const float4 av = *(const float4*)&att[bn + lane * 4];
#pragma unroll 4
    for (int er = warp * 16; er < warp * 16 + 16; er++) {
        int e = bm + er;
        int src = adj[e], dst = adj[E1_ + e];
        float4 xlv = *(const float4*)&g_xl[(size_t)src * DIN + bn + lane * 4];
        float4 xrv = *(const float4*)&g_xr[(size_t)dst * DIN + bn + lane * 4];
        float p;
        p  = lrelu02(xlv.x + xrv.x + ET(er, lane * 4 + 0)) * av.x;
        p += lrelu02(xlv.y + xrv.y + ET(er, lane * 4 + 1)) * av.y;
        p += lrelu02(xlv.z + xrv.z + ET(er, lane * 4 + 2)) * av.z;
        p += lrelu02(xlv.w + xrv.w + ET(er, lane * 4 + 3)) * av.w;
#pragma unroll
        for (int off = 8; off > 0; off >>= 1)
            p += __shfl_xor_sync(0xffffffff, p, off);
        float ex = expf(p);
        red_add_v4(&g_nodeout[(size_t)dst * DIN + bn + lane * 4],
                   make_float4(ex * xlv.x, ex * xlv.y, ex * xlv.z, ex * xlv.w));
        if (lane == 0 || lane == 16) {
            int head = 2 * blockIdx.x + (lane >> 4);
            atomicAdd(&g_den1[(size_t)dst * 4 + head], ex);
        }
    }
}

// ---------------- prep: concat + inits (nodeout zero-seeded: numerator accumulator) ----------------
__global__ void prep_kernel(const float* __restrict__ x_node,
                            const float* __restrict__ x_log)
{
    size_t idx = (size_t)blockIdx.x * blockDim.x + threadIdx.x;
    if (idx >= (size_t)NN_ * DIN) return;
    int i = (int)(idx >> 8), c = (int)(idx & 255);
    g_node[idx] = (c < 128) ? x_node[(size_t)i * 128 + c]
                            : x_log[(size_t)i * 128 + (c - 128)];
    g_nodeout[idx] = 0.f;
    if (idx < NN_ * 4) g_den1[idx] = 0.f;
    if (idx < (size_t)E1_ * 4) g_den2[idx] = 0.f;
}

// normalize nodeout in place AND write xn / xlg output regions
__global__ void normalize_node_kernel(float* __restrict__ out, const float* __restrict__ bias1) {
    size_t idx = (size_t)blockIdx.x * blockDim.x + threadIdx.x;
    if (idx >= (size_t)NN_ * DIN) return;
    int i = (int)(idx >> 8), c = (int)(idx & 255);
    float v = g_nodeout[idx] / (g_den1[i * 4 + (c >> 6)] + EPSV) + bias1[c];
    g_nodeout[idx] = v;
    const size_t XN = (size_t)NN_ * 128;
    const size_t XT = (size_t)E1_ * 128;
    if (c < 128) out[(size_t)i * 128 + c] = v;
    else         out[XN + XT + (size_t)i * 128 + (c - 128)] = v;
}

// ---------------- layer-2 merged attention + aggregate, 2 edges/warp ----------------
// All 6 gathers issued before any compute (MLP=6), then per-edge exp + RED.
__global__ __launch_bounds__(256) void alpha2_agg2_kernel(const int* __restrict__ adj,
                                                          const int* __restrict__ efea,
                                                          const float* __restrict__ att,
                                                          float* __restrict__ out_xt)
{
    int warp = (blockIdx.x * blockDim.x + threadIdx.x) >> 5;
    int lane = threadIdx.x & 31;
    int e0 = warp * 2;
    if (e0 >= E2_) return;
    float4 av = *(const float4*)&att[lane * 4];

    int src0 = adj[e0],     dst0 = adj[(size_t)E2_ + e0];
    int src1 = adj[e0 + 1], dst1 = adj[(size_t)E2_ + e0 + 1];
    int ef0  = efea[e0],    ef1  = efea[e0 + 1];

    // issue all 6 row gathers up front
    float4 xl0 = *(const float4*)&g_xl2  [(size_t)src0 * DED + lane * 4];
    float4 xr0 = *(const float4*)&g_xr2  [(size_t)dst0 * DED + lane * 4];
    float4 ee0 = *(const float4*)&g_gfeat[(size_t)ef0  * DED + lane * 4];
    float4 xl1 = *(const float4*)&g_xl2  [(size_t)src1 * DED + lane * 4];
    float4 xr1 = *(const float4*)&g_xr2  [(size_t)dst1 * DED + lane * 4];
    float4 ee1 = *(const float4*)&g_gfeat[(size_t)ef1  * DED + lane * 4];

    float p0, p1;
    p0  = lrelu02(xl0.x + xr0.x + ee0.x) * av.x;
    p0 += lrelu02(xl0.y + xr0.y + ee0.y) * av.y;
    p0 += lrelu02(xl0.z + xr0.z + ee0.z) * av.z;
    p0 += lrelu02(xl0.w + xr0.w + ee0.w) * av.w;
    p1  = lrelu02(xl1.x + xr1.x + ee1.x) * av.x;
    p1 += lrelu02(xl1.y + xr1.y + ee1.y) * av.y;
    p1 += lrelu02(xl1.z + xr1.z + ee1.z) * av.z;
    p1 += lrelu02(xl1.w + xr1.w + ee1.w) * av.w;
#pragma unroll
    for (int off = 4; off > 0; off >>= 1) {
        p0 += __shfl_xor_sync(0xffffffff, p0, off);
        p1 += __shfl_xor_sync(0xffffffff, p1, off);
    }
    float ex0 = expf(p0);
    float ex1 = expf(p1);
    red_add_v4(&out_xt[(size_t)dst0 * DED + lane * 4],
               make_float4(ex0 * xl0.x, ex0 * xl0.y, ex0 * xl0.z, ex0 * xl0.w));
    red_add_v4(&out_xt[(size_t)dst1 * DED + lane * 4],
               make_float4(ex1 * xl1.x, ex1 * xl1.y, ex1 * xl1.z, ex1 * xl1.w));
    if ((lane & 7) == 0) {
        atomicAdd(&g_den2[(size_t)dst0 * 4 + (lane >> 3)], ex0);
        atomicAdd(&g_den2[(size_t)dst1 * 4 + (lane >> 3)], ex1);
    }
}

// seed xt output region with zeros (numerator accumulator)
__global__ void seed_xt_kernel(float* __restrict__ out_xt) {
    size_t idx = (size_t)blockIdx.x * blockDim.x + threadIdx.x;
    if (idx >= (size_t)E1_ * 128) return;
    out_xt[idx] = 0.f;
}

// normalize xt in place: divide by den, add bias
__global__ void normalize_xt_kernel(float* __restrict__ out_xt, const float* __restrict__ bias2) {
    size_t idx = (size_t)blockIdx.x * blockDim.x + threadIdx.x;
    if (idx >= (size_t)E1_ * 128) return;
    int e = (int)(idx >> 7), c = (int)(idx & 127);
    out_xt[idx] = out_xt[idx] / (g_den2[(size_t)e * 4 + (c >> 5)] + EPSV) + bias2[c];
}

// ---------------- launch ----------------
extern "C" void kernel_launch(void* const* d_in, const int* in_sizes, int n_in,
                              void* d_out, int out_size)
{
    const float* x_node   = (const float*)d_in[0];
    const float* x_trace  = (const float*)d_in[1];
    const float* x_log    = (const float*)d_in[2];
    const int*   node_adj = (const int*)d_in[3];
    const int*   edge_adj = (const int*)d_in[4];
    const int*   edge_efea= (const int*)d_in[5];
    const float* n2n_Wl   = (const float*)d_in[6];
    const float* n2n_bl   = (const float*)d_in[7];
    const float* n2n_Wr   = (const float*)d_in[8];
    const float* n2n_br   = (const float*)d_in[9];
    const float* n2n_We   = (const float*)d_in[10];
    const float* n2n_att  = (const float*)d_in[11];
    const float* n2n_bias = (const float*)d_in[12];
    const float* e2n_Wl   = (const float*)d_in[13];
    const float* e2n_bl   = (const float*)d_in[14];
    const float* e2n_Wr   = (const float*)d_in[15];
    const float* e2n_br   = (const float*)d_in[16];
    const float* e2n_We   = (const float*)d_in[17];
    const float* e2n_att  = (const float*)d_in[18];
    const float* e2n_bias = (const float*)d_in[19];
    float* out = (float*)d_out;
    float* out_xt = out + (size_t)NN_ * 128;

    float* p_node;    cudaGetSymbolAddress((void**)&p_node,    g_node);
    float* p_xl;      cudaGetSymbolAddress((void**)&p_xl,      g_xl);
    float* p_xr;      cudaGetSymbolAddress((void**)&p_xr,      g_xr);
    float* p_nodeout; cudaGetSymbolAddress((void**)&p_nodeout, g_nodeout);
    float* p_xl2;     cudaGetSymbolAddress((void**)&p_xl2,     g_xl2);
    float* p_xr2;     cudaGetSymbolAddress((void**)&p_xr2,     g_xr2);
    float* p_g;       cudaGetSymbolAddress((void**)&p_g,       g_gfeat);

    const int SMEM_PIPE = 2 * STG * 4;          // 71680 (covers ET 128*132*4=67584 too)
    static cudaStream_t s1 = nullptr;
    static cudaEvent_t evA = nullptr, evB = nullptr;
    if (!s1) {
        cudaFuncSetAttribute(gemm_pipe, cudaFuncAttributeMaxDynamicSharedMemorySize, SMEM_PIPE);
        cudaFuncSetAttribute(gemm_alpha1_agg1_fused, cudaFuncAttributeMaxDynamicSharedMemorySize, SMEM_PIPE);
        cudaStreamCreateWithFlags(&s1, cudaStreamNonBlocking);
        cudaEventCreateWithFlags(&evA, cudaEventDisableTiming);
        cudaEventCreateWithFlags(&evB, cudaEventDisableTiming);
    }

    // fork side stream: zero-seed xt numerator + xl2/xr2 GEMM (depend only on inputs)
    cudaEventRecord(evA, 0);
    cudaStreamWaitEvent(s1, evA, 0);
    seed_xt_kernel<<<(E1_ * 128) / 256, 256, 0, s1>>>(out_xt);
    {
        dim3 gdim(DED / TBN, E1_ / TBM, 2);
        gemm_pipe<<<gdim, 256, SMEM_PIPE, s1>>>(x_trace, e2n_Wl, e2n_Wr, e2n_bl, e2n_br,
                                                p_xl2, p_xr2, E1_, DED, DED);
    }
    cudaEventRecord(evB, s1);

    // main stream: prep -> xl/xr -> fused alpha1+agg1 -> normalize_node
    prep_kernel<<<(NN_ * DIN) / 256, 256>>>(x_node, x_log);
    {
        dim3 gdim(DIN / TBN, NN_ / TBM, 2);
        gemm_pipe<<<gdim, 256, SMEM_PIPE>>>(p_node, n2n_Wl, n2n_Wr, n2n_bl, n2n_br,
                                            p_xl, p_xr, NN_, DIN, DIN);
    }
    {
        dim3 gdim(DIN / TBN, E1_ / TBM);
        gemm_alpha1_agg1_fused<<<gdim, 256, SMEM_PIPE>>>(x_trace, n2n_We, node_adj, n2n_att);
    }
    normalize_node_kernel<<<(NN_ * DIN) / 256, 256>>>(out, n2n_bias);

    // main: gfeat = node_out @ We2
    {
        dim3 gdim(DED / TBN, NN_ / TBM, 1);
        gemm_pipe<<<gdim, 256, SMEM_PIPE>>>(p_nodeout, e2n_We, e2n_We, nullptr, nullptr,
                                            p_g, p_g, NN_, DED, DIN);
    }

    // join: merged layer-2 needs xl2/xr2 + seeded xt from side stream
    cudaStreamWaitEvent(0, evB, 0);

    alpha2_agg2_kernel<<<E2_ / 16, 256>>>(edge_adj, edge_efea, e2n_att, out_xt);
    normalize_xt_kernel<<<(E1_ * 128) / 256, 256>>>(out_xt, e2n_bias);
}

// round 12
// speedup vs baseline: 1.4724x; 1.0135x over previous
#include <cuda_runtime.h>
#include <stdint.h>
#include <math.h>
#include <float.h>

// ---------------- problem constants ----------------
#define NN_   8192      // nodes
#define E1_   131072    // node-graph edges (= trace rows)
#define E2_   524288    // line-graph edges
#define DIN   256       // layer1 channels (4 heads x 64)
#define DED   128       // layer2 channels (4 heads x 32)
#define EPSV  1e-16f

// ---------------- scratch (static device, no allocs) ----------------
__device__ float g_node   [(size_t)NN_ * DIN];
__device__ float g_xl     [(size_t)NN_ * DIN];
__device__ float g_xr     [(size_t)NN_ * DIN];
__device__ float g_den1   [(size_t)NN_ * 4];
__device__ float g_nodeout[(size_t)NN_ * DIN];  // numerator, then normalized
__device__ float g_xl2    [(size_t)E1_ * DED];
__device__ float g_xr2    [(size_t)E1_ * DED];
__device__ float g_gfeat  [(size_t)NN_ * DED];
__device__ float g_den2   [(size_t)E1_ * 4];

// ---------------- helpers ----------------
__device__ __forceinline__ float lrelu02(float x) { return x > 0.f ? x : 0.2f * x; }
__device__ __forceinline__ uint32_t to_tf32(float v) {
    uint32_t t;
    asm("cvt.rna.tf32.f32 %0, %1;" : "=r"(t) : "f"(v));
    return t;
}
__device__ __forceinline__ void cp16(uint32_t dst, const void* src) {
    asm volatile("cp.async.cg.shared.global [%0], [%1], 16;" :: "r"(dst), "l"(src));
}
__device__ __forceinline__ void red_add_v4(float* addr, float4 v) {
    asm volatile("red.global.add.v4.f32 [%0], {%1,%2,%3,%4};"
                 :: "l"(addr), "f"(v.x), "f"(v.y), "f"(v.z), "f"(v.w) : "memory");
}

// ---------------- tf32 GEMM tiles ----------------
#define TBM 128
#define TBN 128
#define TBK 32
#define STG 8960                 // floats per stage: 128*36 + 32*136
#define AS(S,M,K_) smem[(S)*STG + (M)*36 + (K_)]
#define BS(S,KK,N_) smem[(S)*STG + 4608 + (KK)*136 + (N_)]
#define ET(R,C) smem[(R)*132 + (C)]

struct Frag { float c[4][4][4]; };

__device__ __forceinline__ void load_stage(float* smem, int s,
    const float* __restrict__ A, const float* __restrict__ W,
    int bm, int bn, int k0, int K, int Ncol, int tid)
{
#pragma unroll
    for (int i = 0; i < 4; i++) {
        int idx = tid + i * 256;
        int m = idx >> 3, kc = idx & 7;
        cp16((uint32_t)__cvta_generic_to_shared(&AS(s, m, kc * 4)),
             &A[(size_t)(bm + m) * K + k0 + kc * 4]);
    }
#pragma unroll
    for (int i = 0; i < 4; i++) {
        int idx = tid + i * 256;
        int kk = idx >> 5, nc = idx & 31;
        cp16((uint32_t)__cvta_generic_to_shared(&BS(s, kk, nc * 4)),
             &W[(size_t)(k0 + kk) * Ncol + bn + nc * 4]);
    }
    asm volatile("cp.async.commit_group;");
}

__device__ __forceinline__ void compute_stage(const float* smem, int s, Frag& f,
                                              int wm, int wn, int g, int tg)
{
#pragma unroll
    for (int ks = 0; ks < 4; ks++) {
        const int kb = ks * 8;
        uint32_t afr[4][4], bfr[4][2];
#pragma unroll
        for (int mt = 0; mt < 4; mt++) {
            int mr = wm + mt * 16 + g;
            afr[mt][0] = to_tf32(AS(s, mr,     kb + tg));
            afr[mt][1] = to_tf32(AS(s, mr + 8, kb + tg));
            afr[mt][2] = to_tf32(AS(s, mr,     kb + tg + 4));
            afr[mt][3] = to_tf32(AS(s, mr + 8, kb + tg + 4));
        }
#pragma unroll
        for (int nt = 0; nt < 4; nt++) {
            int nc = wn + nt * 8 + g;
            bfr[nt][0] = to_tf32(BS(s, kb + tg,     nc));
            bfr[nt][1] = to_tf32(BS(s, kb + tg + 4, nc));
        }
#pragma unroll
        for (int mt = 0; mt < 4; mt++)
#pragma unroll
            for (int nt = 0; nt < 4; nt++) {
                asm volatile(
                    "mma.sync.aligned.m16n8k8.row.col.f32.tf32.tf32.f32 "
                    "{%0,%1,%2,%3}, {%4,%5,%6,%7}, {%8,%9}, {%0,%1,%2,%3};"
                    : "+f"(f.c[mt][nt][0]), "+f"(f.c[mt][nt][1]),
                      "+f"(f.c[mt][nt][2]), "+f"(f.c[mt][nt][3])
                    : "r"(afr[mt][0]), "r"(afr[mt][1]),
                      "r"(afr[mt][2]), "r"(afr[mt][3]),
                      "r"(bfr[nt][0]), "r"(bfr[nt][1]));
            }
    }
}

// Pipelined GEMM, optionally dual-output (blockIdx.z selects W/bias/C).
__global__ __launch_bounds__(256) void gemm_pipe(
    const float* __restrict__ A,
    const float* __restrict__ W0, const float* __restrict__ W1,
    const float* __restrict__ b0, const float* __restrict__ b1,
    float* __restrict__ C0, float* __restrict__ C1,
    int M, int Ncol, int K)
{
    extern __shared__ float smem[];
    const int tid  = threadIdx.x;
    const int lane = tid & 31, warp = tid >> 5;
    const int g = lane >> 2, tg = lane & 3;
    const int wm = (warp >> 2) * 64, wn = (warp & 3) * 32;
    const int bm = blockIdx.y * TBM, bn = blockIdx.x * TBN;
    const int z  = blockIdx.z;
    const float* W    = z ? W1 : W0;
    const float* bias = z ? b1 : b0;
    float* C          = z ? C1 : C0;

    Frag f;
#pragma unroll
    for (int mt = 0; mt < 4; mt++)
#pragma unroll
        for (int nt = 0; nt < 4; nt++)
#pragma unroll
            for (int r = 0; r < 4; r++) f.c[mt][nt][r] = 0.f;

    const int KT = K / TBK;
    load_stage(smem, 0, A, W, bm, bn, 0, K, Ncol, tid);
    for (int kt = 0; kt < KT; kt++) {
        int s = kt & 1;
        if (kt + 1 < KT) {
            load_stage(smem, s ^ 1, A, W, bm, bn, (kt + 1) * TBK, K, Ncol, tid);
            asm volatile("cp.async.wait_group 1;");
        } else {
            asm volatile("cp.async.wait_group 0;");
        }
        __syncthreads();
        compute_stage(smem, s, f, wm, wn, g, tg);
        __syncthreads();
    }

#pragma unroll
    for (int mt = 0; mt < 4; mt++) {
        int r0 = bm + wm + mt * 16 + g;
#pragma unroll
        for (int nt = 0; nt < 4; nt++) {
            int col = bn + wn + nt * 8 + 2 * tg;
            float bb0 = bias ? bias[col] : 0.f;
            float bb1 = bias ? bias[col + 1] : 0.f;
            float2 v0 = make_float2(f.c[mt][nt][0] + bb0, f.c[mt][nt][1] + bb1);
            float2 v1 = make_float2(f.c[mt][nt][2] + bb0, f.c[mt][nt][3] + bb1);
            *(float2*)&C[(size_t)r0 * Ncol + col] = v0;
            *(float2*)&C[(size_t)(r0 + 8) * Ncol + col] = v1;
        }
    }
}

// Fused layer-1: e1 = trace @ We in smem, then per-edge logit -> exp ->
// numerator (ex * xl[src]) RED into nodeout + denominator RED into den1.
// grid (2, E1/128): blockIdx.x selects channels [0,128)=heads{0,1} or [128,256)=heads{2,3}.
// Phase-2 processes 2 edges at a time with front-batched gathers (MLP=4).
__global__ __launch_bounds__(256) void gemm_alpha1_agg1_fused(
    const float* __restrict__ A,      // x_trace [E1,128]
    const float* __restrict__ W,      // n2n_We [128,256]
    const int*   __restrict__ adj,    // node_adj [2,E1]
    const float* __restrict__ att)    // [4,64]
{
    extern __shared__ float smem[];
    const int tid  = threadIdx.x;
    const int lane = tid & 31, warp = tid >> 5;
    const int g = lane >> 2, tg = lane & 3;
    const int wm = (warp >> 2) * 64, wn = (warp & 3) * 32;
    const int bm = blockIdx.y * TBM, bn = blockIdx.x * TBN;
    const int K = 128, Ncol = DIN;

    Frag f;
#pragma unroll
    for (int mt = 0; mt < 4; mt++)
#pragma unroll
        for (int nt = 0; nt < 4; nt++)
#pragma unroll
            for (int r = 0; r < 4; r++) f.c[mt][nt][r] = 0.f;

    const int KT = K / TBK;
    load_stage(smem, 0, A, W, bm, bn, 0, K, Ncol, tid);
    for (int kt = 0; kt < KT; kt++) {
        int s = kt & 1;
        if (kt + 1 < KT) {
            load_stage(smem, s ^ 1, A, W, bm, bn, (kt + 1) * TBK, K, Ncol, tid);
            asm volatile("cp.async.wait_group 1;");
        } else {
            asm volatile("cp.async.wait_group 0;");
        }
        __syncthreads();
        compute_stage(smem, s, f, wm, wn, g, tg);
        __syncthreads();
    }

    // stage e1 tile into smem (overwrites stage buffers; synced above)
#pragma unroll
    for (int mt = 0; mt < 4; mt++) {
        int r0 = wm + mt * 16 + g;
#pragma unroll
        for (int nt = 0; nt < 4; nt++) {
            int col = wn + nt * 8 + 2 * tg;
            ET(r0, col)         = f.c[mt][nt][0];
            ET(r0, col + 1)     = f.c[mt][nt][1];
            ET(r0 + 8, col)     = f.c[mt][nt][2];
            ET(r0 + 8, col + 1) = f.c[mt][nt][3];
        }
    }
    __syncthreads();

    // phase 2: 2 edges at a time, gathers front-batched
    const float4 av = *(const float4*)&att[bn + lane * 4];
#pragma unroll 2
    for (int er = warp * 16; er < warp * 16 + 16; er += 2) {
        int e0 = bm + er, e1 = bm + er + 1;
        int s0 = adj[e0], d0 = adj[E1_ + e0];
        int s1 = adj[e1], d1 = adj[E1_ + e1];
        float4 xl0 = *(const float4*)&g_xl[(size_t)s0 * DIN + bn + lane * 4];
        float4 xr0 = *(const float4*)&g_xr[(size_t)d0 * DIN + bn + lane * 4];
        float4 xl1 = *(const float4*)&g_xl[(size_t)s1 * DIN + bn + lane * 4];
        float4 xr1 = *(const float4*)&g_xr[(size_t)d1 * DIN + bn + lane * 4];
        float p0, p1;
        p0  = lrelu02(xl0.x + xr0.x + ET(er, lane * 4 + 0)) * av.x;
        p0 += lrelu02(xl0.y + xr0.y + ET(er, lane * 4 + 1)) * av.y;
        p0 += lrelu02(xl0.z + xr0.z + ET(er, lane * 4 + 2)) * av.z;
        p0 += lrelu02(xl0.w + xr0.w + ET(er, lane * 4 + 3)) * av.w;
        p1  = lrelu02(xl1.x + xr1.x + ET(er + 1, lane * 4 + 0)) * av.x;
        p1 += lrelu02(xl1.y + xr1.y + ET(er + 1, lane * 4 + 1)) * av.y;
        p1 += lrelu02(xl1.z + xr1.z + ET(er + 1, lane * 4 + 2)) * av.z;
        p1 += lrelu02(xl1.w + xr1.w + ET(er + 1, lane * 4 + 3)) * av.w;
#pragma unroll
        for (int off = 8; off > 0; off >>= 1) {
            p0 += __shfl_xor_sync(0xffffffff, p0, off);
            p1 += __shfl_xor_sync(0xffffffff, p1, off);
        }
        float ex0 = expf(p0), ex1 = expf(p1);
        red_add_v4(&g_nodeout[(size_t)d0 * DIN + bn + lane * 4],
                   make_float4(ex0 * xl0.x, ex0 * xl0.y, ex0 * xl0.z, ex0 * xl0.w));
        red_add_v4(&g_nodeout[(size_t)d1 * DIN + bn + lane * 4],
                   make_float4(ex1 * xl1.x, ex1 * xl1.y, ex1 * xl1.z, ex1 * xl1.w));
        if (lane == 0 || lane == 16) {
            int head = 2 * blockIdx.x + (lane >> 4);
            atomicAdd(&g_den1[(size_t)d0 * 4 + head], ex0);
            atomicAdd(&g_den1[(size_t)d1 * 4 + head], ex1);
        }
    }
}

// ---------------- prep: concat + inits (nodeout zero-seeded: numerator accumulator) ----------------
__global__ void prep_kernel(const float* __restrict__ x_node,
                            const float* __restrict__ x_log)
{
    size_t idx = (size_t)blockIdx.x * blockDim.x + threadIdx.x;
    if (idx >= (size_t)NN_ * DIN) return;
    int i = (int)(idx >> 8), c = (int)(idx & 255);
    g_node[idx] = (c < 128) ? x_node[(size_t)i * 128 + c]
                            : x_log[(size_t)i * 128 + (c - 128)];
    g_nodeout[idx] = 0.f;
    if (idx < NN_ * 4) g_den1[idx] = 0.f;
    if (idx < (size_t)E1_ * 4) g_den2[idx] = 0.f;
}

// normalize nodeout in place AND write xn / xlg output regions
__global__ void normalize_node_kernel(float* __restrict__ out, const float* __restrict__ bias1) {
    size_t idx = (size_t)blockIdx.x * blockDim.x + threadIdx.x;
    if (idx >= (size_t)NN_ * DIN) return;
    int i = (int)(idx >> 8), c = (int)(idx & 255);
    float v = g_nodeout[idx] / (g_den1[i * 4 + (c >> 6)] + EPSV) + bias1[c];
    g_nodeout[idx] = v;
    const size_t XN = (size_t)NN_ * 128;
    const size_t XT = (size_t)E1_ * 128;
    if (c < 128) out[(size_t)i * 128 + c] = v;
    else         out[XN + XT + (size_t)i * 128 + (c - 128)] = v;
}

// ---------------- layer-2 merged attention + aggregate, 4 edges/warp ----------------
// All 12 gathers issued before any compute (MLP=12), then per-edge exp + RED.
__global__ __launch_bounds__(256) void alpha2_agg2_kernel(const int* __restrict__ adj,
                                                          const int* __restrict__ efea,
                                                          const float* __restrict__ att,
                                                          float* __restrict__ out_xt)
{
    int warp = (blockIdx.x * blockDim.x + threadIdx.x) >> 5;
    int lane = threadIdx.x & 31;
    int e0 = warp * 4;
    if (e0 >= E2_) return;
    float4 av = *(const float4*)&att[lane * 4];

    int src[4], dst[4], ef[4];
#pragma unroll
    for (int i = 0; i < 4; i++) {
        src[i] = adj[e0 + i];
        dst[i] = adj[(size_t)E2_ + e0 + i];
        ef[i]  = efea[e0 + i];
    }

    // issue all 12 row gathers up front
    float4 xl[4], xr[4], ee[4];
#pragma unroll
    for (int i = 0; i < 4; i++) xl[i] = *(const float4*)&g_xl2  [(size_t)src[i] * DED + lane * 4];
#pragma unroll
    for (int i = 0; i < 4; i++) xr[i] = *(const float4*)&g_xr2  [(size_t)dst[i] * DED + lane * 4];
#pragma unroll
    for (int i = 0; i < 4; i++) ee[i] = *(const float4*)&g_gfeat[(size_t)ef[i]  * DED + lane * 4];

    float p[4];
#pragma unroll
    for (int i = 0; i < 4; i++) {
        float q;
        q  = lrelu02(xl[i].x + xr[i].x + ee[i].x) * av.x;
        q += lrelu02(xl[i].y + xr[i].y + ee[i].y) * av.y;
        q += lrelu02(xl[i].z + xr[i].z + ee[i].z) * av.z;
        q += lrelu02(xl[i].w + xr[i].w + ee[i].w) * av.w;
        p[i] = q;
    }
#pragma unroll
    for (int off = 4; off > 0; off >>= 1) {
#pragma unroll
        for (int i = 0; i < 4; i++)
            p[i] += __shfl_xor_sync(0xffffffff, p[i], off);
    }
#pragma unroll
    for (int i = 0; i < 4; i++) {
        float ex = expf(p[i]);
        red_add_v4(&out_xt[(size_t)dst[i] * DED + lane * 4],
                   make_float4(ex * xl[i].x, ex * xl[i].y, ex * xl[i].z, ex * xl[i].w));
        if ((lane & 7) == 0)
            atomicAdd(&g_den2[(size_t)dst[i] * 4 + (lane >> 3)], ex);
    }
}

// seed xt output region with zeros (numerator accumulator)
__global__ void seed_xt_kernel(float* __restrict__ out_xt) {
    size_t idx = (size_t)blockIdx.x * blockDim.x + threadIdx.x;
    if (idx >= (size_t)E1_ * 128) return;
    out_xt[idx] = 0.f;
}

// normalize xt in place: divide by den, add bias
__global__ void normalize_xt_kernel(float* __restrict__ out_xt, const float* __restrict__ bias2) {
    size_t idx = (size_t)blockIdx.x * blockDim.x + threadIdx.x;
    if (idx >= (size_t)E1_ * 128) return;
    int e = (int)(idx >> 7), c = (int)(idx & 127);
    out_xt[idx] = out_xt[idx] / (g_den2[(size_t)e * 4 + (c >> 5)] + EPSV) + bias2[c];
}

// ---------------- launch ----------------
extern "C" void kernel_launch(void* const* d_in, const int* in_sizes, int n_in,
                              void* d_out, int out_size)
{
    const float* x_node   = (const float*)d_in[0];
    const float* x_trace  = (const float*)d_in[1];
    const float* x_log    = (const float*)d_in[2];
    const int*   node_adj = (const int*)d_in[3];
    const int*   edge_adj = (const int*)d_in[4];
    const int*   edge_efea= (const int*)d_in[5];
    const float* n2n_Wl   = (const float*)d_in[6];
    const float* n2n_bl   = (const float*)d_in[7];
    const float* n2n_Wr   = (const float*)d_in[8];
    const float* n2n_br   = (const float*)d_in[9];
    const float* n2n_We   = (const float*)d_in[10];
    const float* n2n_att  = (const float*)d_in[11];
    const float* n2n_bias = (const float*)d_in[12];
    const float* e2n_Wl   = (const float*)d_in[13];
    const float* e2n_bl   = (const float*)d_in[14];
    const float* e2n_Wr   = (const float*)d_in[15];
    const float* e2n_br   = (const float*)d_in[16];
    const float* e2n_We   = (const float*)d_in[17];
    const float* e2n_att  = (const float*)d_in[18];
    const float* e2n_bias = (const float*)d_in[19];
    float* out = (float*)d_out;
    float* out_xt = out + (size_t)NN_ * 128;

    float* p_node;    cudaGetSymbolAddress((void**)&p_node,    g_node);
    float* p_xl;      cudaGetSymbolAddress((void**)&p_xl,      g_xl);
    float* p_xr;      cudaGetSymbolAddress((void**)&p_xr,      g_xr);
    float* p_nodeout; cudaGetSymbolAddress((void**)&p_nodeout, g_nodeout);
    float* p_xl2;     cudaGetSymbolAddress((void**)&p_xl2,     g_xl2);
    float* p_xr2;     cudaGetSymbolAddress((void**)&p_xr2,     g_xr2);
    float* p_g;       cudaGetSymbolAddress((void**)&p_g,       g_gfeat);

    const int SMEM_PIPE = 2 * STG * 4;          // 71680 (covers ET 128*132*4=67584 too)
    static cudaStream_t s1 = nullptr;
    static cudaEvent_t evA = nullptr, evB = nullptr;
    if (!s1) {
        cudaFuncSetAttribute(gemm_pipe, cudaFuncAttributeMaxDynamicSharedMemorySize, SMEM_PIPE);
        cudaFuncSetAttribute(gemm_alpha1_agg1_fused, cudaFuncAttributeMaxDynamicSharedMemorySize, SMEM_PIPE);
        cudaStreamCreateWithFlags(&s1, cudaStreamNonBlocking);
        cudaEventCreateWithFlags(&evA, cudaEventDisableTiming);
        cudaEventCreateWithFlags(&evB, cudaEventDisableTiming);
    }

    // fork side stream: zero-seed xt numerator + xl2/xr2 GEMM (depend only on inputs)
    cudaEventRecord(evA, 0);
    cudaStreamWaitEvent(s1, evA, 0);
    seed_xt_kernel<<<(E1_ * 128) / 256, 256, 0, s1>>>(out_xt);
    {
        dim3 gdim(DED / TBN, E1_ / TBM, 2);
        gemm_pipe<<<gdim, 256, SMEM_PIPE, s1>>>(x_trace, e2n_Wl, e2n_Wr, e2n_bl, e2n_br,
                                                p_xl2, p_xr2, E1_, DED, DED);
    }
    cudaEventRecord(evB, s1);

    // main stream: prep -> xl/xr -> fused alpha1+agg1 -> normalize_node
    prep_kernel<<<(NN_ * DIN) / 256, 256>>>(x_node, x_log);
    {
        dim3 gdim(DIN / TBN, NN_ / TBM, 2);
        gemm_pipe<<<gdim, 256, SMEM_PIPE>>>(p_node, n2n_Wl, n2n_Wr, n2n_bl, n2n_br,
                                            p_xl, p_xr, NN_, DIN, DIN);
    }
    {
        dim3 gdim(DIN / TBN, E1_ / TBM);
        gemm_alpha1_agg1_fused<<<gdim, 256, SMEM_PIPE>>>(x_trace, n2n_We, node_adj, n2n_att);
    }
    normalize_node_kernel<<<(NN_ * DIN) / 256, 256>>>(out, n2n_bias);

    // main: gfeat = node_out @ We2
    {
        dim3 gdim(DED / TBN, NN_ / TBM, 1);
        gemm_pipe<<<gdim, 256, SMEM_PIPE>>>(p_nodeout, e2n_We, e2n_We, nullptr, nullptr,
                                            p_g, p_g, NN_, DED, DIN);
    }

    // join: merged layer-2 needs xl2/xr2 + seeded xt from side stream
    cudaStreamWaitEvent(0, evB, 0);

    alpha2_agg2_kernel<<<E2_ / 32, 256>>>(edge_adj, edge_efea, e2n_att, out_xt);
    normalize_xt_kernel<<<(E1_ * 128) / 256, 256>>>(out_xt, e2n_bias);
}

// round 13
// speedup vs baseline: 1.5077x; 1.0239x over previous
#include <cuda_runtime.h>
#include <stdint.h>
#include <math.h>
#include <float.h>

// ---------------- problem constants ----------------
#define NN_   8192      // nodes
#define E1_   131072    // node-graph edges (= trace rows)
#define E2_   524288    // line-graph edges
#define DIN   256       // layer1 channels (4 heads x 64)
#define DED   128       // layer2 channels (4 heads x 32)
#define EPSV  1e-16f

// ---------------- scratch (static device, no allocs) ----------------
__device__ float g_xl     [(size_t)NN_ * DIN];
__device__ float g_xr     [(size_t)NN_ * DIN];
__device__ float g_den1   [(size_t)NN_ * 4];
__device__ float g_nodeout[(size_t)NN_ * DIN];  // numerator, then normalized
__device__ float g_xl2    [(size_t)E1_ * DED];
__device__ float g_xr2    [(size_t)E1_ * DED];
__device__ float g_gfeat  [(size_t)NN_ * DED];
__device__ float g_den2   [(size_t)E1_ * 4];

// ---------------- helpers ----------------
__device__ __forceinline__ float lrelu02(float x) { return x > 0.f ? x : 0.2f * x; }
__device__ __forceinline__ uint32_t to_tf32(float v) {
    uint32_t t;
    asm("cvt.rna.tf32.f32 %0, %1;" : "=r"(t) : "f"(v));
    return t;
}
__device__ __forceinline__ void cp16(uint32_t dst, const void* src) {
    asm volatile("cp.async.cg.shared.global [%0], [%1], 16;" :: "r"(dst), "l"(src));
}
__device__ __forceinline__ void red_add_v4(float* addr, float4 v) {
    asm volatile("red.global.add.v4.f32 [%0], {%1,%2,%3,%4};"
                 :: "l"(addr), "f"(v.x), "f"(v.y), "f"(v.z), "f"(v.w) : "memory");
}

// ---------------- tf32 GEMM tiles ----------------
#define TBM 128
#define TBN 128
#define TBK 32
#define STG 8960                 // floats per stage: 128*36 + 32*136
#define AS(S,M,K_) smem[(S)*STG + (M)*36 + (K_)]
#define BS(S,KK,N_) smem[(S)*STG + 4608 + (KK)*136 + (N_)]
#define ET(R,C) smem[(R)*132 + (C)]

struct Frag { float c[4][4][4]; };

// A source: if A1 != nullptr, rows come from A (k<128) or A1 (k>=128), each stride 128.
// Otherwise A with row stride strideA.
__device__ __forceinline__ void load_stage(float* smem, int s,
    const float* __restrict__ A, const float* __restrict__ A1, int strideA,
    const float* __restrict__ W,
    int bm, int bn, int k0, int Ncol, int tid)
{
    const float* Abase = A;
    int acol = k0;
    int astr = strideA;
    if (A1) {
        astr = 128;
        if (k0 >= 128) { Abase = A1; acol = k0 - 128; }
    }
#pragma unroll
    for (int i = 0; i < 4; i++) {
        int idx = tid + i * 256;
        int m = idx >> 3, kc = idx & 7;
        cp16((uint32_t)__cvta_generic_to_shared(&AS(s, m, kc * 4)),
             &Abase[(size_t)(bm + m) * astr + acol + kc * 4]);
    }
#pragma unroll
    for (int i = 0; i < 4; i++) {
        int idx = tid + i * 256;
        int kk = idx >> 5, nc = idx & 31;
        cp16((uint32_t)__cvta_generic_to_shared(&BS(s, kk, nc * 4)),
             &W[(size_t)(k0 + kk) * Ncol + bn + nc * 4]);
    }
    asm volatile("cp.async.commit_group;");
}

__device__ __forceinline__ void compute_stage(const float* smem, int s, Frag& f,
                                              int wm, int wn, int g, int tg)
{
#pragma unroll
    for (int ks = 0; ks < 4; ks++) {
        const int kb = ks * 8;
        uint32_t afr[4][4], bfr[4][2];
#pragma unroll
        for (int mt = 0; mt < 4; mt++) {
            int mr = wm + mt * 16 + g;
            afr[mt][0] = to_tf32(AS(s, mr,     kb + tg));
            afr[mt][1] = to_tf32(AS(s, mr + 8, kb + tg));
            afr[mt][2] = to_tf32(AS(s, mr,     kb + tg + 4));
            afr[mt][3] = to_tf32(AS(s, mr + 8, kb + tg + 4));
        }
#pragma unroll
        for (int nt = 0; nt < 4; nt++) {
            int nc = wn + nt * 8 + g;
            bfr[nt][0] = to_tf32(BS(s, kb + tg,     nc));
            bfr[nt][1] = to_tf32(BS(s, kb + tg + 4, nc));
        }
#pragma unroll
        for (int mt = 0; mt < 4; mt++)
#pragma unroll
            for (int nt = 0; nt < 4; nt++) {
                asm volatile(
                    "mma.sync.aligned.m16n8k8.row.col.f32.tf32.tf32.f32 "
                    "{%0,%1,%2,%3}, {%4,%5,%6,%7}, {%8,%9}, {%0,%1,%2,%3};"
                    : "+f"(f.c[mt][nt][0]), "+f"(f.c[mt][nt][1]),
                      "+f"(f.c[mt][nt][2]), "+f"(f.c[mt][nt][3])
                    : "r"(afr[mt][0]), "r"(afr[mt][1]),
                      "r"(afr[mt][2]), "r"(afr[mt][3]),
                      "r"(bfr[nt][0]), "r"(bfr[nt][1]));
            }
    }
}

// Pipelined GEMM; optional dual-A (concat rows) and dual-output (blockIdx.z selects W/bias/C).
__global__ __launch_bounds__(256) void gemm_pipe(
    const float* __restrict__ A, const float* __restrict__ A1,
    const float* __restrict__ W0, const float* __restrict__ W1,
    const float* __restrict__ b0, const float* __restrict__ b1,
    float* __restrict__ C0, float* __restrict__ C1,
    int M, int Ncol, int K)
{
    extern __shared__ float smem[];
    const int tid  = threadIdx.x;
    const int lane = tid & 31, warp = tid >> 5;
    const int g = lane >> 2, tg = lane & 3;
    const int wm = (warp >> 2) * 64, wn = (warp & 3) * 32;
    const int bm = blockIdx.y * TBM, bn = blockIdx.x * TBN;
    const int z  = blockIdx.z;
    const float* W    = z ? W1 : W0;
    const float* bias = z ? b1 : b0;
    float* C          = z ? C1 : C0;

    Frag f;
#pragma unroll
    for (int mt = 0; mt < 4; mt++)
#pragma unroll
        for (int nt = 0; nt < 4; nt++)
#pragma unroll
            for (int r = 0; r < 4; r++) f.c[mt][nt][r] = 0.f;

    const int KT = K / TBK;
    load_stage(smem, 0, A, A1, K, W, bm, bn, 0, Ncol, tid);
    for (int kt = 0; kt < KT; kt++) {
        int s = kt & 1;
        if (kt + 1 < KT) {
            load_stage(smem, s ^ 1, A, A1, K, W, bm, bn, (kt + 1) * TBK, Ncol, tid);
            asm volatile("cp.async.wait_group 1;");
        } else {
            asm volatile("cp.async.wait_group 0;");
        }
        __syncthreads();
        compute_stage(smem, s, f, wm, wn, g, tg);
        __syncthreads();
    }

#pragma unroll
    for (int mt = 0; mt < 4; mt++) {
        int r0 = bm + wm + mt * 16 + g;
#pragma unroll
        for (int nt = 0; nt < 4; nt++) {
            int col = bn + wn + nt * 8 + 2 * tg;
            float bb0 = bias ? bias[col] : 0.f;
            float bb1 = bias ? bias[col + 1] : 0.f;
            float2 v0 = make_float2(f.c[mt][nt][0] + bb0, f.c[mt][nt][1] + bb1);
            float2 v1 = make_float2(f.c[mt][nt][2] + bb0, f.c[mt][nt][3] + bb1);
            *(float2*)&C[(size_t)r0 * Ncol + col] = v0;
            *(float2*)&C[(size_t)(r0 + 8) * Ncol + col] = v1;
        }
    }
}

// Fused layer-1: e1 = trace @ We in smem, then per-edge logit -> exp ->
// numerator (ex * xl[src]) RED into nodeout + denominator RED into den1.
// grid (2, E1/128): blockIdx.x selects channels [0,128)=heads{0,1} or [128,256)=heads{2,3}.
// Phase-2 processes 4 edges at a time with front-batched gathers (MLP=8).
__global__ __launch_bounds__(256) void gemm_alpha1_agg1_fused(
    const float* __restrict__ A,      // x_trace [E1,128]
    const float* __restrict__ W,      // n2n_We [128,256]
    const int*   __restrict__ adj,    // node_adj [2,E1]
    const float* __restrict__ att)    // [4,64]
{
    extern __shared__ float smem[];
    const int tid  = threadIdx.x;
    const int lane = tid & 31, warp = tid >> 5;
    const int g = lane >> 2, tg = lane & 3;
    const int wm = (warp >> 2) * 64, wn = (warp & 3) * 32;
    const int bm = blockIdx.y * TBM, bn = blockIdx.x * TBN;
    const int K = 128, Ncol = DIN;

    Frag f;
#pragma unroll
    for (int mt = 0; mt < 4; mt++)
#pragma unroll
        for (int nt = 0; nt < 4; nt++)
#pragma unroll
            for (int r = 0; r < 4; r++) f.c[mt][nt][r] = 0.f;

    const int KT = K / TBK;
    load_stage(smem, 0, A, nullptr, K, W, bm, bn, 0, Ncol, tid);
    for (int kt = 0; kt < KT; kt++) {
        int s = kt & 1;
        if (kt + 1 < KT) {
            load_stage(smem, s ^ 1, A, nullptr, K, W, bm, bn, (kt + 1) * TBK, Ncol, tid);
            asm volatile("cp.async.wait_group 1;");
        } else {
            asm volatile("cp.async.wait_group 0;");
        }
        __syncthreads();
        compute_stage(smem, s, f, wm, wn, g, tg);
        __syncthreads();
    }

    // stage e1 tile into smem (overwrites stage buffers; synced above)
#pragma unroll
    for (int mt = 0; mt < 4; mt++) {
        int r0 = wm + mt * 16 + g;
#pragma unroll
        for (int nt = 0; nt < 4; nt++) {
            int col = wn + nt * 8 + 2 * tg;
            ET(r0, col)         = f.c[mt][nt][0];
            ET(r0, col + 1)     = f.c[mt][nt][1];
            ET(r0 + 8, col)     = f.c[mt][nt][2];
            ET(r0 + 8, col + 1) = f.c[mt][nt][3];
        }
    }
    __syncthreads();

    // phase 2: 4 edges at a time, gathers front-batched
    const float4 av = *(const float4*)&att[bn + lane * 4];
#pragma unroll
    for (int it = 0; it < 4; it++) {
        int er = warp * 16 + it * 4;
        int eg = bm + er;
        int s_[4], d_[4];
#pragma unroll
        for (int i = 0; i < 4; i++) {
            s_[i] = adj[eg + i];
            d_[i] = adj[E1_ + eg + i];
        }
        float4 xlv[4], xrv[4];
#pragma unroll
        for (int i = 0; i < 4; i++) xlv[i] = *(const float4*)&g_xl[(size_t)s_[i] * DIN + bn + lane * 4];
#pragma unroll
        for (int i = 0; i < 4; i++) xrv[i] = *(const float4*)&g_xr[(size_t)d_[i] * DIN + bn + lane * 4];

        float p[4];
#pragma unroll
        for (int i = 0; i < 4; i++) {
            float q;
            q  = lrelu02(xlv[i].x + xrv[i].x + ET(er + i, lane * 4 + 0)) * av.x;
            q += lrelu02(xlv[i].y + xrv[i].y + ET(er + i, lane * 4 + 1)) * av.y;
            q += lrelu02(xlv[i].z + xrv[i].z + ET(er + i, lane * 4 + 2)) * av.z;
            q += lrelu02(xlv[i].w + xrv[i].w + ET(er + i, lane * 4 + 3)) * av.w;
            p[i] = q;
        }
#pragma unroll
        for (int off = 8; off > 0; off >>= 1) {
#pragma unroll
            for (int i = 0; i < 4; i++)
                p[i] += __shfl_xor_sync(0xffffffff, p[i], off);
        }
#pragma unroll
        for (int i = 0; i < 4; i++) {
            float ex = expf(p[i]);
            red_add_v4(&g_nodeout[(size_t)d_[i] * DIN + bn + lane * 4],
                       make_float4(ex * xlv[i].x, ex * xlv[i].y, ex * xlv[i].z, ex * xlv[i].w));
            if (lane == 0 || lane == 16) {
                int head = 2 * blockIdx.x + (lane >> 4);
                atomicAdd(&g_den1[(size_t)d_[i] * 4 + head], ex);
            }
        }
    }
}

// ---------------- prep: zero numerator + den inits ----------------
__global__ void prep_kernel() {
    size_t idx = (size_t)blockIdx.x * blockDim.x + threadIdx.x;
    if (idx >= (size_t)NN_ * DIN) return;
    g_nodeout[idx] = 0.f;
    if (idx < NN_ * 4) g_den1[idx] = 0.f;
    if (idx < (size_t)E1_ * 4) g_den2[idx] = 0.f;
}

// normalize nodeout in place AND write xn / xlg output regions
__global__ void normalize_node_kernel(float* __restrict__ out, const float* __restrict__ bias1) {
    size_t idx = (size_t)blockIdx.x * blockDim.x + threadIdx.x;
    if (idx >= (size_t)NN_ * DIN) return;
    int i = (int)(idx >> 8), c = (int)(idx & 255);
    float v = g_nodeout[idx] / (g_den1[i * 4 + (c >> 6)] + EPSV) + bias1[c];
    g_nodeout[idx] = v;
    const size_t XN = (size_t)NN_ * 128;
    const size_t XT = (size_t)E1_ * 128;
    if (c < 128) out[(size_t)i * 128 + c] = v;
    else         out[XN + XT + (size_t)i * 128 + (c - 128)] = v;
}

// ---------------- layer-2 merged attention + aggregate, 4 edges/warp ----------------
__global__ __launch_bounds__(256) void alpha2_agg2_kernel(const int* __restrict__ adj,
                                                          const int* __restrict__ efea,
                                                          const float* __restrict__ att,
                                                          float* __restrict__ out_xt)
{
    int warp = (blockIdx.x * blockDim.x + threadIdx.x) >> 5;
    int lane = threadIdx.x & 31;
    int e0 = warp * 4;
    if (e0 >= E2_) return;
    float4 av = *(const float4*)&att[lane * 4];

    int src[4], dst[4], ef[4];
#pragma unroll
    for (int i = 0; i < 4; i++) {
        src[i] = adj[e0 + i];
        dst[i] = adj[(size_t)E2_ + e0 + i];
        ef[i]  = efea[e0 + i];
    }

    float4 xl[4], xr[4], ee[4];
#pragma unroll
    for (int i = 0; i < 4; i++) xl[i] = *(const float4*)&g_xl2  [(size_t)src[i] * DED + lane * 4];
#pragma unroll
    for (int i = 0; i < 4; i++) xr[i] = *(const float4*)&g_xr2  [(size_t)dst[i] * DED + lane * 4];
#pragma unroll
    for (int i = 0; i < 4; i++) ee[i] = *(const float4*)&g_gfeat[(size_t)ef[i]  * DED + lane * 4];

    float p[4];
#pragma unroll
    for (int i = 0; i < 4; i++) {
        float q;
        q  = lrelu02(xl[i].x + xr[i].x + ee[i].x) * av.x;
        q += lrelu02(xl[i].y + xr[i].y + ee[i].y) * av.y;
        q += lrelu02(xl[i].z + xr[i].z + ee[i].z) * av.z;
        q += lrelu02(xl[i].w + xr[i].w + ee[i].w) * av.w;
        p[i] = q;
    }
#pragma unroll
    for (int off = 4; off > 0; off >>= 1) {
#pragma unroll
        for (int i = 0; i < 4; i++)
            p[i] += __shfl_xor_sync(0xffffffff, p[i], off);
    }
#pragma unroll
    for (int i = 0; i < 4; i++) {
        float ex = expf(p[i]);
        red_add_v4(&out_xt[(size_t)dst[i] * DED + lane * 4],
                   make_float4(ex * xl[i].x, ex * xl[i].y, ex * xl[i].z, ex * xl[i].w));
        if ((lane & 7) == 0)
            atomicAdd(&g_den2[(size_t)dst[i] * 4 + (lane >> 3)], ex);
    }
}

// seed xt output region with zeros (numerator accumulator)
__global__ void seed_xt_kernel(float* __restrict__ out_xt) {
    size_t idx = (size_t)blockIdx.x * blockDim.x + threadIdx.x;
    if (idx >= (size_t)E1_ * 128) return;
    out_xt[idx] = 0.f;
}

// normalize xt in place: divide by den, add bias
__global__ void normalize_xt_kernel(float* __restrict__ out_xt, const float* __restrict__ bias2) {
    size_t idx = (size_t)blockIdx.x * blockDim.x + threadIdx.x;
    if (idx >= (size_t)E1_ * 128) return;
    int e = (int)(idx >> 7), c = (int)(idx & 127);
    out_xt[idx] = out_xt[idx] / (g_den2[(size_t)e * 4 + (c >> 5)] + EPSV) + bias2[c];
}

// ---------------- launch ----------------
extern "C" void kernel_launch(void* const* d_in, const int* in_sizes, int n_in,
                              void* d_out, int out_size)
{
    const float* x_node   = (const float*)d_in[0];
    const float* x_trace  = (const float*)d_in[1];
    const float* x_log    = (const float*)d_in[2];
    const int*   node_adj = (const int*)d_in[3];
    const int*   edge_adj = (const int*)d_in[4];
    const int*   edge_efea= (const int*)d_in[5];
    const float* n2n_Wl   = (const float*)d_in[6];
    const float* n2n_bl   = (const float*)d_in[7];
    const float* n2n_Wr   = (const float*)d_in[8];
    const float* n2n_br   = (const float*)d_in[9];
    const float* n2n_We   = (const float*)d_in[10];
    const float* n2n_att  = (const float*)d_in[11];
    const float* n2n_bias = (const float*)d_in[12];
    const float* e2n_Wl   = (const float*)d_in[13];
    const float* e2n_bl   = (const float*)d_in[14];
    const float* e2n_Wr   = (const float*)d_in[15];
    const float* e2n_br   = (const float*)d_in[16];
    const float* e2n_We   = (const float*)d_in[17];
    const float* e2n_att  = (const float*)d_in[18];
    const float* e2n_bias = (const float*)d_in[19];
    float* out = (float*)d_out;
    float* out_xt = out + (size_t)NN_ * 128;

    float* p_xl;      cudaGetSymbolAddress((void**)&p_xl,      g_xl);
    float* p_xr;      cudaGetSymbolAddress((void**)&p_xr,      g_xr);
    float* p_nodeout; cudaGetSymbolAddress((void**)&p_nodeout, g_nodeout);
    float* p_xl2;     cudaGetSymbolAddress((void**)&p_xl2,     g_xl2);
    float* p_xr2;     cudaGetSymbolAddress((void**)&p_xr2,     g_xr2);
    float* p_g;       cudaGetSymbolAddress((void**)&p_g,       g_gfeat);

    const int SMEM_PIPE = 2 * STG * 4;          // 71680 (covers ET 128*132*4=67584 too)
    static cudaStream_t s1 = nullptr;
    static cudaEvent_t evA = nullptr, evB = nullptr;
    if (!s1) {
        cudaFuncSetAttribute(gemm_pipe, cudaFuncAttributeMaxDynamicSharedMemorySize, SMEM_PIPE);
        cudaFuncSetAttribute(gemm_alpha1_agg1_fused, cudaFuncAttributeMaxDynamicSharedMemorySize, SMEM_PIPE);
        cudaStreamCreateWithFlags(&s1, cudaStreamNonBlocking);
        cudaEventCreateWithFlags(&evA, cudaEventDisableTiming);
        cudaEventCreateWithFlags(&evB, cudaEventDisableTiming);
    }

    // fork side stream: zero-seed xt numerator + xl2/xr2 GEMM (depend only on inputs)
    cudaEventRecord(evA, 0);
    cudaStreamWaitEvent(s1, evA, 0);
    seed_xt_kernel<<<(E1_ * 128) / 256, 256, 0, s1>>>(out_xt);
    {
        dim3 gdim(DED / TBN, E1_ / TBM, 2);
        gemm_pipe<<<gdim, 256, SMEM_PIPE, s1>>>(x_trace, nullptr, e2n_Wl, e2n_Wr, e2n_bl, e2n_br,
                                                p_xl2, p_xr2, E1_, DED, DED);
    }
    cudaEventRecord(evB, s1);

    // main stream: prep -> xl/xr (dual-A, no concat) -> fused alpha1+agg1 -> normalize_node
    prep_kernel<<<(NN_ * DIN) / 256, 256>>>();
    {
        dim3 gdim(DIN / TBN, NN_ / TBM, 2);
        gemm_pipe<<<gdim, 256, SMEM_PIPE>>>(x_node, x_log, n2n_Wl, n2n_Wr, n2n_bl, n2n_br,
                                            p_xl, p_xr, NN_, DIN, DIN);
    }
    {
        dim3 gdim(DIN / TBN, E1_ / TBM);
        gemm_alpha1_agg1_fused<<<gdim, 256, SMEM_PIPE>>>(x_trace, n2n_We, node_adj, n2n_att);
    }
    normalize_node_kernel<<<(NN_ * DIN) / 256, 256>>>(out, n2n_bias);

    // main: gfeat = node_out @ We2
    {
        dim3 gdim(DED / TBN, NN_ / TBM, 1);
        gemm_pipe<<<gdim, 256, SMEM_PIPE>>>(p_nodeout, nullptr, e2n_We, e2n_We, nullptr, nullptr,
                                            p_g, p_g, NN_, DED, DIN);
    }

    // join: merged layer-2 needs xl2/xr2 + seeded xt from side stream
    cudaStreamWaitEvent(0, evB, 0);

    alpha2_agg2_kernel<<<E2_ / 32, 256>>>(edge_adj, edge_efea, e2n_att, out_xt);
    normalize_xt_kernel<<<(E1_ * 128) / 256, 256>>>(out_xt, e2n_bias);
}

// round 14
// speedup vs baseline: 1.5711x; 1.0421x over previous
#include <cuda_runtime.h>
#include <stdint.h>
#include <math.h>
#include <float.h>

// ---------------- problem constants ----------------
#define NN_   8192      // nodes
#define E1_   131072    // node-graph edges (= trace rows)
#define E2_   524288    // line-graph edges
#define DIN   256       // layer1 channels (4 heads x 64)
#define DED   128       // layer2 channels (4 heads x 32)
#define EPSV  1e-16f

// ---------------- scratch (static device, no allocs) ----------------
__device__ float g_xl     [(size_t)NN_ * DIN];
__device__ float g_xr     [(size_t)NN_ * DIN];
__device__ float g_den1   [(size_t)NN_ * 4];
__device__ float g_num    [(size_t)NN_ * DIN];  // layer-1 numerator (never normalized in place)
__device__ float g_xl2    [(size_t)E1_ * DED];
__device__ float g_xr2    [(size_t)E1_ * DED];
__device__ float g_gfeat  [(size_t)NN_ * DED];
__device__ float g_den2   [(size_t)E1_ * 4];

// ---------------- helpers ----------------
__device__ __forceinline__ float lrelu02(float x) { return x > 0.f ? x : 0.2f * x; }
__device__ __forceinline__ uint32_t to_tf32(float v) {
    uint32_t t;
    asm("cvt.rna.tf32.f32 %0, %1;" : "=r"(t) : "f"(v));
    return t;
}
__device__ __forceinline__ void cp16(uint32_t dst, const void* src) {
    asm volatile("cp.async.cg.shared.global [%0], [%1], 16;" :: "r"(dst), "l"(src));
}
__device__ __forceinline__ void red_add_v4(float* addr, float4 v) {
    asm volatile("red.global.add.v4.f32 [%0], {%1,%2,%3,%4};"
                 :: "l"(addr), "f"(v.x), "f"(v.y), "f"(v.z), "f"(v.w) : "memory");
}

// ---------------- tf32 GEMM tiles ----------------
#define TBM 128
#define TBN 128
#define TBK 32
#define STG 8960                 // floats per stage: 128*36 + 32*136
#define AS(S,M,K_) smem[(S)*STG + (M)*36 + (K_)]
#define BS(S,KK,N_) smem[(S)*STG + 4608 + (KK)*136 + (N_)]
#define ET(R,C) smem[(R)*132 + (C)]

struct Frag { float c[4][4][4]; };

// A source: if A1 != nullptr, rows come from A (k<128) or A1 (k>=128), each stride 128.
__device__ __forceinline__ void load_stage(float* smem, int s,
    const float* __restrict__ A, const float* __restrict__ A1, int strideA,
    const float* __restrict__ W,
    int bm, int bn, int k0, int Ncol, int tid)
{
    const float* Abase = A;
    int acol = k0;
    int astr = strideA;
    if (A1) {
        astr = 128;
        if (k0 >= 128) { Abase = A1; acol = k0 - 128; }
    }
#pragma unroll
    for (int i = 0; i < 4; i++) {
        int idx = tid + i * 256;
        int m = idx >> 3, kc = idx & 7;
        cp16((uint32_t)__cvta_generic_to_shared(&AS(s, m, kc * 4)),
             &Abase[(size_t)(bm + m) * astr + acol + kc * 4]);
    }
#pragma unroll
    for (int i = 0; i < 4; i++) {
        int idx = tid + i * 256;
        int kk = idx >> 5, nc = idx & 31;
        cp16((uint32_t)__cvta_generic_to_shared(&BS(s, kk, nc * 4)),
             &W[(size_t)(k0 + kk) * Ncol + bn + nc * 4]);
    }
    asm volatile("cp.async.commit_group;");
}

__device__ __forceinline__ void compute_stage(const float* smem, int s, Frag& f,
                                              int wm, int wn, int g, int tg)
{
#pragma unroll
    for (int ks = 0; ks < 4; ks++) {
        const int kb = ks * 8;
        uint32_t afr[4][4], bfr[4][2];
#pragma unroll
        for (int mt = 0; mt < 4; mt++) {
            int mr = wm + mt * 16 + g;
            afr[mt][0] = to_tf32(AS(s, mr,     kb + tg));
            afr[mt][1] = to_tf32(AS(s, mr + 8, kb + tg));
            afr[mt][2] = to_tf32(AS(s, mr,     kb + tg + 4));
            afr[mt][3] = to_tf32(AS(s, mr + 8, kb + tg + 4));
        }
#pragma unroll
        for (int nt = 0; nt < 4; nt++) {
            int nc = wn + nt * 8 + g;
            bfr[nt][0] = to_tf32(BS(s, kb + tg,     nc));
            bfr[nt][1] = to_tf32(BS(s, kb + tg + 4, nc));
        }
#pragma unroll
        for (int mt = 0; mt < 4; mt++)
#pragma unroll
            for (int nt = 0; nt < 4; nt++) {
                asm volatile(
                    "mma.sync.aligned.m16n8k8.row.col.f32.tf32.tf32.f32 "
                    "{%0,%1,%2,%3}, {%4,%5,%6,%7}, {%8,%9}, {%0,%1,%2,%3};"
                    : "+f"(f.c[mt][nt][0]), "+f"(f.c[mt][nt][1]),
                      "+f"(f.c[mt][nt][2]), "+f"(f.c[mt][nt][3])
                    : "r"(afr[mt][0]), "r"(afr[mt][1]),
                      "r"(afr[mt][2]), "r"(afr[mt][3]),
                      "r"(bfr[nt][0]), "r"(bfr[nt][1]));
            }
    }
}

// Pipelined GEMM; optional dual-A (concat rows) and dual-output (blockIdx.z selects W/bias/C).
__global__ __launch_bounds__(256) void gemm_pipe(
    const float* __restrict__ A, const float* __restrict__ A1,
    const float* __restrict__ W0, const float* __restrict__ W1,
    const float* __restrict__ b0, const float* __restrict__ b1,
    float* __restrict__ C0, float* __restrict__ C1,
    int M, int Ncol, int K)
{
    extern __shared__ float smem[];
    const int tid  = threadIdx.x;
    const int lane = tid & 31, warp = tid >> 5;
    const int g = lane >> 2, tg = lane & 3;
    const int wm = (warp >> 2) * 64, wn = (warp & 3) * 32;
    const int bm = blockIdx.y * TBM, bn = blockIdx.x * TBN;
    const int z  = blockIdx.z;
    const float* W    = z ? W1 : W0;
    const float* bias = z ? b1 : b0;
    float* C          = z ? C1 : C0;

    Frag f;
#pragma unroll
    for (int mt = 0; mt < 4; mt++)
#pragma unroll
        for (int nt = 0; nt < 4; nt++)
#pragma unroll
            for (int r = 0; r < 4; r++) f.c[mt][nt][r] = 0.f;

    const int KT = K / TBK;
    load_stage(smem, 0, A, A1, K, W, bm, bn, 0, Ncol, tid);
    for (int kt = 0; kt < KT; kt++) {
        int s = kt & 1;
        if (kt + 1 < KT) {
            load_stage(smem, s ^ 1, A, A1, K, W, bm, bn, (kt + 1) * TBK, Ncol, tid);
            asm volatile("cp.async.wait_group 1;");
        } else {
            asm volatile("cp.async.wait_group 0;");
        }
        __syncthreads();
        compute_stage(smem, s, f, wm, wn, g, tg);
        __syncthreads();
    }

#pragma unroll
    for (int mt = 0; mt < 4; mt++) {
        int r0 = bm + wm + mt * 16 + g;
#pragma unroll
        for (int nt = 0; nt < 4; nt++) {
            int col = bn + wn + nt * 8 + 2 * tg;
            float bb0 = bias ? bias[col] : 0.f;
            float bb1 = bias ? bias[col + 1] : 0.f;
            float2 v0 = make_float2(f.c[mt][nt][0] + bb0, f.c[mt][nt][1] + bb1);
            float2 v1 = make_float2(f.c[mt][nt][2] + bb0, f.c[mt][nt][3] + bb1);
            *(float2*)&C[(size_t)r0 * Ncol + col] = v0;
            *(float2*)&C[(size_t)(r0 + 8) * Ncol + col] = v1;
        }
    }
}

// gfeat GEMM with on-the-fly normalization of A:
// A[m][k] = num[m][k] / (den1[m][k>>6] + eps) + bias1[k];  C = A @ We2  (M=NN_, N=128, K=256)
__global__ __launch_bounds__(256) void gemm_gfeat(
    const float* __restrict__ num, const float* __restrict__ den,
    const float* __restrict__ bias1, const float* __restrict__ W,
    float* __restrict__ C)
{
    extern __shared__ float smem[];
    const int tid  = threadIdx.x;
    const int lane = tid & 31, warp = tid >> 5;
    const int g = lane >> 2, tg = lane & 3;
    const int wm = (warp >> 2) * 64, wn = (warp & 3) * 32;
    const int bm = blockIdx.y * TBM, bn = 0;
    const int Ncol = DED, K = DIN;

    Frag f;
#pragma unroll
    for (int mt = 0; mt < 4; mt++)
#pragma unroll
        for (int nt = 0; nt < 4; nt++)
#pragma unroll
            for (int r = 0; r < 4; r++) f.c[mt][nt][r] = 0.f;

    // A loader: transform into registers
    auto loadA = [&](int k0, float4* out) {
#pragma unroll
        for (int i = 0; i < 4; i++) {
            int idx = tid + i * 256;
            int m = idx >> 3, kc = idx & 7;
            int col = k0 + kc * 4;
            float4 v = *(const float4*)&num[(size_t)(bm + m) * DIN + col];
            float invd = __fdividef(1.f, den[(bm + m) * 4 + (col >> 6)] + EPSV);
            float4 b = *(const float4*)&bias1[col];
            out[i] = make_float4(v.x * invd + b.x, v.y * invd + b.y,
                                 v.z * invd + b.z, v.w * invd + b.w);
        }
    };
    auto stsA = [&](int s, const float4* regs) {
#pragma unroll
        for (int i = 0; i < 4; i++) {
            int idx = tid + i * 256;
            int m = idx >> 3, kc = idx & 7;
            *(float4*)&AS(s, m, kc * 4) = regs[i];
        }
    };
    auto loadB = [&](int s, int k0) {
#pragma unroll
        for (int i = 0; i < 4; i++) {
            int idx = tid + i * 256;
            int kk = idx >> 5, nc = idx & 31;
            cp16((uint32_t)__cvta_generic_to_shared(&BS(s, kk, nc * 4)),
                 &W[(size_t)(k0 + kk) * Ncol + bn + nc * 4]);
        }
        asm volatile("cp.async.commit_group;");
    };

    const int KT = K / TBK;   // 8
    float4 aregs[4];
    loadA(0, aregs);
    stsA(0, aregs);
    loadB(0, 0);
    for (int kt = 0; kt < KT; kt++) {
        int s = kt & 1;
        float4 anext[4];
        if (kt + 1 < KT) {
            loadA((kt + 1) * TBK, anext);
            loadB(s ^ 1, (kt + 1) * TBK);
            asm volatile("cp.async.wait_group 1;");
        } else {
            asm volatile("cp.async.wait_group 0;");
        }
        __syncthreads();
        compute_stage(smem, s, f, wm, wn, g, tg);
        __syncthreads();
        if (kt + 1 < KT) stsA(s ^ 1, anext);
    }

#pragma unroll
    for (int mt = 0; mt < 4; mt++) {
        int r0 = bm + wm + mt * 16 + g;
#pragma unroll
        for (int nt = 0; nt < 4; nt++) {
            int col = bn + wn + nt * 8 + 2 * tg;
            *(float2*)&C[(size_t)r0 * Ncol + col] =
                make_float2(f.c[mt][nt][0], f.c[mt][nt][1]);
            *(float2*)&C[(size_t)(r0 + 8) * Ncol + col] =
                make_float2(f.c[mt][nt][2], f.c[mt][nt][3]);
        }
    }
}

// Fused layer-1: e1 = trace @ We in smem, then per-edge logit -> exp ->
// numerator (ex * xl[src]) RED into g_num + denominator RED into den1.
// grid (2, E1/128). Phase-2: 4 edges at a time, front-batched gathers.
__global__ __launch_bounds__(256) void gemm_alpha1_agg1_fused(
    const float* __restrict__ A,      // x_trace [E1,128]
    const float* __restrict__ W,      // n2n_We [128,256]
    const int*   __restrict__ adj,    // node_adj [2,E1]
    const float* __restrict__ att)    // [4,64]
{
    extern __shared__ float smem[];
    const int tid  = threadIdx.x;
    const int lane = tid & 31, warp = tid >> 5;
    const int g = lane >> 2, tg = lane & 3;
    const int wm = (warp >> 2) * 64, wn = (warp & 3) * 32;
    const int bm = blockIdx.y * TBM, bn = blockIdx.x * TBN;
    const int K = 128, Ncol = DIN;

    Frag f;
#pragma unroll
    for (int mt = 0; mt < 4; mt++)
#pragma unroll
        for (int nt = 0; nt < 4; nt++)
#pragma unroll
            for (int r = 0; r < 4; r++) f.c[mt][nt][r] = 0.f;

    const int KT = K / TBK;
    load_stage(smem, 0, A, nullptr, K, W, bm, bn, 0, Ncol, tid);
    for (int kt = 0; kt < KT; kt++) {
        int s = kt & 1;
        if (kt + 1 < KT) {
            load_stage(smem, s ^ 1, A, nullptr, K, W, bm, bn, (kt + 1) * TBK, Ncol, tid);
            asm volatile("cp.async.wait_group 1;");
        } else {
            asm volatile("cp.async.wait_group 0;");
        }
        __syncthreads();
        compute_stage(smem, s, f, wm, wn, g, tg);
        __syncthreads();
    }

    // stage e1 tile into smem
#pragma unroll
    for (int mt = 0; mt < 4; mt++) {
        int r0 = wm + mt * 16 + g;
#pragma unroll
        for (int nt = 0; nt < 4; nt++) {
            int col = wn + nt * 8 + 2 * tg;
            ET(r0, col)         = f.c[mt][nt][0];
            ET(r0, col + 1)     = f.c[mt][nt][1];
            ET(r0 + 8, col)     = f.c[mt][nt][2];
            ET(r0 + 8, col + 1) = f.c[mt][nt][3];
        }
    }
    __syncthreads();

    const float4 av = *(const float4*)&att[bn + lane * 4];
#pragma unroll
    for (int it = 0; it < 4; it++) {
        int er = warp * 16 + it * 4;
        int eg = bm + er;
        int s_[4], d_[4];
#pragma unroll
        for (int i = 0; i < 4; i++) {
            s_[i] = adj[eg + i];
            d_[i] = adj[E1_ + eg + i];
        }
        float4 xlv[4], xrv[4];
#pragma unroll
        for (int i = 0; i < 4; i++) xlv[i] = *(const float4*)&g_xl[(size_t)s_[i] * DIN + bn + lane * 4];
#pragma unroll
        for (int i = 0; i < 4; i++) xrv[i] = *(const float4*)&g_xr[(size_t)d_[i] * DIN + bn + lane * 4];

        float p[4];
#pragma unroll
        for (int i = 0; i < 4; i++) {
            float q;
            q  = lrelu02(xlv[i].x + xrv[i].x + ET(er + i, lane * 4 + 0)) * av.x;
            q += lrelu02(xlv[i].y + xrv[i].y + ET(er + i, lane * 4 + 1)) * av.y;
            q += lrelu02(xlv[i].z + xrv[i].z + ET(er + i, lane * 4 + 2)) * av.z;
            q += lrelu02(xlv[i].w + xrv[i].w + ET(er + i, lane * 4 + 3)) * av.w;
            p[i] = q;
        }
#pragma unroll
        for (int off = 8; off > 0; off >>= 1) {
#pragma unroll
            for (int i = 0; i < 4; i++)
                p[i] += __shfl_xor_sync(0xffffffff, p[i], off);
        }
#pragma unroll
        for (int i = 0; i < 4; i++) {
            float ex = expf(p[i]);
            red_add_v4(&g_num[(size_t)d_[i] * DIN + bn + lane * 4],
                       make_float4(ex * xlv[i].x, ex * xlv[i].y, ex * xlv[i].z, ex * xlv[i].w));
            if (lane == 0 || lane == 16) {
                int head = 2 * blockIdx.x + (lane >> 4);
                atomicAdd(&g_den1[(size_t)d_[i] * 4 + head], ex);
            }
        }
    }
}

// ---------------- prep: zero numerator + den inits ----------------
__global__ void prep_kernel() {
    size_t idx = (size_t)blockIdx.x * blockDim.x + threadIdx.x;
    if (idx >= (size_t)NN_ * DIN) return;
    g_num[idx] = 0.f;
    if (idx < NN_ * 4) g_den1[idx] = 0.f;
    if (idx < (size_t)E1_ * 4) g_den2[idx] = 0.f;
}

// write xn / xlg output regions from numerator (pure output writer, runs on side stream)
__global__ void write_node_out_kernel(float* __restrict__ out, const float* __restrict__ bias1) {
    size_t idx = (size_t)blockIdx.x * blockDim.x + threadIdx.x;
    if (idx >= (size_t)NN_ * DIN) return;
    int i = (int)(idx >> 8), c = (int)(idx & 255);
    float v = g_num[idx] / (g_den1[i * 4 + (c >> 6)] + EPSV) + bias1[c];
    const size_t XN = (size_t)NN_ * 128;
    const size_t XT = (size_t)E1_ * 128;
    if (c < 128) out[(size_t)i * 128 + c] = v;
    else         out[XN + XT + (size_t)i * 128 + (c - 128)] = v;
}

// ---------------- layer-2 merged attention + aggregate, 4 edges/warp ----------------
__global__ __launch_bounds__(256) void alpha2_agg2_kernel(const int* __restrict__ adj,
                                                          const int* __restrict__ efea,
                                                          const float* __restrict__ att,
                                                          float* __restrict__ out_xt)
{
    int warp = (blockIdx.x * blockDim.x + threadIdx.x) >> 5;
    int lane = threadIdx.x & 31;
    int e0 = warp * 4;
    if (e0 >= E2_) return;
    float4 av = *(const float4*)&att[lane * 4];

    int src[4], dst[4], ef[4];
#pragma unroll
    for (int i = 0; i < 4; i++) {
        src[i] = adj[e0 + i];
        dst[i] = adj[(size_t)E2_ + e0 + i];
        ef[i]  = efea[e0 + i];
    }

    float4 xl[4], xr[4], ee[4];
#pragma unroll
    for (int i = 0; i < 4; i++) xl[i] = *(const float4*)&g_xl2  [(size_t)src[i] * DED + lane * 4];
#pragma unroll
    for (int i = 0; i < 4; i++) xr[i] = *(const float4*)&g_xr2  [(size_t)dst[i] * DED + lane * 4];
#pragma unroll
    for (int i = 0; i < 4; i++) ee[i] = *(const float4*)&g_gfeat[(size_t)ef[i]  * DED + lane * 4];

    float p[4];
#pragma unroll
    for (int i = 0; i < 4; i++) {
        float q;
        q  = lrelu02(xl[i].x + xr[i].x + ee[i].x) * av.x;
        q += lrelu02(xl[i].y + xr[i].y + ee[i].y) * av.y;
        q += lrelu02(xl[i].z + xr[i].z + ee[i].z) * av.z;
        q += lrelu02(xl[i].w + xr[i].w + ee[i].w) * av.w;
        p[i] = q;
    }
#pragma unroll
    for (int off = 4; off > 0; off >>= 1) {
#pragma unroll
        for (int i = 0; i < 4; i++)
            p[i] += __shfl_xor_sync(0xffffffff, p[i], off);
    }
#pragma unroll
    for (int i = 0; i < 4; i++) {
        float ex = expf(p[i]);
        red_add_v4(&out_xt[(size_t)dst[i] * DED + lane * 4],
                   make_float4(ex * xl[i].x, ex * xl[i].y, ex * xl[i].z, ex * xl[i].w));
        if ((lane & 7) == 0)
            atomicAdd(&g_den2[(size_t)dst[i] * 4 + (lane >> 3)], ex);
    }
}

// seed xt output region with zeros (numerator accumulator)
__global__ void seed_xt_kernel(float* __restrict__ out_xt) {
    size_t idx = (size_t)blockIdx.x * blockDim.x + threadIdx.x;
    if (idx >= (size_t)E1_ * 128) return;
    out_xt[idx] = 0.f;
}

// normalize xt in place: divide by den, add bias
__global__ void normalize_xt_kernel(float* __restrict__ out_xt, const float* __restrict__ bias2) {
    size_t idx = (size_t)blockIdx.x * blockDim.x + threadIdx.x;
    if (idx >= (size_t)E1_ * 128) return;
    int e = (int)(idx >> 7), c = (int)(idx & 127);
    out_xt[idx] = out_xt[idx] / (g_den2[(size_t)e * 4 + (c >> 5)] + EPSV) + bias2[c];
}

// ---------------- launch ----------------
extern "C" void kernel_launch(void* const* d_in, const int* in_sizes, int n_in,
                              void* d_out, int out_size)
{
    const float* x_node   = (const float*)d_in[0];
    const float* x_trace  = (const float*)d_in[1];
    const float* x_log    = (const float*)d_in[2];
    const int*   node_adj = (const int*)d_in[3];
    const int*   edge_adj = (const int*)d_in[4];
    const int*   edge_efea= (const int*)d_in[5];
    const float* n2n_Wl   = (const float*)d_in[6];
    const float* n2n_bl   = (const float*)d_in[7];
    const float* n2n_Wr   = (const float*)d_in[8];
    const float* n2n_br   = (const float*)d_in[9];
    const float* n2n_We   = (const float*)d_in[10];
    const float* n2n_att  = (const float*)d_in[11];
    const float* n2n_bias = (const float*)d_in[12];
    const float* e2n_Wl   = (const float*)d_in[13];
    const float* e2n_bl   = (const float*)d_in[14];
    const float* e2n_Wr   = (const float*)d_in[15];
    const float* e2n_br   = (const float*)d_in[16];
    const float* e2n_We   = (const float*)d_in[17];
    const float* e2n_att  = (const float*)d_in[18];
    const float* e2n_bias = (const float*)d_in[19];
    float* out = (float*)d_out;
    float* out_xt = out + (size_t)NN_ * 128;

    float* p_xl;   cudaGetSymbolAddress((void**)&p_xl,   g_xl);
    float* p_xr;   cudaGetSymbolAddress((void**)&p_xr,   g_xr);
    float* p_num;  cudaGetSymbolAddress((void**)&p_num,  g_num);
    float* p_den1; cudaGetSymbolAddress((void**)&p_den1, g_den1);
    float* p_xl2;  cudaGetSymbolAddress((void**)&p_xl2,  g_xl2);
    float* p_xr2;  cudaGetSymbolAddress((void**)&p_xr2,  g_xr2);
    float* p_g;    cudaGetSymbolAddress((void**)&p_g,    g_gfeat);

    const int SMEM_PIPE = 2 * STG * 4;          // 71680 (covers ET 128*132*4=67584 too)
    static cudaStream_t s1 = nullptr;
    static cudaEvent_t evA = nullptr, evB = nullptr, evP = nullptr, evC = nullptr, evD = nullptr;
    if (!s1) {
        cudaFuncSetAttribute(gemm_pipe, cudaFuncAttributeMaxDynamicSharedMemorySize, SMEM_PIPE);
        cudaFuncSetAttribute(gemm_gfeat, cudaFuncAttributeMaxDynamicSharedMemorySize, SMEM_PIPE);
        cudaFuncSetAttribute(gemm_alpha1_agg1_fused, cudaFuncAttributeMaxDynamicSharedMemorySize, SMEM_PIPE);
        cudaStreamCreateWithFlags(&s1, cudaStreamNonBlocking);
        cudaEventCreateWithFlags(&evA, cudaEventDisableTiming);
        cudaEventCreateWithFlags(&evB, cudaEventDisableTiming);
        cudaEventCreateWithFlags(&evP, cudaEventDisableTiming);
        cudaEventCreateWithFlags(&evC, cudaEventDisableTiming);
        cudaEventCreateWithFlags(&evD, cudaEventDisableTiming);
    }

    // fork side stream: prep + zero-seed xt + xl2/xr2 GEMM (depend only on inputs)
    cudaEventRecord(evA, 0);
    cudaStreamWaitEvent(s1, evA, 0);
    prep_kernel<<<(NN_ * DIN) / 256, 256, 0, s1>>>();
    cudaEventRecord(evP, s1);
    seed_xt_kernel<<<(E1_ * 128) / 256, 256, 0, s1>>>(out_xt);
    {
        dim3 gdim(DED / TBN, E1_ / TBM, 2);
        gemm_pipe<<<gdim, 256, SMEM_PIPE, s1>>>(x_trace, nullptr, e2n_Wl, e2n_Wr, e2n_bl, e2n_br,
                                                p_xl2, p_xr2, E1_, DED, DED);
    }
    cudaEventRecord(evB, s1);

    // main stream: xl/xr (dual-A, no concat) -> (wait prep) -> fused alpha1+agg1
    {
        dim3 gdim(DIN / TBN, NN_ / TBM, 2);
        gemm_pipe<<<gdim, 256, SMEM_PIPE>>>(x_node, x_log, n2n_Wl, n2n_Wr, n2n_bl, n2n_br,
                                            p_xl, p_xr, NN_, DIN, DIN);
    }
    cudaStreamWaitEvent(0, evP, 0);
    {
        dim3 gdim(DIN / TBN, E1_ / TBM);
        gemm_alpha1_agg1_fused<<<gdim, 256, SMEM_PIPE>>>(x_trace, n2n_We, node_adj, n2n_att);
    }
    cudaEventRecord(evC, 0);   // numerator + den1 final

    // side stream: write xn/xlg outputs while main does gfeat + alpha2_agg2
    cudaStreamWaitEvent(s1, evC, 0);
    write_node_out_kernel<<<(NN_ * DIN) / 256, 256, 0, s1>>>(out, n2n_bias);
    cudaEventRecord(evD, s1);

    // main: gfeat = normalize(num) @ We2 (normalization fused into A-load)
    {
        dim3 gdim(1, NN_ / TBM);
        gemm_gfeat<<<gdim, 256, SMEM_PIPE>>>(p_num, p_den1, n2n_bias, e2n_We, p_g);
    }

    // join: merged layer-2 needs xl2/xr2 + seeded xt from side stream
    cudaStreamWaitEvent(0, evB, 0);

    alpha2_agg2_kernel<<<E2_ / 32, 256>>>(edge_adj, edge_efea, e2n_att, out_xt);
    normalize_xt_kernel<<<(E1_ * 128) / 256, 256>>>(out_xt, e2n_bias);

    // final join: node-out writes must be ordered into stream 0
    cudaStreamWaitEvent(0, evD, 0);
}

// round 15
// speedup vs baseline: 1.8147x; 1.1550x over previous
#include <cuda_runtime.h>
#include <stdint.h>
#include <math.h>
#include <float.h>

// ---------------- problem constants ----------------
#define NN_   8192      // nodes
#define E1_   131072    // node-graph edges (= trace rows)
#define E2_   524288    // line-graph edges
#define DIN   256       // layer1 channels (4 heads x 64)
#define DED   128       // layer2 channels (4 heads x 32)
#define EPSV  1e-16f

// ---------------- scratch (static device, no allocs) ----------------
__device__ float g_xl     [(size_t)NN_ * DIN];
__device__ float g_xr     [(size_t)NN_ * DIN];
__device__ float g_den1   [(size_t)NN_ * 4];
__device__ float g_num    [(size_t)NN_ * DIN];  // layer-1 numerator
__device__ float g_xl2    [(size_t)E1_ * DED];
__device__ float g_xr2    [(size_t)E1_ * DED];
__device__ float g_gfeat  [(size_t)NN_ * DED];
__device__ float g_den2   [(size_t)E1_ * 4];

// ---------------- helpers ----------------
__device__ __forceinline__ float lrelu02(float x) { return x > 0.f ? x : 0.2f * x; }
__device__ __forceinline__ uint32_t to_tf32(float v) {
    uint32_t t;
    asm("cvt.rna.tf32.f32 %0, %1;" : "=r"(t) : "f"(v));
    return t;
}
__device__ __forceinline__ void cp16(uint32_t dst, const void* src) {
    asm volatile("cp.async.cg.shared.global [%0], [%1], 16;" :: "r"(dst), "l"(src));
}
__device__ __forceinline__ void red_add_v4(float* addr, float4 v) {
    asm volatile("red.global.add.v4.f32 [%0], {%1,%2,%3,%4};"
                 :: "l"(addr), "f"(v.x), "f"(v.y), "f"(v.z), "f"(v.w) : "memory");
}

// ---------------- tf32 GEMM tiles ----------------
#define TBM 128
#define TBN 128
#define TBK 32
#define STG 8960                 // floats per stage: 128*36 + 32*136
#define AS(S,M,K_) smem[(S)*STG + (M)*36 + (K_)]
#define BS(S,KK,N_) smem[(S)*STG + 4608 + (KK)*136 + (N_)]
#define ET(R,C) smem[(R)*132 + (C)]

struct Frag { float c[4][4][4]; };

// A source: if A1 != nullptr, rows come from A (k<128) or A1 (k>=128), each stride 128.
__device__ __forceinline__ void load_stage(float* smem, int s,
    const float* __restrict__ A, const float* __restrict__ A1, int strideA,
    const float* __restrict__ W,
    int bm, int bn, int k0, int Ncol, int tid)
{
    const float* Abase = A;
    int acol = k0;
    int astr = strideA;
    if (A1) {
        astr = 128;
        if (k0 >= 128) { Abase = A1; acol = k0 - 128; }
    }
#pragma unroll
    for (int i = 0; i < 4; i++) {
        int idx = tid + i * 256;
        int m = idx >> 3, kc = idx & 7;
        cp16((uint32_t)__cvta_generic_to_shared(&AS(s, m, kc * 4)),
             &Abase[(size_t)(bm + m) * astr + acol + kc * 4]);
    }
#pragma unroll
    for (int i = 0; i < 4; i++) {
        int idx = tid + i * 256;
        int kk = idx >> 5, nc = idx & 31;
        cp16((uint32_t)__cvta_generic_to_shared(&BS(s, kk, nc * 4)),
             &W[(size_t)(k0 + kk) * Ncol + bn + nc * 4]);
    }
    asm volatile("cp.async.commit_group;");
}

__device__ __forceinline__ void compute_stage(const float* smem, int s, Frag& f,
                                              int wm, int wn, int g, int tg)
{
#pragma unroll
    for (int ks = 0; ks < 4; ks++) {
        const int kb = ks * 8;
        uint32_t afr[4][4], bfr[4][2];
#pragma unroll
        for (int mt = 0; mt < 4; mt++) {
            int mr = wm + mt * 16 + g;
            afr[mt][0] = to_tf32(AS(s, mr,     kb + tg));
            afr[mt][1] = to_tf32(AS(s, mr + 8, kb + tg));
            afr[mt][2] = to_tf32(AS(s, mr,     kb + tg + 4));
            afr[mt][3] = to_tf32(AS(s, mr + 8, kb + tg + 4));
        }
#pragma unroll
        for (int nt = 0; nt < 4; nt++) {
            int nc = wn + nt * 8 + g;
            bfr[nt][0] = to_tf32(BS(s, kb + tg,     nc));
            bfr[nt][1] = to_tf32(BS(s, kb + tg + 4, nc));
        }
#pragma unroll
        for (int mt = 0; mt < 4; mt++)
#pragma unroll
            for (int nt = 0; nt < 4; nt++) {
                asm volatile(
                    "mma.sync.aligned.m16n8k8.row.col.f32.tf32.tf32.f32 "
                    "{%0,%1,%2,%3}, {%4,%5,%6,%7}, {%8,%9}, {%0,%1,%2,%3};"
                    : "+f"(f.c[mt][nt][0]), "+f"(f.c[mt][nt][1]),
                      "+f"(f.c[mt][nt][2]), "+f"(f.c[mt][nt][3])
                    : "r"(afr[mt][0]), "r"(afr[mt][1]),
                      "r"(afr[mt][2]), "r"(afr[mt][3]),
                      "r"(bfr[nt][0]), "r"(bfr[nt][1]));
            }
    }
}

// Pipelined GEMM; optional dual-A (concat rows) and dual-output (blockIdx.z selects W/bias/C).
__global__ __launch_bounds__(256) void gemm_pipe(
    const float* __restrict__ A, const float* __restrict__ A1,
    const float* __restrict__ W0, const float* __restrict__ W1,
    const float* __restrict__ b0, const float* __restrict__ b1,
    float* __restrict__ C0, float* __restrict__ C1,
    int M, int Ncol, int K)
{
    extern __shared__ float smem[];
    const int tid  = threadIdx.x;
    const int lane = tid & 31, warp = tid >> 5;
    const int g = lane >> 2, tg = lane & 3;
    const int wm = (warp >> 2) * 64, wn = (warp & 3) * 32;
    const int bm = blockIdx.y * TBM, bn = blockIdx.x * TBN;
    const int z  = blockIdx.z;
    const float* W    = z ? W1 : W0;
    const float* bias = z ? b1 : b0;
    float* C          = z ? C1 : C0;

    Frag f;
#pragma unroll
    for (int mt = 0; mt < 4; mt++)
#pragma unroll
        for (int nt = 0; nt < 4; nt++)
#pragma unroll
            for (int r = 0; r < 4; r++) f.c[mt][nt][r] = 0.f;

    const int KT = K / TBK;
    load_stage(smem, 0, A, A1, K, W, bm, bn, 0, Ncol, tid);
    for (int kt = 0; kt < KT; kt++) {
        int s = kt & 1;
        if (kt + 1 < KT) {
            load_stage(smem, s ^ 1, A, A1, K, W, bm, bn, (kt + 1) * TBK, Ncol, tid);
            asm volatile("cp.async.wait_group 1;");
        } else {
            asm volatile("cp.async.wait_group 0;");
        }
        __syncthreads();
        compute_stage(smem, s, f, wm, wn, g, tg);
        __syncthreads();
    }

#pragma unroll
    for (int mt = 0; mt < 4; mt++) {
        int r0 = bm + wm + mt * 16 + g;
#pragma unroll
        for (int nt = 0; nt < 4; nt++) {
            int col = bn + wn + nt * 8 + 2 * tg;
            float bb0 = bias ? bias[col] : 0.f;
            float bb1 = bias ? bias[col + 1] : 0.f;
            float2 v0 = make_float2(f.c[mt][nt][0] + bb0, f.c[mt][nt][1] + bb1);
            float2 v1 = make_float2(f.c[mt][nt][2] + bb0, f.c[mt][nt][3] + bb1);
            *(float2*)&C[(size_t)r0 * Ncol + col] = v0;
            *(float2*)&C[(size_t)(r0 + 8) * Ncol + col] = v1;
        }
    }
}

// gfeat GEMM with on-the-fly normalization of A:
// A[m][k] = num[m][k] / (den1[m][k>>6] + eps) + bias1[k];  C = A @ We2
__global__ __launch_bounds__(256) void gemm_gfeat(
    const float* __restrict__ num, const float* __restrict__ den,
    const float* __restrict__ bias1, const float* __restrict__ W,
    float* __restrict__ C)
{
    extern __shared__ float smem[];
    const int tid  = threadIdx.x;
    const int lane = tid & 31, warp = tid >> 5;
    const int g = lane >> 2, tg = lane & 3;
    const int wm = (warp >> 2) * 64, wn = (warp & 3) * 32;
    const int bm = blockIdx.y * TBM, bn = 0;
    const int Ncol = DED, K = DIN;

    Frag f;
#pragma unroll
    for (int mt = 0; mt < 4; mt++)
#pragma unroll
        for (int nt = 0; nt < 4; nt++)
#pragma unroll
            for (int r = 0; r < 4; r++) f.c[mt][nt][r] = 0.f;

    auto loadA = [&](int k0, float4* out) {
#pragma unroll
        for (int i = 0; i < 4; i++) {
            int idx = tid + i * 256;
            int m = idx >> 3, kc = idx & 7;
            int col = k0 + kc * 4;
            float4 v = *(const float4*)&num[(size_t)(bm + m) * DIN + col];
            float invd = __fdividef(1.f, den[(bm + m) * 4 + (col >> 6)] + EPSV);
            float4 b = *(const float4*)&bias1[col];
            out[i] = make_float4(v.x * invd + b.x, v.y * invd + b.y,
                                 v.z * invd + b.z, v.w * invd + b.w);
        }
    };
    auto stsA = [&](int s, const float4* regs) {
#pragma unroll
        for (int i = 0; i < 4; i++) {
            int idx = tid + i * 256;
            int m = idx >> 3, kc = idx & 7;
            *(float4*)&AS(s, m, kc * 4) = regs[i];
        }
    };
    auto loadB = [&](int s, int k0) {
#pragma unroll
        for (int i = 0; i < 4; i++) {
            int idx = tid + i * 256;
            int kk = idx >> 5, nc = idx & 31;
            cp16((uint32_t)__cvta_generic_to_shared(&BS(s, kk, nc * 4)),
                 &W[(size_t)(k0 + kk) * Ncol + bn + nc * 4]);
        }
        asm volatile("cp.async.commit_group;");
    };

    const int KT = K / TBK;
    float4 aregs[4];
    loadA(0, aregs);
    stsA(0, aregs);
    loadB(0, 0);
    for (int kt = 0; kt < KT; kt++) {
        int s = kt & 1;
        float4 anext[4];
        if (kt + 1 < KT) {
            loadA((kt + 1) * TBK, anext);
            loadB(s ^ 1, (kt + 1) * TBK);
            asm volatile("cp.async.wait_group 1;");
        } else {
            asm volatile("cp.async.wait_group 0;");
        }
        __syncthreads();
        compute_stage(smem, s, f, wm, wn, g, tg);
        __syncthreads();
        if (kt + 1 < KT) stsA(s ^ 1, anext);
    }

#pragma unroll
    for (int mt = 0; mt < 4; mt++) {
        int r0 = bm + wm + mt * 16 + g;
#pragma unroll
        for (int nt = 0; nt < 4; nt++) {
            int col = bn + wn + nt * 8 + 2 * tg;
            *(float2*)&C[(size_t)r0 * Ncol + col] =
                make_float2(f.c[mt][nt][0], f.c[mt][nt][1]);
            *(float2*)&C[(size_t)(r0 + 8) * Ncol + col] =
                make_float2(f.c[mt][nt][2], f.c[mt][nt][3]);
        }
    }
}

// Fused layer-1: e1 = trace @ We in smem, then per-edge logit -> exp ->
// numerator (ex * xl[src]) RED into g_num + denominator RED into den1.
// grid (2, E1/128). Phase-2: 8 edges at a time, front-batched gathers (MLP=16).
__global__ __launch_bounds__(256) void gemm_alpha1_agg1_fused(
    const float* __restrict__ A,      // x_trace [E1,128]
    const float* __restrict__ W,      // n2n_We [128,256]
    const int*   __restrict__ adj,    // node_adj [2,E1]
    const float* __restrict__ att)    // [4,64]
{
    extern __shared__ float smem[];
    const int tid  = threadIdx.x;
    const int lane = tid & 31, warp = tid >> 5;
    const int g = lane >> 2, tg = lane & 3;
    const int wm = (warp >> 2) * 64, wn = (warp & 3) * 32;
    const int bm = blockIdx.y * TBM, bn = blockIdx.x * TBN;
    const int K = 128, Ncol = DIN;

    Frag f;
#pragma unroll
    for (int mt = 0; mt < 4; mt++)
#pragma unroll
        for (int nt = 0; nt < 4; nt++)
#pragma unroll
            for (int r = 0; r < 4; r++) f.c[mt][nt][r] = 0.f;

    const int KT = K / TBK;
    load_stage(smem, 0, A, nullptr, K, W, bm, bn, 0, Ncol, tid);
    for (int kt = 0; kt < KT; kt++) {
        int s = kt & 1;
        if (kt + 1 < KT) {
            load_stage(smem, s ^ 1, A, nullptr, K, W, bm, bn, (kt + 1) * TBK, Ncol, tid);
            asm volatile("cp.async.wait_group 1;");
        } else {
            asm volatile("cp.async.wait_group 0;");
        }
        __syncthreads();
        compute_stage(smem, s, f, wm, wn, g, tg);
        __syncthreads();
    }

    // stage e1 tile into smem
#pragma unroll
    for (int mt = 0; mt < 4; mt++) {
        int r0 = wm + mt * 16 + g;
#pragma unroll
        for (int nt = 0; nt < 4; nt++) {
            int col = wn + nt * 8 + 2 * tg;
            ET(r0, col)         = f.c[mt][nt][0];
            ET(r0, col + 1)     = f.c[mt][nt][1];
            ET(r0 + 8, col)     = f.c[mt][nt][2];
            ET(r0 + 8, col + 1) = f.c[mt][nt][3];
        }
    }
    __syncthreads();

    // phase 2: 8 edges at a time, gathers front-batched (GEMM accumulators are dead
    // here, so the 64-reg payload reuses their registers)
    const float4 av = *(const float4*)&att[bn + lane * 4];
#pragma unroll
    for (int it = 0; it < 2; it++) {
        int er = warp * 16 + it * 8;
        int eg = bm + er;
        int s_[8], d_[8];
#pragma unroll
        for (int i = 0; i < 8; i++) {
            s_[i] = adj[eg + i];
            d_[i] = adj[E1_ + eg + i];
        }
        float4 xlv[8], xrv[8];
#pragma unroll
        for (int i = 0; i < 8; i++) xlv[i] = *(const float4*)&g_xl[(size_t)s_[i] * DIN + bn + lane * 4];
#pragma unroll
        for (int i = 0; i < 8; i++) xrv[i] = *(const float4*)&g_xr[(size_t)d_[i] * DIN + bn + lane * 4];

        float p[8];
#pragma unroll
        for (int i = 0; i < 8; i++) {
            float q;
            q  = lrelu02(xlv[i].x + xrv[i].x + ET(er + i, lane * 4 + 0)) * av.x;
            q += lrelu02(xlv[i].y + xrv[i].y + ET(er + i, lane * 4 + 1)) * av.y;
            q += lrelu02(xlv[i].z + xrv[i].z + ET(er + i, lane * 4 + 2)) * av.z;
            q += lrelu02(xlv[i].w + xrv[i].w + ET(er + i, lane * 4 + 3)) * av.w;
            p[i] = q;
        }
#pragma unroll
        for (int off = 8; off > 0; off >>= 1) {
#pragma unroll
            for (int i = 0; i < 8; i++)
                p[i] += __shfl_xor_sync(0xffffffff, p[i], off);
        }
#pragma unroll
        for (int i = 0; i < 8; i++) {
            float ex = expf(p[i]);
            red_add_v4(&g_num[(size_t)d_[i] * DIN + bn + lane * 4],
                       make_float4(ex * xlv[i].x, ex * xlv[i].y, ex * xlv[i].z, ex * xlv[i].w));
            if (lane == 0 || lane == 16) {
                int head = 2 * blockIdx.x + (lane >> 4);
                atomicAdd(&g_den1[(size_t)d_[i] * 4 + head], ex);
            }
        }
    }
}

// ---------------- prep: zero numerator + den inits ----------------
__global__ void prep_kernel() {
    size_t idx = (size_t)blockIdx.x * blockDim.x + threadIdx.x;   // NN_*DIN/4 threads
    if (idx >= (size_t)NN_ * DIN / 4) return;
    ((float4*)g_num)[idx] = make_float4(0.f, 0.f, 0.f, 0.f);
    if (idx < NN_ * 4) g_den1[idx] = 0.f;
    if (idx < (size_t)E1_ * 4) g_den2[idx] = 0.f;
}

// write xn / xlg output regions from numerator (float4, runs on side stream)
__global__ void write_node_out_kernel(float* __restrict__ out, const float* __restrict__ bias1) {
    size_t idx = (size_t)blockIdx.x * blockDim.x + threadIdx.x;   // NN_*64 threads
    if (idx >= (size_t)NN_ * 64) return;
    int i = (int)(idx >> 6), c4 = (int)(idx & 63) * 4;
    float4 v = *(const float4*)&g_num[(size_t)i * DIN + c4];
    float invd = __fdividef(1.f, g_den1[i * 4 + (c4 >> 6)] + EPSV);
    float4 b = *(const float4*)&bias1[c4];
    float4 r = make_float4(v.x * invd + b.x, v.y * invd + b.y,
                           v.z * invd + b.z, v.w * invd + b.w);
    const size_t XN = (size_t)NN_ * 128;
    const size_t XT = (size_t)E1_ * 128;
    if (c4 < 128) *(float4*)&out[(size_t)i * 128 + c4] = r;
    else          *(float4*)&out[XN + XT + (size_t)i * 128 + (c4 - 128)] = r;
}

// ---------------- layer-2 merged attention + aggregate, 4 edges/warp ----------------
__global__ __launch_bounds__(256) void alpha2_agg2_kernel(const int* __restrict__ adj,
                                                          const int* __restrict__ efea,
                                                          const float* __restrict__ att,
                                                          float* __restrict__ out_xt)
{
    int warp = (blockIdx.x * blockDim.x + threadIdx.x) >> 5;
    int lane = threadIdx.x & 31;
    int e0 = warp * 4;
    if (e0 >= E2_) return;
    float4 av = *(const float4*)&att[lane * 4];

    int src[4], dst[4], ef[4];
#pragma unroll
    for (int i = 0; i < 4; i++) {
        src[i] = adj[e0 + i];
        dst[i] = adj[(size_t)E2_ + e0 + i];
        ef[i]  = efea[e0 + i];
    }

    float4 xl[4], xr[4], ee[4];
#pragma unroll
    for (int i = 0; i < 4; i++) xl[i] = *(const float4*)&g_xl2  [(size_t)src[i] * DED + lane * 4];
#pragma unroll
    for (int i = 0; i < 4; i++) xr[i] = *(const float4*)&g_xr2  [(size_t)dst[i] * DED + lane * 4];
#pragma unroll
    for (int i = 0; i < 4; i++) ee[i] = *(const float4*)&g_gfeat[(size_t)ef[i]  * DED + lane * 4];

    float p[4];
#pragma unroll
    for (int i = 0; i < 4; i++) {
        float q;
        q  = lrelu02(xl[i].x + xr[i].x + ee[i].x) * av.x;
        q += lrelu02(xl[i].y + xr[i].y + ee[i].y) * av.y;
        q += lrelu02(xl[i].z + xr[i].z + ee[i].z) * av.z;
        q += lrelu02(xl[i].w + xr[i].w + ee[i].w) * av.w;
        p[i] = q;
    }
#pragma unroll
    for (int off = 4; off > 0; off >>= 1) {
#pragma unroll
        for (int i = 0; i < 4; i++)
            p[i] += __shfl_xor_sync(0xffffffff, p[i], off);
    }
#pragma unroll
    for (int i = 0; i < 4; i++) {
        float ex = expf(p[i]);
        red_add_v4(&out_xt[(size_t)dst[i] * DED + lane * 4],
                   make_float4(ex * xl[i].x, ex * xl[i].y, ex * xl[i].z, ex * xl[i].w));
        if ((lane & 7) == 0)
            atomicAdd(&g_den2[(size_t)dst[i] * 4 + (lane >> 3)], ex);
    }
}

// seed xt output region with zeros (float4)
__global__ void seed_xt_kernel(float* __restrict__ out_xt) {
    size_t idx = (size_t)blockIdx.x * blockDim.x + threadIdx.x;   // E1_*32 threads
    if (idx >= (size_t)E1_ * 32) return;
    ((float4*)out_xt)[idx] = make_float4(0.f, 0.f, 0.f, 0.f);
}

// normalize xt in place (float4): divide by den, add bias
__global__ void normalize_xt_kernel(float* __restrict__ out_xt, const float* __restrict__ bias2) {
    size_t idx = (size_t)blockIdx.x * blockDim.x + threadIdx.x;   // E1_*32 threads
    if (idx >= (size_t)E1_ * 32) return;
    int e = (int)(idx >> 5), c4 = (int)(idx & 31) * 4;
    float4 v = ((const float4*)out_xt)[idx];
    float invd = __fdividef(1.f, g_den2[(size_t)e * 4 + (c4 >> 5)] + EPSV);
    float4 b = *(const float4*)&bias2[c4];
    ((float4*)out_xt)[idx] = make_float4(v.x * invd + b.x, v.y * invd + b.y,
                                         v.z * invd + b.z, v.w * invd + b.w);
}

// ---------------- launch ----------------
extern "C" void kernel_launch(void* const* d_in, const int* in_sizes, int n_in,
                              void* d_out, int out_size)
{
    const float* x_node   = (const float*)d_in[0];
    const float* x_trace  = (const float*)d_in[1];
    const float* x_log    = (const float*)d_in[2];
    const int*   node_adj = (const int*)d_in[3];
    const int*   edge_adj = (const int*)d_in[4];
    const int*   edge_efea= (const int*)d_in[5];
    const float* n2n_Wl   = (const float*)d_in[6];
    const float* n2n_bl   = (const float*)d_in[7];
    const float* n2n_Wr   = (const float*)d_in[8];
    const float* n2n_br   = (const float*)d_in[9];
    const float* n2n_We   = (const float*)d_in[10];
    const float* n2n_att  = (const float*)d_in[11];
    const float* n2n_bias = (const float*)d_in[12];
    const float* e2n_Wl   = (const float*)d_in[13];
    const float* e2n_bl   = (const float*)d_in[14];
    const float* e2n_Wr   = (const float*)d_in[15];
    const float* e2n_br   = (const float*)d_in[16];
    const float* e2n_We   = (const float*)d_in[17];
    const float* e2n_att  = (const float*)d_in[18];
    const float* e2n_bias = (const float*)d_in[19];
    float* out = (float*)d_out;
    float* out_xt = out + (size_t)NN_ * 128;

    float* p_xl;   cudaGetSymbolAddress((void**)&p_xl,   g_xl);
    float* p_xr;   cudaGetSymbolAddress((void**)&p_xr,   g_xr);
    float* p_num;  cudaGetSymbolAddress((void**)&p_num,  g_num);
    float* p_den1; cudaGetSymbolAddress((void**)&p_den1, g_den1);
    float* p_xl2;  cudaGetSymbolAddress((void**)&p_xl2,  g_xl2);
    float* p_xr2;  cudaGetSymbolAddress((void**)&p_xr2,  g_xr2);
    float* p_g;    cudaGetSymbolAddress((void**)&p_g,    g_gfeat);

    const int SMEM_PIPE = 2 * STG * 4;
    static cudaStream_t s1 = nullptr;
    static cudaEvent_t evA = nullptr, evB = nullptr, evP = nullptr, evC = nullptr, evD = nullptr;
    if (!s1) {
        cudaFuncSetAttribute(gemm_pipe, cudaFuncAttributeMaxDynamicSharedMemorySize, SMEM_PIPE);
        cudaFuncSetAttribute(gemm_gfeat, cudaFuncAttributeMaxDynamicSharedMemorySize, SMEM_PIPE);
        cudaFuncSetAttribute(gemm_alpha1_agg1_fused, cudaFuncAttributeMaxDynamicSharedMemorySize, SMEM_PIPE);
        cudaStreamCreateWithFlags(&s1, cudaStreamNonBlocking);
        cudaEventCreateWithFlags(&evA, cudaEventDisableTiming);
        cudaEventCreateWithFlags(&evB, cudaEventDisableTiming);
        cudaEventCreateWithFlags(&evP, cudaEventDisableTiming);
        cudaEventCreateWithFlags(&evC, cudaEventDisableTiming);
        cudaEventCreateWithFlags(&evD, cudaEventDisableTiming);
    }

    // fork side stream: prep + zero-seed xt + xl2/xr2 GEMM
    cudaEventRecord(evA, 0);
    cudaStreamWaitEvent(s1, evA, 0);
    prep_kernel<<<(NN_ * DIN / 4 + 255) / 256, 256, 0, s1>>>();
    cudaEventRecord(evP, s1);
    seed_xt_kernel<<<(E1_ * 32) / 256, 256, 0, s1>>>(out_xt);
    {
        dim3 gdim(DED / TBN, E1_ / TBM, 2);
        gemm_pipe<<<gdim, 256, SMEM_PIPE, s1>>>(x_trace, nullptr, e2n_Wl, e2n_Wr, e2n_bl, e2n_br,
                                                p_xl2, p_xr2, E1_, DED, DED);
    }
    cudaEventRecord(evB, s1);

    // main stream: xl/xr (dual-A, no concat) -> (wait prep) -> fused alpha1+agg1
    {
        dim3 gdim(DIN / TBN, NN_ / TBM, 2);
        gemm_pipe<<<gdim, 256, SMEM_PIPE>>>(x_node, x_log, n2n_Wl, n2n_Wr, n2n_bl, n2n_br,
                                            p_xl, p_xr, NN_, DIN, DIN);
    }
    cudaStreamWaitEvent(0, evP, 0);
    {
        dim3 gdim(DIN / TBN, E1_ / TBM);
        gemm_alpha1_agg1_fused<<<gdim, 256, SMEM_PIPE>>>(x_trace, n2n_We, node_adj, n2n_att);
    }
    cudaEventRecord(evC, 0);   // numerator + den1 final

    // side stream: write xn/xlg outputs while main does gfeat + alpha2_agg2
    cudaStreamWaitEvent(s1, evC, 0);
    write_node_out_kernel<<<(NN_ * 64) / 256, 256, 0, s1>>>(out, n2n_bias);
    cudaEventRecord(evD, s1);

    // main: gfeat = normalize(num) @ We2
    {
        dim3 gdim(1, NN_ / TBM);
        gemm_gfeat<<<gdim, 256, SMEM_PIPE>>>(p_num, p_den1, n2n_bias, e2n_We, p_g);
    }

    // join: merged layer-2 needs xl2/xr2 + seeded xt from side stream
    cudaStreamWaitEvent(0, evB, 0);

    alpha2_agg2_kernel<<<E2_ / 32, 256>>>(edge_adj, edge_efea, e2n_att, out_xt);
    normalize_xt_kernel<<<(E1_ * 32) / 256, 256>>>(out_xt, e2n_bias);

    // final join: node-out writes ordered into stream 0
    cudaStreamWaitEvent(0, evD, 0);
}